// round 7
// baseline (speedup 1.0000x reference)
#include <cuda_runtime.h>
#include <math.h>
#include <stdint.h>

// Problem constants
#define Bn   8
#define Ln   4096
#define DINn 64
#define Dn   256
#define NLn  2
#define DIn  512
#define DSn  16
#define DCn  4
#define DTRn 16
#define Mrows (Bn * Ln)   // 32768

#define C_CHUNKS 4
#define CH_LEN   1024
#define NCH      (Bn * DIn * DSn)   // 65536

// ---------------------------------------------------------------------------
// Scratch (device globals — no runtime allocation allowed)
// ---------------------------------------------------------------------------
__device__ float g_h    [Mrows * Dn];
__device__ float g_t0   [Mrows * Dn];
__device__ float g_xz   [Mrows * 2 * DIn];
__device__ float g_u    [Mrows * DIn];
__device__ float g_dt   [Mrows * DIn];
__device__ float g_xdbc [Mrows * 48];
__device__ float g_y    [Mrows * DIn];
__device__ float g_P    [(C_CHUNKS - 1) * NCH];
__device__ float g_h0   [(C_CHUNKS - 1) * NCH];
__device__ float g_hini [C_CHUNKS * NCH];
__device__ float g_logit[Mrows];
__device__ float g_part [Bn * 16 * Dn];

// ---------------------------------------------------------------------------
// Helpers
// ---------------------------------------------------------------------------
__device__ __forceinline__ float softplus_f(float x) {
    return fmaxf(x, 0.f) + log1pf(__expf(-fabsf(x)));
}
__device__ __forceinline__ float silu_f(float x) {
    return x / (1.f + __expf(-x));
}
__device__ __forceinline__ float to_tf32(float x) {
    float r;
    asm("cvt.rna.tf32.f32 %0, %1;" : "=f"(r) : "f"(x));
    return r;
}
__device__ __forceinline__ void mma8(float* d,
                                     float a0, float a1, float a2, float a3,
                                     float b0, float b1) {
    asm volatile(
        "mma.sync.aligned.m16n8k8.row.col.f32.tf32.tf32.f32 "
        "{%0,%1,%2,%3},{%4,%5,%6,%7},{%8,%9},{%0,%1,%2,%3};"
        : "+f"(d[0]), "+f"(d[1]), "+f"(d[2]), "+f"(d[3])
        : "r"(__float_as_uint(a0)), "r"(__float_as_uint(a1)),
          "r"(__float_as_uint(a2)), "r"(__float_as_uint(a3)),
          "r"(__float_as_uint(b0)), "r"(__float_as_uint(b1)));
}

// ---------------------------------------------------------------------------
// HYBRID GEMM: C[M,N] = A[M,K](row-major,lda) * W[N,K]^T.
// Requires M%128==0, N%128==0, K%16==0.
// Tile 128x128x16, 256 threads. Warps 0-3: tensor (tf32 mma) on cols 0-63.
// Warps 4-7: SIMT fp32 8x8 microtiles on cols 64-127 (fma pipe).
// Tensor and fma pipes run concurrently -> ~1.5x over all-tensor.
// Dynamic smem layout (floats):
//   AT [2][128][24]  tf32, k-permuted    @ 0      (6144)
//   WT [2][ 64][24]  tf32, k-permuted    @ 6144   (3072)
//   AS [2][16][132]  fp32, k-major       @ 9216   (4224)
//   WS [2][16][ 68]  fp32, k-major       @ 13440  (2176)
// EPI: 0 = store, 1 = +bias
// ---------------------------------------------------------------------------
#define HYB_SMEM_FLOATS 15616
#define HYB_SMEM_BYTES  (HYB_SMEM_FLOATS * 4)

template <int EPI>
__global__ void __launch_bounds__(256, 2) hyb_gemm(
    int N, int K,
    const float* __restrict__ A, int lda,
    const float* __restrict__ W,
    const float* __restrict__ bias,
    float* __restrict__ C, int ldc)
{
    extern __shared__ float sm[];
    const int AT0 = 0, WT0 = 6144, AS0 = 9216, WS0 = 13440;

    const int tid  = threadIdx.x;
    const int wid  = tid >> 5, lane = tid & 31;
    const int m0   = blockIdx.y * 128;
    const int n0   = blockIdx.x * 128;

    // staging indices (identical scheme to the proven R4 kernel)
    const int lr0 = tid >> 2;           // 0..63
    const int lj  = tid & 3;            // k-quad
    const int pb  = (lj & 2) * 4 + (lj & 1);   // permuted tensor col base

    const float* Ag = A + (size_t)(m0 + lr0) * lda + lj * 4;
    const float* Wg = W + (size_t)(n0 + lr0) * K + lj * 4;

    // role constants
    const int gr = lane >> 2, gc = lane & 3;      // tensor frag coords
    const int mh = (wid & 1) * 64;                // tensor m-half
    const int nq = ((wid >> 1) & 1) * 32;         // tensor n-quarter (of 64)
    const int sw = wid - 4;                       // SIMT warp index 0..3
    const int tx = lane & 7, ty = lane >> 3;      // SIMT lane coords

    // accumulators: tensor uses accT, SIMT uses accS (disjoint by role)
    float accT[4][4][4];
    float accS[8][8];
    if (wid < 4) {
        #pragma unroll
        for (int i = 0; i < 4; i++)
            #pragma unroll
            for (int j = 0; j < 4; j++)
                #pragma unroll
                for (int t = 0; t < 4; t++) accT[i][j][t] = 0.f;
    } else {
        #pragma unroll
        for (int i = 0; i < 8; i++)
            #pragma unroll
            for (int j = 0; j < 8; j++) accS[i][j] = 0.f;
    }

    float4 ra0, ra1, rw0, rw1;

    // ---- stage chunk 0 ----
    ra0 = *(const float4*)(Ag);
    ra1 = *(const float4*)(Ag + (size_t)64 * lda);
    rw0 = *(const float4*)(Wg);                       // W row n0+lr0   -> tensor
    rw1 = *(const float4*)(Wg + (size_t)64 * K);      // W row n0+lr0+64 -> SIMT
    {
        float a0[4] = {ra0.x, ra0.y, ra0.z, ra0.w};
        float a1[4] = {ra1.x, ra1.y, ra1.z, ra1.w};
        float w0[4] = {rw0.x, rw0.y, rw0.z, rw0.w};
        float w1[4] = {rw1.x, rw1.y, rw1.z, rw1.w};
        #pragma unroll
        for (int i = 0; i < 4; i++) {
            sm[AT0 + lr0 * 24 + pb + 2 * i]        = to_tf32(a0[i]);
            sm[AT0 + (lr0 + 64) * 24 + pb + 2 * i] = to_tf32(a1[i]);
            sm[WT0 + lr0 * 24 + pb + 2 * i]        = to_tf32(w0[i]);
            sm[AS0 + (lj * 4 + i) * 132 + lr0]      = a0[i];
            sm[AS0 + (lj * 4 + i) * 132 + lr0 + 64] = a1[i];
            sm[WS0 + (lj * 4 + i) * 68 + lr0]       = w1[i];
        }
    }
    __syncthreads();

    int buf = 0;
    for (int k0 = 16; k0 < K; k0 += 16) {
        // prefetch next chunk
        ra0 = *(const float4*)(Ag + k0);
        ra1 = *(const float4*)(Ag + (size_t)64 * lda + k0);
        rw0 = *(const float4*)(Wg + k0);
        rw1 = *(const float4*)(Wg + (size_t)64 * K + k0);

        // ---- compute current buffer ----
        if (wid < 4) {
            const int ato = AT0 + buf * 3072;
            const int wto = WT0 + buf * 1536;
            #pragma unroll
            for (int ks = 0; ks < 2; ks++) {
                float2 alo[4], ahi[4], bfr[4];
                #pragma unroll
                for (int fm = 0; fm < 4; fm++) {
                    alo[fm] = *(const float2*)&sm[ato + (mh + fm * 16 + gr) * 24 + ks * 8 + 2 * gc];
                    ahi[fm] = *(const float2*)&sm[ato + (mh + fm * 16 + gr + 8) * 24 + ks * 8 + 2 * gc];
                }
                #pragma unroll
                for (int fn = 0; fn < 4; fn++)
                    bfr[fn] = *(const float2*)&sm[wto + (nq + fn * 8 + gr) * 24 + ks * 8 + 2 * gc];
                #pragma unroll
                for (int fm = 0; fm < 4; fm++)
                    #pragma unroll
                    for (int fn = 0; fn < 4; fn++)
                        mma8(accT[fm][fn], alo[fm].x, ahi[fm].x, alo[fm].y, ahi[fm].y,
                             bfr[fn].x, bfr[fn].y);
            }
        } else {
            const int aso = AS0 + buf * 2112 + sw * 32 + ty * 8;
            const int wso = WS0 + buf * 1088 + tx * 8;
            #pragma unroll
            for (int k = 0; k < 16; k++) {
                float4 a0 = *(const float4*)&sm[aso + k * 132];
                float4 a1 = *(const float4*)&sm[aso + k * 132 + 4];
                float4 b0 = *(const float4*)&sm[wso + k * 68];
                float4 b1 = *(const float4*)&sm[wso + k * 68 + 4];
                const float a[8] = {a0.x, a0.y, a0.z, a0.w, a1.x, a1.y, a1.z, a1.w};
                const float b[8] = {b0.x, b0.y, b0.z, b0.w, b1.x, b1.y, b1.z, b1.w};
                #pragma unroll
                for (int i = 0; i < 8; i++)
                    #pragma unroll
                    for (int j = 0; j < 8; j++)
                        accS[i][j] = fmaf(a[i], b[j], accS[i][j]);
            }
        }

        // ---- stage into other buffer ----
        const int nb = buf ^ 1;
        {
            float a0[4] = {ra0.x, ra0.y, ra0.z, ra0.w};
            float a1[4] = {ra1.x, ra1.y, ra1.z, ra1.w};
            float w0[4] = {rw0.x, rw0.y, rw0.z, rw0.w};
            float w1[4] = {rw1.x, rw1.y, rw1.z, rw1.w};
            const int ato = AT0 + nb * 3072;
            const int wto = WT0 + nb * 1536;
            const int aso = AS0 + nb * 2112;
            const int wso = WS0 + nb * 1088;
            #pragma unroll
            for (int i = 0; i < 4; i++) {
                sm[ato + lr0 * 24 + pb + 2 * i]        = to_tf32(a0[i]);
                sm[ato + (lr0 + 64) * 24 + pb + 2 * i] = to_tf32(a1[i]);
                sm[wto + lr0 * 24 + pb + 2 * i]        = to_tf32(w0[i]);
                sm[aso + (lj * 4 + i) * 132 + lr0]      = a0[i];
                sm[aso + (lj * 4 + i) * 132 + lr0 + 64] = a1[i];
                sm[wso + (lj * 4 + i) * 68 + lr0]       = w1[i];
            }
        }
        __syncthreads();
        buf = nb;
    }

    // ---- tail compute ----
    if (wid < 4) {
        const int ato = AT0 + buf * 3072;
        const int wto = WT0 + buf * 1536;
        #pragma unroll
        for (int ks = 0; ks < 2; ks++) {
            float2 alo[4], ahi[4], bfr[4];
            #pragma unroll
            for (int fm = 0; fm < 4; fm++) {
                alo[fm] = *(const float2*)&sm[ato + (mh + fm * 16 + gr) * 24 + ks * 8 + 2 * gc];
                ahi[fm] = *(const float2*)&sm[ato + (mh + fm * 16 + gr + 8) * 24 + ks * 8 + 2 * gc];
            }
            #pragma unroll
            for (int fn = 0; fn < 4; fn++)
                bfr[fn] = *(const float2*)&sm[wto + (nq + fn * 8 + gr) * 24 + ks * 8 + 2 * gc];
            #pragma unroll
            for (int fm = 0; fm < 4; fm++)
                #pragma unroll
                for (int fn = 0; fn < 4; fn++)
                    mma8(accT[fm][fn], alo[fm].x, ahi[fm].x, alo[fm].y, ahi[fm].y,
                         bfr[fn].x, bfr[fn].y);
        }
        // tensor epilogue: cols n0 + nq + fn*8 + 2gc
        #pragma unroll
        for (int fm = 0; fm < 4; fm++) {
            const int r0 = m0 + mh + fm * 16 + gr;
            #pragma unroll
            for (int fn = 0; fn < 4; fn++) {
                const int c0 = n0 + nq + fn * 8 + 2 * gc;
                float v0 = accT[fm][fn][0], v1 = accT[fm][fn][1];
                float v2 = accT[fm][fn][2], v3 = accT[fm][fn][3];
                if (EPI == 1) {
                    v0 += bias[c0]; v1 += bias[c0 + 1];
                    v2 += bias[c0]; v3 += bias[c0 + 1];
                }
                *(float2*)&C[(size_t)r0 * ldc + c0]       = make_float2(v0, v1);
                *(float2*)&C[(size_t)(r0 + 8) * ldc + c0] = make_float2(v2, v3);
            }
        }
    } else {
        const int aso = AS0 + buf * 2112 + sw * 32 + ty * 8;
        const int wso = WS0 + buf * 1088 + tx * 8;
        #pragma unroll
        for (int k = 0; k < 16; k++) {
            float4 a0 = *(const float4*)&sm[aso + k * 132];
            float4 a1 = *(const float4*)&sm[aso + k * 132 + 4];
            float4 b0 = *(const float4*)&sm[wso + k * 68];
            float4 b1 = *(const float4*)&sm[wso + k * 68 + 4];
            const float a[8] = {a0.x, a0.y, a0.z, a0.w, a1.x, a1.y, a1.z, a1.w};
            const float b[8] = {b0.x, b0.y, b0.z, b0.w, b1.x, b1.y, b1.z, b1.w};
            #pragma unroll
            for (int i = 0; i < 8; i++)
                #pragma unroll
                for (int j = 0; j < 8; j++)
                    accS[i][j] = fmaf(a[i], b[j], accS[i][j]);
        }
        // SIMT epilogue: rows m0 + sw*32 + ty*8 + i, cols n0 + 64 + tx*8 + j
        #pragma unroll
        for (int i = 0; i < 8; i++) {
            const int r = m0 + sw * 32 + ty * 8 + i;
            const int c = n0 + 64 + tx * 8;
            float v[8];
            #pragma unroll
            for (int j = 0; j < 8; j++) {
                v[j] = accS[i][j];
                if (EPI == 1) v[j] += bias[c + j];
            }
            *(float4*)&C[(size_t)r * ldc + c]     = make_float4(v[0], v[1], v[2], v[3]);
            *(float4*)&C[(size_t)r * ldc + c + 4] = make_float4(v[4], v[5], v[6], v[7]);
        }
    }
}

// ---------------------------------------------------------------------------
// TF32 tensor GEMM with N guards (Wx only: N=48, K=512).  R4-proven.
// ---------------------------------------------------------------------------
#define SPAD 24
__global__ void __launch_bounds__(256, 2) tf32_gemm(
    int N, int K,
    const float* __restrict__ A, int lda,
    const float* __restrict__ W,
    float* __restrict__ C, int ldc)
{
    __shared__ float As[2][128][SPAD];
    __shared__ float Ws[2][128][SPAD];

    const int tid  = threadIdx.x;
    const int wid  = tid >> 5, lane = tid & 31;
    const int wm   = (wid >> 2) * 64;
    const int wn   = (wid & 3) * 32;
    const int gr   = lane >> 2;
    const int gc   = lane & 3;
    const int m0   = blockIdx.y * 128;
    const int n0   = blockIdx.x * 128;

    const int lr0 = tid >> 2;
    const int lj  = tid & 3;
    const int pb  = (lj & 2) * 4 + (lj & 1);

    const float* Ag = A + (size_t)(m0 + lr0) * lda + lj * 4;
    const float* Wg = W + (size_t)(n0 + lr0) * K + lj * 4;
    const bool wok0 = (n0 + lr0) < N;
    const bool wok1 = (n0 + lr0 + 64) < N;

    float acc[4][4][4];
    #pragma unroll
    for (int i = 0; i < 4; i++)
        #pragma unroll
        for (int j = 0; j < 4; j++)
            #pragma unroll
            for (int t = 0; t < 4; t++) acc[i][j][t] = 0.f;

    float4 ra0, ra1, rw0, rw1;
    const float4 z4 = make_float4(0.f, 0.f, 0.f, 0.f);

    ra0 = *(const float4*)(Ag);
    ra1 = *(const float4*)(Ag + (size_t)64 * lda);
    rw0 = wok0 ? *(const float4*)(Wg) : z4;
    rw1 = wok1 ? *(const float4*)(Wg + (size_t)64 * K) : z4;
    {
        As[0][lr0     ][pb]     = to_tf32(ra0.x);
        As[0][lr0     ][pb + 2] = to_tf32(ra0.y);
        As[0][lr0     ][pb + 4] = to_tf32(ra0.z);
        As[0][lr0     ][pb + 6] = to_tf32(ra0.w);
        As[0][lr0 + 64][pb]     = to_tf32(ra1.x);
        As[0][lr0 + 64][pb + 2] = to_tf32(ra1.y);
        As[0][lr0 + 64][pb + 4] = to_tf32(ra1.z);
        As[0][lr0 + 64][pb + 6] = to_tf32(ra1.w);
        Ws[0][lr0     ][pb]     = to_tf32(rw0.x);
        Ws[0][lr0     ][pb + 2] = to_tf32(rw0.y);
        Ws[0][lr0     ][pb + 4] = to_tf32(rw0.z);
        Ws[0][lr0     ][pb + 6] = to_tf32(rw0.w);
        Ws[0][lr0 + 64][pb]     = to_tf32(rw1.x);
        Ws[0][lr0 + 64][pb + 2] = to_tf32(rw1.y);
        Ws[0][lr0 + 64][pb + 4] = to_tf32(rw1.z);
        Ws[0][lr0 + 64][pb + 6] = to_tf32(rw1.w);
    }
    __syncthreads();

    int buf = 0;
    for (int k0 = 16; k0 < K; k0 += 16) {
        ra0 = *(const float4*)(Ag + k0);
        ra1 = *(const float4*)(Ag + (size_t)64 * lda + k0);
        rw0 = wok0 ? *(const float4*)(Wg + k0) : z4;
        rw1 = wok1 ? *(const float4*)(Wg + (size_t)64 * K + k0) : z4;

        #pragma unroll
        for (int ks = 0; ks < 2; ks++) {
            float2 alo[4], ahi[4], bfr[4];
            #pragma unroll
            for (int fm = 0; fm < 4; fm++) {
                alo[fm] = *(const float2*)&As[buf][wm + fm * 16 + gr    ][ks * 8 + 2 * gc];
                ahi[fm] = *(const float2*)&As[buf][wm + fm * 16 + gr + 8][ks * 8 + 2 * gc];
            }
            #pragma unroll
            for (int fn = 0; fn < 4; fn++)
                bfr[fn] = *(const float2*)&Ws[buf][wn + fn * 8 + gr][ks * 8 + 2 * gc];
            #pragma unroll
            for (int fm = 0; fm < 4; fm++)
                #pragma unroll
                for (int fn = 0; fn < 4; fn++)
                    mma8(acc[fm][fn], alo[fm].x, ahi[fm].x, alo[fm].y, ahi[fm].y,
                         bfr[fn].x, bfr[fn].y);
        }

        const int nb = buf ^ 1;
        As[nb][lr0     ][pb]     = to_tf32(ra0.x);
        As[nb][lr0     ][pb + 2] = to_tf32(ra0.y);
        As[nb][lr0     ][pb + 4] = to_tf32(ra0.z);
        As[nb][lr0     ][pb + 6] = to_tf32(ra0.w);
        As[nb][lr0 + 64][pb]     = to_tf32(ra1.x);
        As[nb][lr0 + 64][pb + 2] = to_tf32(ra1.y);
        As[nb][lr0 + 64][pb + 4] = to_tf32(ra1.z);
        As[nb][lr0 + 64][pb + 6] = to_tf32(ra1.w);
        Ws[nb][lr0     ][pb]     = to_tf32(rw0.x);
        Ws[nb][lr0     ][pb + 2] = to_tf32(rw0.y);
        Ws[nb][lr0     ][pb + 4] = to_tf32(rw0.z);
        Ws[nb][lr0     ][pb + 6] = to_tf32(rw0.w);
        Ws[nb][lr0 + 64][pb]     = to_tf32(rw1.x);
        Ws[nb][lr0 + 64][pb + 2] = to_tf32(rw1.y);
        Ws[nb][lr0 + 64][pb + 4] = to_tf32(rw1.z);
        Ws[nb][lr0 + 64][pb + 6] = to_tf32(rw1.w);
        __syncthreads();
        buf = nb;
    }

    #pragma unroll
    for (int ks = 0; ks < 2; ks++) {
        float2 alo[4], ahi[4], bfr[4];
        #pragma unroll
        for (int fm = 0; fm < 4; fm++) {
            alo[fm] = *(const float2*)&As[buf][wm + fm * 16 + gr    ][ks * 8 + 2 * gc];
            ahi[fm] = *(const float2*)&As[buf][wm + fm * 16 + gr + 8][ks * 8 + 2 * gc];
        }
        #pragma unroll
        for (int fn = 0; fn < 4; fn++)
            bfr[fn] = *(const float2*)&Ws[buf][wn + fn * 8 + gr][ks * 8 + 2 * gc];
        #pragma unroll
        for (int fm = 0; fm < 4; fm++)
            #pragma unroll
            for (int fn = 0; fn < 4; fn++)
                mma8(acc[fm][fn], alo[fm].x, ahi[fm].x, alo[fm].y, ahi[fm].y,
                     bfr[fn].x, bfr[fn].y);
    }

    #pragma unroll
    for (int fm = 0; fm < 4; fm++) {
        const int r0 = m0 + wm + fm * 16 + gr;
        #pragma unroll
        for (int fn = 0; fn < 4; fn++) {
            const int c0 = n0 + wn + fn * 8 + 2 * gc;
            if (c0 < N) {
                *(float2*)&C[(size_t)r0 * ldc + c0] =
                    make_float2(acc[fm][fn][0], acc[fm][fn][1]);
                *(float2*)&C[(size_t)(r0 + 8) * ldc + c0] =
                    make_float2(acc[fm][fn][2], acc[fm][fn][3]);
            }
        }
    }
}

// ---------------------------------------------------------------------------
// dt = softplus(dtraw @ Wdt^T + bdt): write-bound, one block per row.
// ---------------------------------------------------------------------------
__global__ void __launch_bounds__(512) dt_kernel(
    const float* __restrict__ xdbc, const float* __restrict__ Wdt,
    const float* __restrict__ bdt, float* __restrict__ dt)
{
    __shared__ float dr[16];
    const int row = blockIdx.x;
    const int d   = threadIdx.x;
    if (d < 16) dr[d] = xdbc[(size_t)row * 48 + d];
    __syncthreads();
    float acc = bdt[d];
    const float* w = Wdt + d * 16;
    #pragma unroll
    for (int r = 0; r < 16; r++) acc = fmaf(dr[r], w[r], acc);
    dt[(size_t)row * DIn + d] = softplus_f(acc);
}

// ---------------------------------------------------------------------------
// Depthwise causal conv (DC=4) + bias + SiLU — R4-proven scalar version.
// ---------------------------------------------------------------------------
__global__ void conv_silu_kernel(const float* __restrict__ xz,
                                 const float* __restrict__ w,
                                 const float* __restrict__ cb,
                                 float* __restrict__ u)
{
    const int idx = blockIdx.x * blockDim.x + threadIdx.x;
    if (idx >= Mrows * DIn) return;
    const int d  = idx & (DIn - 1);
    const int bl = idx >> 9;
    const int l  = bl & (Ln - 1);
    float acc = cb[d];
    #pragma unroll
    for (int k = 0; k < 4; k++) {
        const int ll = l - 3 + k;
        if (ll >= 0)
            acc = fmaf(w[d * 4 + k], xz[(size_t)(bl - 3 + k) * (2 * DIn) + d], acc);
    }
    u[idx] = silu_f(acc);
}

// ---------------------------------------------------------------------------
// LayerNorm over last dim (256), one block per row.
// ---------------------------------------------------------------------------
__global__ void ln256_kernel(const float* __restrict__ in, float* __restrict__ out,
                             const float* __restrict__ g, const float* __restrict__ b)
{
    const int row = blockIdx.x;
    const int t = threadIdx.x;
    const float v = in[(size_t)row * 256 + t];
    float s = v, sq = v * v;
    #pragma unroll
    for (int o = 16; o > 0; o >>= 1) {
        s  += __shfl_xor_sync(~0u, s, o);
        sq += __shfl_xor_sync(~0u, sq, o);
    }
    __shared__ float ss[8], ssq[8];
    if ((t & 31) == 0) { ss[t >> 5] = s; ssq[t >> 5] = sq; }
    __syncthreads();
    float tot = 0.f, totq = 0.f;
    #pragma unroll
    for (int i = 0; i < 8; i++) { tot += ss[i]; totq += ssq[i]; }
    const float mean = tot * (1.f / 256.f);
    const float var  = totq * (1.f / 256.f) - mean * mean;
    const float rstd = rsqrtf(var + 1e-5f);
    out[(size_t)row * 256 + t] = (v - mean) * rstd * g[t] + b[t];
}

// ---------------------------------------------------------------------------
// Chunked selective scan (C_CHUNKS=4 chunks of 1024).
// ---------------------------------------------------------------------------
#define SCH 64

__global__ void __launch_bounds__(512) scan_carry_kernel(
    const float* __restrict__ u, const float* __restrict__ dt,
    const float* __restrict__ xdbc, const float* __restrict__ A_log,
    float* __restrict__ Pout, float* __restrict__ h0out)
{
    __shared__ float s_dt[SCH][32], s_u[SCH][32], s_B[SCH][16];

    const int tid = threadIdx.x;
    const int c   = blockIdx.x >> 7;
    const int rem = blockIdx.x & 127;
    const int b   = rem >> 4;
    const int d0  = (rem & 15) * 32;
    const int s   = tid & 15;
    const int dd  = tid >> 4;
    const int d   = d0 + dd;

    const float A = -__expf(A_log[d * DSn + s]);
    float h = 0.f, P = 1.f;

    const size_t base_bl = (size_t)b * Ln + (size_t)c * CH_LEN;

    for (int l0 = 0; l0 < CH_LEN; l0 += SCH) {
        for (int i = tid; i < SCH * 32; i += 512) {
            const int r = i >> 5, cc = i & 31;
            const size_t bl = base_bl + l0 + r;
            s_dt[r][cc] = dt[bl * DIn + d0 + cc];
            s_u [r][cc] = u [bl * DIn + d0 + cc];
        }
        for (int i = tid; i < SCH * 16; i += 512) {
            const int r = i >> 4, cc = i & 15;
            const size_t bl = base_bl + l0 + r;
            s_B[r][cc] = xdbc[bl * 48 + 16 + cc];
        }
        __syncthreads();

        #pragma unroll 4
        for (int i = 0; i < SCH; i++) {
            const float dtv = s_dt[i][dd];
            const float dA  = __expf(dtv * A);
            P *= dA;
            h = fmaf(h, dA, dtv * s_u[i][dd] * s_B[i][s]);
        }
        __syncthreads();
    }

    const int ch = ((b * DIn + d) * DSn + s);
    Pout [c * NCH + ch] = P;
    h0out[c * NCH + ch] = h;
}

__global__ void scan_fix_kernel(const float* __restrict__ P,
                                const float* __restrict__ h0,
                                float* __restrict__ hini)
{
    const int ch = blockIdx.x * blockDim.x + threadIdx.x;
    float h = 0.f;
    hini[ch] = 0.f;
    #pragma unroll
    for (int c = 1; c < C_CHUNKS; c++) {
        h = fmaf(P[(c - 1) * NCH + ch], h, h0[(c - 1) * NCH + ch]);
        hini[c * NCH + ch] = h;
    }
}

__global__ void __launch_bounds__(512) scan_main_kernel(
    const float* __restrict__ u, const float* __restrict__ dt,
    const float* __restrict__ xz, const float* __restrict__ xdbc,
    const float* __restrict__ A_log, const float* __restrict__ Dp,
    const float* __restrict__ hini,
    float* __restrict__ y)
{
    __shared__ float s_dt[SCH][32], s_u[SCH][32], s_z[SCH][32], s_y[SCH][32];
    __shared__ float s_B[SCH][16], s_C[SCH][16];

    const int tid = threadIdx.x;
    const int c   = blockIdx.x >> 7;
    const int rem = blockIdx.x & 127;
    const int b   = rem >> 4;
    const int d0  = (rem & 15) * 32;
    const int s   = tid & 15;
    const int dd  = tid >> 4;
    const int d   = d0 + dd;

    const float A   = -__expf(A_log[d * DSn + s]);
    const float dpv = Dp[d];
    const int ch = ((b * DIn + d) * DSn + s);
    float h = hini[c * NCH + ch];

    const size_t base_bl = (size_t)b * Ln + (size_t)c * CH_LEN;

    for (int l0 = 0; l0 < CH_LEN; l0 += SCH) {
        for (int i = tid; i < SCH * 32; i += 512) {
            const int r = i >> 5, cc = i & 31;
            const size_t bl = base_bl + l0 + r;
            s_dt[r][cc] = dt[bl * DIn + d0 + cc];
            s_u [r][cc] = u [bl * DIn + d0 + cc];
            s_z [r][cc] = xz[bl * (2 * DIn) + DIn + d0 + cc];
        }
        for (int i = tid; i < SCH * 16; i += 512) {
            const int r = i >> 4, cc = i & 15;
            const size_t bl = base_bl + l0 + r;
            s_B[r][cc] = xdbc[bl * 48 + 16 + cc];
            s_C[r][cc] = xdbc[bl * 48 + 32 + cc];
        }
        __syncthreads();

        #pragma unroll 4
        for (int i = 0; i < SCH; i++) {
            const float dtv = s_dt[i][dd];
            const float uv  = s_u[i][dd];
            const float dA  = __expf(dtv * A);
            h = fmaf(h, dA, dtv * uv * s_B[i][s]);
            float yv = h * s_C[i][s];
            yv += __shfl_xor_sync(~0u, yv, 1);
            yv += __shfl_xor_sync(~0u, yv, 2);
            yv += __shfl_xor_sync(~0u, yv, 4);
            yv += __shfl_xor_sync(~0u, yv, 8);
            if (s == 0) {
                const float zv = s_z[i][dd];
                s_y[i][dd] = (yv + uv * dpv) * silu_f(zv);
            }
        }
        __syncthreads();

        for (int i = tid; i < SCH * 32; i += 512) {
            const int r = i >> 5, cc = i & 31;
            y[(base_bl + l0 + r) * DIn + d0 + cc] = s_y[r][cc];
        }
        __syncthreads();
    }
}

// ---------------------------------------------------------------------------
// Pooling, split for chip-wide bandwidth.
// ---------------------------------------------------------------------------
__global__ void pool_logit_kernel(const float* __restrict__ h,
                                  const float* __restrict__ wa,
                                  const float* __restrict__ ba,
                                  float* __restrict__ logit)
{
    const int wid_in_blk = threadIdx.x >> 5;
    const int lane = threadIdx.x & 31;
    const int row = blockIdx.x * 8 + wid_in_blk;
    const float* r = h + (size_t)row * 256;
    float acc = 0.f;
    #pragma unroll
    for (int k = 0; k < 2; k++) {
        const float4 hv = *(const float4*)(r + k * 128 + lane * 4);
        const float4 wv = *(const float4*)(wa + k * 128 + lane * 4);
        acc += hv.x * wv.x + hv.y * wv.y + hv.z * wv.z + hv.w * wv.w;
    }
    #pragma unroll
    for (int o = 16; o > 0; o >>= 1) acc += __shfl_xor_sync(~0u, acc, o);
    if (lane == 0) logit[row] = acc + ba[0];
}

__global__ void __launch_bounds__(1024) pool_softmax_kernel(float* __restrict__ logit)
{
    __shared__ float s_red[32];
    const int b = blockIdx.x, tid = threadIdx.x;
    float* lg = logit + b * Ln;

    float mx = -1e30f;
    float v[4];
    #pragma unroll
    for (int k = 0; k < 4; k++) {
        v[k] = lg[tid + k * 1024];
        mx = fmaxf(mx, v[k]);
    }
    #pragma unroll
    for (int o = 16; o > 0; o >>= 1) mx = fmaxf(mx, __shfl_xor_sync(~0u, mx, o));
    if ((tid & 31) == 0) s_red[tid >> 5] = mx;
    __syncthreads();
    if (tid < 32) {
        float t = s_red[tid];
        #pragma unroll
        for (int o = 16; o > 0; o >>= 1) t = fmaxf(t, __shfl_xor_sync(~0u, t, o));
        s_red[tid] = t;
    }
    __syncthreads();
    mx = s_red[0];
    __syncthreads();

    float sum = 0.f;
    #pragma unroll
    for (int k = 0; k < 4; k++) {
        v[k] = __expf(v[k] - mx);
        sum += v[k];
    }
    #pragma unroll
    for (int o = 16; o > 0; o >>= 1) sum += __shfl_xor_sync(~0u, sum, o);
    if ((tid & 31) == 0) s_red[tid >> 5] = sum;
    __syncthreads();
    if (tid < 32) {
        float t = s_red[tid];
        #pragma unroll
        for (int o = 16; o > 0; o >>= 1) t += __shfl_xor_sync(~0u, t, o);
        s_red[tid] = t;
    }
    __syncthreads();
    const float inv = 1.f / s_red[0];
    #pragma unroll
    for (int k = 0; k < 4; k++) lg[tid + k * 1024] = v[k] * inv;
}

__global__ void pool_wsum_kernel(const float* __restrict__ h,
                                 const float* __restrict__ p,
                                 float* __restrict__ part)
{
    const int b = blockIdx.x >> 4;
    const int sp = blockIdx.x & 15;
    const int tid = threadIdx.x;
    const size_t base = ((size_t)b * Ln + sp * 256) * 256;
    const float* pp = p + b * Ln + sp * 256;
    float acc = 0.f;
    for (int l = 0; l < 256; l++)
        acc = fmaf(pp[l], h[base + (size_t)l * 256 + tid], acc);
    part[(size_t)(b * 16 + sp) * 256 + tid] = acc;
}

__global__ void pool_final_kernel(const float* __restrict__ part,
                                  const float* __restrict__ Wf,
                                  const float* __restrict__ bf,
                                  float* __restrict__ out)
{
    __shared__ float s_red[8];
    const int b = blockIdx.x, tid = threadIdx.x;
    float pooled = 0.f;
    #pragma unroll
    for (int sp = 0; sp < 16; sp++)
        pooled += part[(size_t)(b * 16 + sp) * 256 + tid];
    float val = pooled * Wf[tid];
    #pragma unroll
    for (int o = 16; o > 0; o >>= 1) val += __shfl_xor_sync(~0u, val, o);
    if ((tid & 31) == 0) s_red[tid >> 5] = val;
    __syncthreads();
    if (tid == 0) {
        float tot = 0.f;
        #pragma unroll
        for (int i = 0; i < 8; i++) tot += s_red[i];
        out[b] = tot + bf[0];
    }
}

// ---------------------------------------------------------------------------
// Launch
// ---------------------------------------------------------------------------
extern "C" void kernel_launch(void* const* d_in, const int* in_sizes, int n_in,
                              void* d_out, int out_size)
{
    const float* x      = (const float*)d_in[0];
    const float* Wp     = (const float*)d_in[1];
    const float* bp     = (const float*)d_in[2];
    const float* g0     = (const float*)d_in[3];
    const float* b0     = (const float*)d_in[4];
    const float* Wi     = (const float*)d_in[5];
    const float* conv_w = (const float*)d_in[6];
    const float* conv_b = (const float*)d_in[7];
    const float* Wx     = (const float*)d_in[8];
    const float* Wdt    = (const float*)d_in[9];
    const float* bdt    = (const float*)d_in[10];
    const float* A_log  = (const float*)d_in[11];
    const float* Dp     = (const float*)d_in[12];
    const float* Wo     = (const float*)d_in[13];
    const float* ln_g   = (const float*)d_in[14];
    const float* ln_b   = (const float*)d_in[15];
    const float* wa     = (const float*)d_in[16];
    const float* ba     = (const float*)d_in[17];
    const float* Wf     = (const float*)d_in[18];
    const float* bf     = (const float*)d_in[19];

    float *p_h, *p_t0, *p_xz, *p_u, *p_dt, *p_xdbc, *p_y;
    float *p_P, *p_h0, *p_hini, *p_logit, *p_part;
    cudaGetSymbolAddress((void**)&p_h,    g_h);
    cudaGetSymbolAddress((void**)&p_t0,   g_t0);
    cudaGetSymbolAddress((void**)&p_xz,   g_xz);
    cudaGetSymbolAddress((void**)&p_u,    g_u);
    cudaGetSymbolAddress((void**)&p_dt,   g_dt);
    cudaGetSymbolAddress((void**)&p_xdbc, g_xdbc);
    cudaGetSymbolAddress((void**)&p_y,    g_y);
    cudaGetSymbolAddress((void**)&p_P,    g_P);
    cudaGetSymbolAddress((void**)&p_h0,   g_h0);
    cudaGetSymbolAddress((void**)&p_hini, g_hini);
    cudaGetSymbolAddress((void**)&p_logit, g_logit);
    cudaGetSymbolAddress((void**)&p_part, g_part);

    cudaFuncSetAttribute(hyb_gemm<0>,
        cudaFuncAttributeMaxDynamicSharedMemorySize, HYB_SMEM_BYTES);
    cudaFuncSetAttribute(hyb_gemm<1>,
        cudaFuncAttributeMaxDynamicSharedMemorySize, HYB_SMEM_BYTES);

    // input projection + bias (hybrid) + LN
    hyb_gemm<1><<<dim3(2, 256), 256, HYB_SMEM_BYTES>>>(
        Dn, DINn, x, DINn, Wp, bp, p_t0, Dn);
    ln256_kernel<<<Mrows, 256>>>(p_t0, p_h, g0, b0);

    for (int l = 0; l < NLn; l++) {
        // xz = h @ Wi^T  (N=1024, K=256) — hybrid
        hyb_gemm<0><<<dim3(8, 256), 256, HYB_SMEM_BYTES>>>(
            2 * DIn, Dn, p_h, Dn, Wi + (size_t)l * 2 * DIn * Dn,
            nullptr, p_xz, 2 * DIn);
        // depthwise causal conv + silu
        conv_silu_kernel<<<(Mrows * DIn) / 256, 256>>>(
            p_xz, conv_w + (size_t)l * DIn * DCn, conv_b + (size_t)l * DIn, p_u);
        // xdbc = u @ Wx^T  (N=48, K=512) — guarded tensor
        tf32_gemm<<<dim3(1, 256), 256>>>(48, DIn, p_u, DIn,
                                         Wx + (size_t)l * 48 * DIn, p_xdbc, 48);
        // dt
        dt_kernel<<<Mrows, 512>>>(p_xdbc, Wdt + (size_t)l * DIn * DTRn,
                                  bdt + (size_t)l * DIn, p_dt);
        // chunked selective scan
        scan_carry_kernel<<<128 * (C_CHUNKS - 1), 512>>>(
            p_u, p_dt, p_xdbc, A_log + (size_t)l * DIn * DSn, p_P, p_h0);
        scan_fix_kernel<<<NCH / 256, 256>>>(p_P, p_h0, p_hini);
        scan_main_kernel<<<128 * C_CHUNKS, 512>>>(
            p_u, p_dt, p_xz, p_xdbc,
            A_log + (size_t)l * DIn * DSn, Dp + (size_t)l * DIn,
            p_hini, p_y);
        // out = y @ Wo^T  (N=256, K=512) — hybrid, then LN
        hyb_gemm<0><<<dim3(2, 256), 256, HYB_SMEM_BYTES>>>(
            Dn, DIn, p_y, DIn, Wo + (size_t)l * Dn * DIn,
            nullptr, p_t0, Dn);
        ln256_kernel<<<Mrows, 256>>>(p_t0, p_h,
                                     ln_g + (size_t)l * Dn, ln_b + (size_t)l * Dn);
    }

    // pooling + final linear
    pool_logit_kernel<<<Mrows / 8, 256>>>(p_h, wa, ba, p_logit);
    pool_softmax_kernel<<<Bn, 1024>>>(p_logit);
    pool_wsum_kernel<<<Bn * 16, 256>>>(p_h, p_logit, p_part);
    pool_final_kernel<<<Bn, 256>>>(p_part, Wf, bf, (float*)d_out);
}

// round 8
// speedup vs baseline: 1.3769x; 1.3769x over previous
#include <cuda_runtime.h>
#include <math.h>
#include <stdint.h>

// Problem constants
#define Bn   8
#define Ln   4096
#define DINn 64
#define Dn   256
#define NLn  2
#define DIn  512
#define DSn  16
#define DCn  4
#define DTRn 16
#define Mrows (Bn * Ln)   // 32768

#define C_CHUNKS 4
#define CH_LEN   1024     // Ln / C_CHUNKS
#define NCH      (Bn * DIn * DSn)   // 65536 channels

// ---------------------------------------------------------------------------
// Scratch (device globals — no runtime allocation allowed)
// ---------------------------------------------------------------------------
__device__ float g_h    [Mrows * Dn];
__device__ float g_t0   [Mrows * Dn];
__device__ float g_xz   [Mrows * 2 * DIn];
__device__ float g_u    [Mrows * DIn];
__device__ float g_dt   [Mrows * DIn];
__device__ float g_xdbc [Mrows * 48];
__device__ float g_y    [Mrows * DIn];
__device__ float g_P    [(C_CHUNKS - 1) * NCH];
__device__ float g_h0   [(C_CHUNKS - 1) * NCH];
__device__ float g_hini [C_CHUNKS * NCH];
__device__ float g_logit[Mrows];
__device__ float g_part [Bn * 16 * Dn];

// ---------------------------------------------------------------------------
// Helpers
// ---------------------------------------------------------------------------
__device__ __forceinline__ float softplus_f(float x) {
    return fmaxf(x, 0.f) + log1pf(__expf(-fabsf(x)));
}
__device__ __forceinline__ float silu_f(float x) {
    return x / (1.f + __expf(-x));
}
__device__ __forceinline__ float to_tf32(float x) {
    float r;
    asm("cvt.rna.tf32.f32 %0, %1;" : "=f"(r) : "f"(x));
    return r;
}
__device__ __forceinline__ void mma8(float* d,
                                     float a0, float a1, float a2, float a3,
                                     float b0, float b1) {
    asm volatile(
        "mma.sync.aligned.m16n8k8.row.col.f32.tf32.tf32.f32 "
        "{%0,%1,%2,%3},{%4,%5,%6,%7},{%8,%9},{%0,%1,%2,%3};"
        : "+f"(d[0]), "+f"(d[1]), "+f"(d[2]), "+f"(d[3])
        : "r"(__float_as_uint(a0)), "r"(__float_as_uint(a1)),
          "r"(__float_as_uint(a2)), "r"(__float_as_uint(a3)),
          "r"(__float_as_uint(b0)), "r"(__float_as_uint(b1)));
}

// ---------------------------------------------------------------------------
// TF32 tensor-core GEMM: C[M,N] = A[M,K] (row-major, lda) * W[N,K]^T.
// M%128==0, K%16==0. N arbitrary (guards on W loads + stores).
// Tile 128x128x16, 256 threads, warp tile 64x32 of m16n8k8.  (R4-proven.)
// EPI: 0 = store, 1 = +bias
// ---------------------------------------------------------------------------
#define SPAD 24
template <int EPI>
__global__ void __launch_bounds__(256, 2) tf32_gemm(
    int N, int K,
    const float* __restrict__ A, int lda,
    const float* __restrict__ W,
    const float* __restrict__ bias,
    float* __restrict__ C, int ldc)
{
    __shared__ float As[2][128][SPAD];
    __shared__ float Ws[2][128][SPAD];

    const int tid  = threadIdx.x;
    const int wid  = tid >> 5, lane = tid & 31;
    const int wm   = (wid >> 2) * 64;
    const int wn   = (wid & 3) * 32;
    const int gr   = lane >> 2;
    const int gc   = lane & 3;
    const int m0   = blockIdx.y * 128;
    const int n0   = blockIdx.x * 128;

    const int lr0 = tid >> 2;
    const int lj  = tid & 3;
    const int pb  = (lj & 2) * 4 + (lj & 1);

    const float* Ag = A + (size_t)(m0 + lr0) * lda + lj * 4;
    const float* Wg = W + (size_t)(n0 + lr0) * K + lj * 4;
    const bool wok0 = (n0 + lr0) < N;
    const bool wok1 = (n0 + lr0 + 64) < N;

    float acc[4][4][4];
    #pragma unroll
    for (int i = 0; i < 4; i++)
        #pragma unroll
        for (int j = 0; j < 4; j++)
            #pragma unroll
            for (int t = 0; t < 4; t++) acc[i][j][t] = 0.f;

    float4 ra0, ra1, rw0, rw1;
    const float4 z4 = make_float4(0.f, 0.f, 0.f, 0.f);

    ra0 = *(const float4*)(Ag);
    ra1 = *(const float4*)(Ag + (size_t)64 * lda);
    rw0 = wok0 ? *(const float4*)(Wg) : z4;
    rw1 = wok1 ? *(const float4*)(Wg + (size_t)64 * K) : z4;
    {
        As[0][lr0     ][pb]     = to_tf32(ra0.x);
        As[0][lr0     ][pb + 2] = to_tf32(ra0.y);
        As[0][lr0     ][pb + 4] = to_tf32(ra0.z);
        As[0][lr0     ][pb + 6] = to_tf32(ra0.w);
        As[0][lr0 + 64][pb]     = to_tf32(ra1.x);
        As[0][lr0 + 64][pb + 2] = to_tf32(ra1.y);
        As[0][lr0 + 64][pb + 4] = to_tf32(ra1.z);
        As[0][lr0 + 64][pb + 6] = to_tf32(ra1.w);
        Ws[0][lr0     ][pb]     = to_tf32(rw0.x);
        Ws[0][lr0     ][pb + 2] = to_tf32(rw0.y);
        Ws[0][lr0     ][pb + 4] = to_tf32(rw0.z);
        Ws[0][lr0     ][pb + 6] = to_tf32(rw0.w);
        Ws[0][lr0 + 64][pb]     = to_tf32(rw1.x);
        Ws[0][lr0 + 64][pb + 2] = to_tf32(rw1.y);
        Ws[0][lr0 + 64][pb + 4] = to_tf32(rw1.z);
        Ws[0][lr0 + 64][pb + 6] = to_tf32(rw1.w);
    }
    __syncthreads();

    int buf = 0;
    for (int k0 = 16; k0 < K; k0 += 16) {
        ra0 = *(const float4*)(Ag + k0);
        ra1 = *(const float4*)(Ag + (size_t)64 * lda + k0);
        rw0 = wok0 ? *(const float4*)(Wg + k0) : z4;
        rw1 = wok1 ? *(const float4*)(Wg + (size_t)64 * K + k0) : z4;

        #pragma unroll
        for (int ks = 0; ks < 2; ks++) {
            float2 alo[4], ahi[4], bfr[4];
            #pragma unroll
            for (int fm = 0; fm < 4; fm++) {
                alo[fm] = *(const float2*)&As[buf][wm + fm * 16 + gr    ][ks * 8 + 2 * gc];
                ahi[fm] = *(const float2*)&As[buf][wm + fm * 16 + gr + 8][ks * 8 + 2 * gc];
            }
            #pragma unroll
            for (int fn = 0; fn < 4; fn++)
                bfr[fn] = *(const float2*)&Ws[buf][wn + fn * 8 + gr][ks * 8 + 2 * gc];
            #pragma unroll
            for (int fm = 0; fm < 4; fm++)
                #pragma unroll
                for (int fn = 0; fn < 4; fn++)
                    mma8(acc[fm][fn], alo[fm].x, ahi[fm].x, alo[fm].y, ahi[fm].y,
                         bfr[fn].x, bfr[fn].y);
        }

        const int nb = buf ^ 1;
        As[nb][lr0     ][pb]     = to_tf32(ra0.x);
        As[nb][lr0     ][pb + 2] = to_tf32(ra0.y);
        As[nb][lr0     ][pb + 4] = to_tf32(ra0.z);
        As[nb][lr0     ][pb + 6] = to_tf32(ra0.w);
        As[nb][lr0 + 64][pb]     = to_tf32(ra1.x);
        As[nb][lr0 + 64][pb + 2] = to_tf32(ra1.y);
        As[nb][lr0 + 64][pb + 4] = to_tf32(ra1.z);
        As[nb][lr0 + 64][pb + 6] = to_tf32(ra1.w);
        Ws[nb][lr0     ][pb]     = to_tf32(rw0.x);
        Ws[nb][lr0     ][pb + 2] = to_tf32(rw0.y);
        Ws[nb][lr0     ][pb + 4] = to_tf32(rw0.z);
        Ws[nb][lr0     ][pb + 6] = to_tf32(rw0.w);
        Ws[nb][lr0 + 64][pb]     = to_tf32(rw1.x);
        Ws[nb][lr0 + 64][pb + 2] = to_tf32(rw1.y);
        Ws[nb][lr0 + 64][pb + 4] = to_tf32(rw1.z);
        Ws[nb][lr0 + 64][pb + 6] = to_tf32(rw1.w);
        __syncthreads();
        buf = nb;
    }

    #pragma unroll
    for (int ks = 0; ks < 2; ks++) {
        float2 alo[4], ahi[4], bfr[4];
        #pragma unroll
        for (int fm = 0; fm < 4; fm++) {
            alo[fm] = *(const float2*)&As[buf][wm + fm * 16 + gr    ][ks * 8 + 2 * gc];
            ahi[fm] = *(const float2*)&As[buf][wm + fm * 16 + gr + 8][ks * 8 + 2 * gc];
        }
        #pragma unroll
        for (int fn = 0; fn < 4; fn++)
            bfr[fn] = *(const float2*)&Ws[buf][wn + fn * 8 + gr][ks * 8 + 2 * gc];
        #pragma unroll
        for (int fm = 0; fm < 4; fm++)
            #pragma unroll
            for (int fn = 0; fn < 4; fn++)
                mma8(acc[fm][fn], alo[fm].x, ahi[fm].x, alo[fm].y, ahi[fm].y,
                     bfr[fn].x, bfr[fn].y);
    }

    #pragma unroll
    for (int fm = 0; fm < 4; fm++) {
        const int r0 = m0 + wm + fm * 16 + gr;
        #pragma unroll
        for (int fn = 0; fn < 4; fn++) {
            const int c0 = n0 + wn + fn * 8 + 2 * gc;
            if (c0 < N) {
                float v0 = acc[fm][fn][0], v1 = acc[fm][fn][1];
                float v2 = acc[fm][fn][2], v3 = acc[fm][fn][3];
                if (EPI == 1) {
                    v0 += bias[c0]; v1 += bias[c0 + 1];
                    v2 += bias[c0]; v3 += bias[c0 + 1];
                }
                *(float2*)&C[(size_t)r0 * ldc + c0]       = make_float2(v0, v1);
                *(float2*)&C[(size_t)(r0 + 8) * ldc + c0] = make_float2(v2, v3);
            }
        }
    }
}

// ---------------------------------------------------------------------------
// dt = softplus(dtraw @ Wdt^T + bdt): write-bound, one block per row.
// ---------------------------------------------------------------------------
__global__ void __launch_bounds__(512) dt_kernel(
    const float* __restrict__ xdbc, const float* __restrict__ Wdt,
    const float* __restrict__ bdt, float* __restrict__ dt)
{
    __shared__ float dr[16];
    const int row = blockIdx.x;
    const int d   = threadIdx.x;
    if (d < 16) dr[d] = xdbc[(size_t)row * 48 + d];
    __syncthreads();
    float acc = bdt[d];
    const float* w = Wdt + d * 16;
    #pragma unroll
    for (int r = 0; r < 16; r++) acc = fmaf(dr[r], w[r], acc);
    dt[(size_t)row * DIn + d] = softplus_f(acc);
}

// ---------------------------------------------------------------------------
// Depthwise causal conv (DC=4) + bias + SiLU — R4-proven scalar version.
// ---------------------------------------------------------------------------
__global__ void conv_silu_kernel(const float* __restrict__ xz,
                                 const float* __restrict__ w,
                                 const float* __restrict__ cb,
                                 float* __restrict__ u)
{
    const int idx = blockIdx.x * blockDim.x + threadIdx.x;
    if (idx >= Mrows * DIn) return;
    const int d  = idx & (DIn - 1);
    const int bl = idx >> 9;
    const int l  = bl & (Ln - 1);
    float acc = cb[d];
    #pragma unroll
    for (int k = 0; k < 4; k++) {
        const int ll = l - 3 + k;
        if (ll >= 0)
            acc = fmaf(w[d * 4 + k], xz[(size_t)(bl - 3 + k) * (2 * DIn) + d], acc);
    }
    u[idx] = silu_f(acc);
}

// ---------------------------------------------------------------------------
// LayerNorm over last dim (256), one block per row.
// ---------------------------------------------------------------------------
__global__ void ln256_kernel(const float* __restrict__ in, float* __restrict__ out,
                             const float* __restrict__ g, const float* __restrict__ b)
{
    const int row = blockIdx.x;
    const int t = threadIdx.x;
    const float v = in[(size_t)row * 256 + t];
    float s = v, sq = v * v;
    #pragma unroll
    for (int o = 16; o > 0; o >>= 1) {
        s  += __shfl_xor_sync(~0u, s, o);
        sq += __shfl_xor_sync(~0u, sq, o);
    }
    __shared__ float ss[8], ssq[8];
    if ((t & 31) == 0) { ss[t >> 5] = s; ssq[t >> 5] = sq; }
    __syncthreads();
    float tot = 0.f, totq = 0.f;
    #pragma unroll
    for (int i = 0; i < 8; i++) { tot += ss[i]; totq += ssq[i]; }
    const float mean = tot * (1.f / 256.f);
    const float var  = totq * (1.f / 256.f) - mean * mean;
    const float rstd = rsqrtf(var + 1e-5f);
    out[(size_t)row * 256 + t] = (v - mean) * rstd * g[t] + b[t];
}

// ---------------------------------------------------------------------------
// Chunked selective scan (C_CHUNKS=4 chunks of 1024).
// ---------------------------------------------------------------------------
#define SCH 64

__global__ void __launch_bounds__(512) scan_carry_kernel(
    const float* __restrict__ u, const float* __restrict__ dt,
    const float* __restrict__ xdbc, const float* __restrict__ A_log,
    float* __restrict__ Pout, float* __restrict__ h0out)
{
    __shared__ float s_dt[SCH][32], s_u[SCH][32], s_B[SCH][16];

    const int tid = threadIdx.x;
    const int c   = blockIdx.x >> 7;
    const int rem = blockIdx.x & 127;
    const int b   = rem >> 4;
    const int d0  = (rem & 15) * 32;
    const int s   = tid & 15;
    const int dd  = tid >> 4;
    const int d   = d0 + dd;

    const float A = -__expf(A_log[d * DSn + s]);
    float h = 0.f, P = 1.f;

    const size_t base_bl = (size_t)b * Ln + (size_t)c * CH_LEN;

    for (int l0 = 0; l0 < CH_LEN; l0 += SCH) {
        for (int i = tid; i < SCH * 32; i += 512) {
            const int r = i >> 5, cc = i & 31;
            const size_t bl = base_bl + l0 + r;
            s_dt[r][cc] = dt[bl * DIn + d0 + cc];
            s_u [r][cc] = u [bl * DIn + d0 + cc];
        }
        for (int i = tid; i < SCH * 16; i += 512) {
            const int r = i >> 4, cc = i & 15;
            const size_t bl = base_bl + l0 + r;
            s_B[r][cc] = xdbc[bl * 48 + 16 + cc];
        }
        __syncthreads();

        #pragma unroll 4
        for (int i = 0; i < SCH; i++) {
            const float dtv = s_dt[i][dd];
            const float dA  = __expf(dtv * A);
            P *= dA;
            h = fmaf(h, dA, dtv * s_u[i][dd] * s_B[i][s]);
        }
        __syncthreads();
    }

    const int ch = ((b * DIn + d) * DSn + s);
    Pout [c * NCH + ch] = P;
    h0out[c * NCH + ch] = h;
}

__global__ void scan_fix_kernel(const float* __restrict__ P,
                                const float* __restrict__ h0,
                                float* __restrict__ hini)
{
    const int ch = blockIdx.x * blockDim.x + threadIdx.x;
    float h = 0.f;
    hini[ch] = 0.f;
    #pragma unroll
    for (int c = 1; c < C_CHUNKS; c++) {
        h = fmaf(P[(c - 1) * NCH + ch], h, h0[(c - 1) * NCH + ch]);
        hini[c * NCH + ch] = h;
    }
}

__global__ void __launch_bounds__(512) scan_main_kernel(
    const float* __restrict__ u, const float* __restrict__ dt,
    const float* __restrict__ xz, const float* __restrict__ xdbc,
    const float* __restrict__ A_log, const float* __restrict__ Dp,
    const float* __restrict__ hini,
    float* __restrict__ y)
{
    __shared__ float s_dt[SCH][32], s_u[SCH][32], s_z[SCH][32], s_y[SCH][32];
    __shared__ float s_B[SCH][16], s_C[SCH][16];

    const int tid = threadIdx.x;
    const int c   = blockIdx.x >> 7;
    const int rem = blockIdx.x & 127;
    const int b   = rem >> 4;
    const int d0  = (rem & 15) * 32;
    const int s   = tid & 15;
    const int dd  = tid >> 4;
    const int d   = d0 + dd;

    const float A   = -__expf(A_log[d * DSn + s]);
    const float dpv = Dp[d];
    const int ch = ((b * DIn + d) * DSn + s);
    float h = hini[c * NCH + ch];

    const size_t base_bl = (size_t)b * Ln + (size_t)c * CH_LEN;

    for (int l0 = 0; l0 < CH_LEN; l0 += SCH) {
        for (int i = tid; i < SCH * 32; i += 512) {
            const int r = i >> 5, cc = i & 31;
            const size_t bl = base_bl + l0 + r;
            s_dt[r][cc] = dt[bl * DIn + d0 + cc];
            s_u [r][cc] = u [bl * DIn + d0 + cc];
            s_z [r][cc] = xz[bl * (2 * DIn) + DIn + d0 + cc];
        }
        for (int i = tid; i < SCH * 16; i += 512) {
            const int r = i >> 4, cc = i & 15;
            const size_t bl = base_bl + l0 + r;
            s_B[r][cc] = xdbc[bl * 48 + 16 + cc];
            s_C[r][cc] = xdbc[bl * 48 + 32 + cc];
        }
        __syncthreads();

        #pragma unroll 4
        for (int i = 0; i < SCH; i++) {
            const float dtv = s_dt[i][dd];
            const float uv  = s_u[i][dd];
            const float dA  = __expf(dtv * A);
            h = fmaf(h, dA, dtv * uv * s_B[i][s]);
            float yv = h * s_C[i][s];
            yv += __shfl_xor_sync(~0u, yv, 1);
            yv += __shfl_xor_sync(~0u, yv, 2);
            yv += __shfl_xor_sync(~0u, yv, 4);
            yv += __shfl_xor_sync(~0u, yv, 8);
            if (s == 0) {
                const float zv = s_z[i][dd];
                s_y[i][dd] = (yv + uv * dpv) * silu_f(zv);
            }
        }
        __syncthreads();

        for (int i = tid; i < SCH * 32; i += 512) {
            const int r = i >> 5, cc = i & 31;
            y[(base_bl + l0 + r) * DIn + d0 + cc] = s_y[r][cc];
        }
        __syncthreads();
    }
}

// ---------------------------------------------------------------------------
// Pooling, split for chip-wide bandwidth.
// ---------------------------------------------------------------------------
__global__ void pool_logit_kernel(const float* __restrict__ h,
                                  const float* __restrict__ wa,
                                  const float* __restrict__ ba,
                                  float* __restrict__ logit)
{
    const int wid_in_blk = threadIdx.x >> 5;
    const int lane = threadIdx.x & 31;
    const int row = blockIdx.x * 8 + wid_in_blk;
    const float* r = h + (size_t)row * 256;
    float acc = 0.f;
    #pragma unroll
    for (int k = 0; k < 2; k++) {
        const float4 hv = *(const float4*)(r + k * 128 + lane * 4);
        const float4 wv = *(const float4*)(wa + k * 128 + lane * 4);
        acc += hv.x * wv.x + hv.y * wv.y + hv.z * wv.z + hv.w * wv.w;
    }
    #pragma unroll
    for (int o = 16; o > 0; o >>= 1) acc += __shfl_xor_sync(~0u, acc, o);
    if (lane == 0) logit[row] = acc + ba[0];
}

__global__ void __launch_bounds__(1024) pool_softmax_kernel(float* __restrict__ logit)
{
    __shared__ float s_red[32];
    const int b = blockIdx.x, tid = threadIdx.x;
    float* lg = logit + b * Ln;

    float mx = -1e30f;
    float v[4];
    #pragma unroll
    for (int k = 0; k < 4; k++) {
        v[k] = lg[tid + k * 1024];
        mx = fmaxf(mx, v[k]);
    }
    #pragma unroll
    for (int o = 16; o > 0; o >>= 1) mx = fmaxf(mx, __shfl_xor_sync(~0u, mx, o));
    if ((tid & 31) == 0) s_red[tid >> 5] = mx;
    __syncthreads();
    if (tid < 32) {
        float t = s_red[tid];
        #pragma unroll
        for (int o = 16; o > 0; o >>= 1) t = fmaxf(t, __shfl_xor_sync(~0u, t, o));
        s_red[tid] = t;
    }
    __syncthreads();
    mx = s_red[0];
    __syncthreads();

    float sum = 0.f;
    #pragma unroll
    for (int k = 0; k < 4; k++) {
        v[k] = __expf(v[k] - mx);
        sum += v[k];
    }
    #pragma unroll
    for (int o = 16; o > 0; o >>= 1) sum += __shfl_xor_sync(~0u, sum, o);
    if ((tid & 31) == 0) s_red[tid >> 5] = sum;
    __syncthreads();
    if (tid < 32) {
        float t = s_red[tid];
        #pragma unroll
        for (int o = 16; o > 0; o >>= 1) t += __shfl_xor_sync(~0u, t, o);
        s_red[tid] = t;
    }
    __syncthreads();
    const float inv = 1.f / s_red[0];
    #pragma unroll
    for (int k = 0; k < 4; k++) lg[tid + k * 1024] = v[k] * inv;
}

__global__ void pool_wsum_kernel(const float* __restrict__ h,
                                 const float* __restrict__ p,
                                 float* __restrict__ part)
{
    const int b = blockIdx.x >> 4;
    const int sp = blockIdx.x & 15;
    const int tid = threadIdx.x;
    const size_t base = ((size_t)b * Ln + sp * 256) * 256;
    const float* pp = p + b * Ln + sp * 256;
    float acc = 0.f;
    for (int l = 0; l < 256; l++)
        acc = fmaf(pp[l], h[base + (size_t)l * 256 + tid], acc);
    part[(size_t)(b * 16 + sp) * 256 + tid] = acc;
}

__global__ void pool_final_kernel(const float* __restrict__ part,
                                  const float* __restrict__ Wf,
                                  const float* __restrict__ bf,
                                  float* __restrict__ out)
{
    __shared__ float s_red[8];
    const int b = blockIdx.x, tid = threadIdx.x;
    float pooled = 0.f;
    #pragma unroll
    for (int sp = 0; sp < 16; sp++)
        pooled += part[(size_t)(b * 16 + sp) * 256 + tid];
    float val = pooled * Wf[tid];
    #pragma unroll
    for (int o = 16; o > 0; o >>= 1) val += __shfl_xor_sync(~0u, val, o);
    if ((tid & 31) == 0) s_red[tid >> 5] = val;
    __syncthreads();
    if (tid == 0) {
        float tot = 0.f;
        #pragma unroll
        for (int i = 0; i < 8; i++) tot += s_red[i];
        out[b] = tot + bf[0];
    }
}

// ---------------------------------------------------------------------------
// Launch
// ---------------------------------------------------------------------------
extern "C" void kernel_launch(void* const* d_in, const int* in_sizes, int n_in,
                              void* d_out, int out_size)
{
    const float* x      = (const float*)d_in[0];
    const float* Wp     = (const float*)d_in[1];
    const float* bp     = (const float*)d_in[2];
    const float* g0     = (const float*)d_in[3];
    const float* b0     = (const float*)d_in[4];
    const float* Wi     = (const float*)d_in[5];
    const float* conv_w = (const float*)d_in[6];
    const float* conv_b = (const float*)d_in[7];
    const float* Wx     = (const float*)d_in[8];
    const float* Wdt    = (const float*)d_in[9];
    const float* bdt    = (const float*)d_in[10];
    const float* A_log  = (const float*)d_in[11];
    const float* Dp     = (const float*)d_in[12];
    const float* Wo     = (const float*)d_in[13];
    const float* ln_g   = (const float*)d_in[14];
    const float* ln_b   = (const float*)d_in[15];
    const float* wa     = (const float*)d_in[16];
    const float* ba     = (const float*)d_in[17];
    const float* Wf     = (const float*)d_in[18];
    const float* bf     = (const float*)d_in[19];

    float *p_h, *p_t0, *p_xz, *p_u, *p_dt, *p_xdbc, *p_y;
    float *p_P, *p_h0, *p_hini, *p_logit, *p_part;
    cudaGetSymbolAddress((void**)&p_h,    g_h);
    cudaGetSymbolAddress((void**)&p_t0,   g_t0);
    cudaGetSymbolAddress((void**)&p_xz,   g_xz);
    cudaGetSymbolAddress((void**)&p_u,    g_u);
    cudaGetSymbolAddress((void**)&p_dt,   g_dt);
    cudaGetSymbolAddress((void**)&p_xdbc, g_xdbc);
    cudaGetSymbolAddress((void**)&p_y,    g_y);
    cudaGetSymbolAddress((void**)&p_P,    g_P);
    cudaGetSymbolAddress((void**)&p_h0,   g_h0);
    cudaGetSymbolAddress((void**)&p_hini, g_hini);
    cudaGetSymbolAddress((void**)&p_logit, g_logit);
    cudaGetSymbolAddress((void**)&p_part, g_part);

    // input projection + bias (tensor tf32) + LN
    tf32_gemm<1><<<dim3(2, 256), 256>>>(Dn, DINn, x, DINn, Wp, bp, p_t0, Dn);
    ln256_kernel<<<Mrows, 256>>>(p_t0, p_h, g0, b0);

    for (int l = 0; l < NLn; l++) {
        // xz = h @ Wi^T  (N=1024, K=256)
        tf32_gemm<0><<<dim3(8, 256), 256>>>(2 * DIn, Dn, p_h, Dn,
                                            Wi + (size_t)l * 2 * DIn * Dn,
                                            nullptr, p_xz, 2 * DIn);
        // depthwise causal conv + silu
        conv_silu_kernel<<<(Mrows * DIn) / 256, 256>>>(
            p_xz, conv_w + (size_t)l * DIn * DCn, conv_b + (size_t)l * DIn, p_u);
        // xdbc = u @ Wx^T  (N=48, K=512)
        tf32_gemm<0><<<dim3(1, 256), 256>>>(48, DIn, p_u, DIn,
                                            Wx + (size_t)l * 48 * DIn,
                                            nullptr, p_xdbc, 48);
        // dt = softplus(dtraw @ Wdt^T + bdt) — write-bound direct kernel
        dt_kernel<<<Mrows, 512>>>(p_xdbc, Wdt + (size_t)l * DIn * DTRn,
                                  bdt + (size_t)l * DIn, p_dt);
        // chunked selective scan
        scan_carry_kernel<<<128 * (C_CHUNKS - 1), 512>>>(
            p_u, p_dt, p_xdbc, A_log + (size_t)l * DIn * DSn, p_P, p_h0);
        scan_fix_kernel<<<NCH / 256, 256>>>(p_P, p_h0, p_hini);
        scan_main_kernel<<<128 * C_CHUNKS, 512>>>(
            p_u, p_dt, p_xz, p_xdbc,
            A_log + (size_t)l * DIn * DSn, Dp + (size_t)l * DIn,
            p_hini, p_y);
        // out = y @ Wo^T  (N=256, K=512), then LN
        tf32_gemm<0><<<dim3(2, 256), 256>>>(Dn, DIn, p_y, DIn,
                                            Wo + (size_t)l * Dn * DIn,
                                            nullptr, p_t0, Dn);
        ln256_kernel<<<Mrows, 256>>>(p_t0, p_h,
                                     ln_g + (size_t)l * Dn, ln_b + (size_t)l * Dn);
    }

    // pooling + final linear
    pool_logit_kernel<<<Mrows / 8, 256>>>(p_h, wa, ba, p_logit);
    pool_softmax_kernel<<<Bn, 1024>>>(p_logit);
    pool_wsum_kernel<<<Bn * 16, 256>>>(p_h, p_logit, p_part);
    pool_final_kernel<<<Bn, 256>>>(p_part, Wf, bf, (float*)d_out);
}

// round 9
// speedup vs baseline: 1.6241x; 1.1796x over previous
#include <cuda_runtime.h>
#include <math.h>
#include <stdint.h>

// Problem constants
#define Bn   8
#define Ln   4096
#define DINn 64
#define Dn   256
#define NLn  2
#define DIn  512
#define DSn  16
#define DCn  4
#define DTRn 16
#define Mrows (Bn * Ln)   // 32768

#define C_CHUNKS 4
#define CH_LEN   1024
#define NCH      (Bn * DIn * DSn)

#define YSPLIT 172   // row-blocks 0..171 tensor, 172..255 SIMT (43:21 ratio)

// ---------------------------------------------------------------------------
// Scratch
// ---------------------------------------------------------------------------
__device__ float g_h    [Mrows * Dn];
__device__ float g_t0   [Mrows * Dn];
__device__ float g_xz   [Mrows * 2 * DIn];
__device__ float g_u    [Mrows * DIn];
__device__ float g_dt   [Mrows * DIn];
__device__ float g_xdbc [Mrows * 48];
__device__ float g_y    [Mrows * DIn];
__device__ float g_P    [(C_CHUNKS - 1) * NCH];
__device__ float g_h0   [(C_CHUNKS - 1) * NCH];
__device__ float g_hini [C_CHUNKS * NCH];
__device__ float g_logit[Mrows];
__device__ float g_part [Bn * 16 * Dn];

// ---------------------------------------------------------------------------
// Helpers
// ---------------------------------------------------------------------------
__device__ __forceinline__ float softplus_f(float x) {
    return fmaxf(x, 0.f) + log1pf(__expf(-fabsf(x)));
}
__device__ __forceinline__ float silu_f(float x) {
    return x / (1.f + __expf(-x));
}
__device__ __forceinline__ float to_tf32(float x) {
    float r;
    asm("cvt.rna.tf32.f32 %0, %1;" : "=f"(r) : "f"(x));
    return r;
}
__device__ __forceinline__ void mma8(float* d,
                                     float a0, float a1, float a2, float a3,
                                     float b0, float b1) {
    asm volatile(
        "mma.sync.aligned.m16n8k8.row.col.f32.tf32.tf32.f32 "
        "{%0,%1,%2,%3},{%4,%5,%6,%7},{%8,%9},{%0,%1,%2,%3};"
        : "+f"(d[0]), "+f"(d[1]), "+f"(d[2]), "+f"(d[3])
        : "r"(__float_as_uint(a0)), "r"(__float_as_uint(a1)),
          "r"(__float_as_uint(a2)), "r"(__float_as_uint(a3)),
          "r"(__float_as_uint(b0)), "r"(__float_as_uint(b1)));
}

#define SPAD 24

// ---------------------------------------------------------------------------
// TF32 tensor GEMM (R4-proven) — used for proj (+bias) and Wx.
// ---------------------------------------------------------------------------
template <int EPI>
__global__ void __launch_bounds__(256, 2) tf32_gemm(
    int N, int K,
    const float* __restrict__ A, int lda,
    const float* __restrict__ W,
    const float* __restrict__ bias,
    float* __restrict__ C, int ldc)
{
    __shared__ float As[2][128][SPAD];
    __shared__ float Ws[2][128][SPAD];

    const int tid  = threadIdx.x;
    const int wid  = tid >> 5, lane = tid & 31;
    const int wm   = (wid >> 2) * 64;
    const int wn   = (wid & 3) * 32;
    const int gr   = lane >> 2;
    const int gc   = lane & 3;
    const int m0   = blockIdx.y * 128;
    const int n0   = blockIdx.x * 128;

    const int lr0 = tid >> 2;
    const int lj  = tid & 3;
    const int pb  = (lj & 2) * 4 + (lj & 1);

    const float* Ag = A + (size_t)(m0 + lr0) * lda + lj * 4;
    const float* Wg = W + (size_t)(n0 + lr0) * K + lj * 4;
    const bool wok0 = (n0 + lr0) < N;
    const bool wok1 = (n0 + lr0 + 64) < N;

    float acc[4][4][4];
    #pragma unroll
    for (int i = 0; i < 4; i++)
        #pragma unroll
        for (int j = 0; j < 4; j++)
            #pragma unroll
            for (int t = 0; t < 4; t++) acc[i][j][t] = 0.f;

    float4 ra0, ra1, rw0, rw1;
    const float4 z4 = make_float4(0.f, 0.f, 0.f, 0.f);

    ra0 = *(const float4*)(Ag);
    ra1 = *(const float4*)(Ag + (size_t)64 * lda);
    rw0 = wok0 ? *(const float4*)(Wg) : z4;
    rw1 = wok1 ? *(const float4*)(Wg + (size_t)64 * K) : z4;
    {
        As[0][lr0     ][pb]     = to_tf32(ra0.x);
        As[0][lr0     ][pb + 2] = to_tf32(ra0.y);
        As[0][lr0     ][pb + 4] = to_tf32(ra0.z);
        As[0][lr0     ][pb + 6] = to_tf32(ra0.w);
        As[0][lr0 + 64][pb]     = to_tf32(ra1.x);
        As[0][lr0 + 64][pb + 2] = to_tf32(ra1.y);
        As[0][lr0 + 64][pb + 4] = to_tf32(ra1.z);
        As[0][lr0 + 64][pb + 6] = to_tf32(ra1.w);
        Ws[0][lr0     ][pb]     = to_tf32(rw0.x);
        Ws[0][lr0     ][pb + 2] = to_tf32(rw0.y);
        Ws[0][lr0     ][pb + 4] = to_tf32(rw0.z);
        Ws[0][lr0     ][pb + 6] = to_tf32(rw0.w);
        Ws[0][lr0 + 64][pb]     = to_tf32(rw1.x);
        Ws[0][lr0 + 64][pb + 2] = to_tf32(rw1.y);
        Ws[0][lr0 + 64][pb + 4] = to_tf32(rw1.z);
        Ws[0][lr0 + 64][pb + 6] = to_tf32(rw1.w);
    }
    __syncthreads();

    int buf = 0;
    for (int k0 = 16; k0 < K; k0 += 16) {
        ra0 = *(const float4*)(Ag + k0);
        ra1 = *(const float4*)(Ag + (size_t)64 * lda + k0);
        rw0 = wok0 ? *(const float4*)(Wg + k0) : z4;
        rw1 = wok1 ? *(const float4*)(Wg + (size_t)64 * K + k0) : z4;

        #pragma unroll
        for (int ks = 0; ks < 2; ks++) {
            float2 alo[4], ahi[4], bfr[4];
            #pragma unroll
            for (int fm = 0; fm < 4; fm++) {
                alo[fm] = *(const float2*)&As[buf][wm + fm * 16 + gr    ][ks * 8 + 2 * gc];
                ahi[fm] = *(const float2*)&As[buf][wm + fm * 16 + gr + 8][ks * 8 + 2 * gc];
            }
            #pragma unroll
            for (int fn = 0; fn < 4; fn++)
                bfr[fn] = *(const float2*)&Ws[buf][wn + fn * 8 + gr][ks * 8 + 2 * gc];
            #pragma unroll
            for (int fm = 0; fm < 4; fm++)
                #pragma unroll
                for (int fn = 0; fn < 4; fn++)
                    mma8(acc[fm][fn], alo[fm].x, ahi[fm].x, alo[fm].y, ahi[fm].y,
                         bfr[fn].x, bfr[fn].y);
        }

        const int nb = buf ^ 1;
        As[nb][lr0     ][pb]     = to_tf32(ra0.x);
        As[nb][lr0     ][pb + 2] = to_tf32(ra0.y);
        As[nb][lr0     ][pb + 4] = to_tf32(ra0.z);
        As[nb][lr0     ][pb + 6] = to_tf32(ra0.w);
        As[nb][lr0 + 64][pb]     = to_tf32(ra1.x);
        As[nb][lr0 + 64][pb + 2] = to_tf32(ra1.y);
        As[nb][lr0 + 64][pb + 4] = to_tf32(ra1.z);
        As[nb][lr0 + 64][pb + 6] = to_tf32(ra1.w);
        Ws[nb][lr0     ][pb]     = to_tf32(rw0.x);
        Ws[nb][lr0     ][pb + 2] = to_tf32(rw0.y);
        Ws[nb][lr0     ][pb + 4] = to_tf32(rw0.z);
        Ws[nb][lr0     ][pb + 6] = to_tf32(rw0.w);
        Ws[nb][lr0 + 64][pb]     = to_tf32(rw1.x);
        Ws[nb][lr0 + 64][pb + 2] = to_tf32(rw1.y);
        Ws[nb][lr0 + 64][pb + 4] = to_tf32(rw1.z);
        Ws[nb][lr0 + 64][pb + 6] = to_tf32(rw1.w);
        __syncthreads();
        buf = nb;
    }

    #pragma unroll
    for (int ks = 0; ks < 2; ks++) {
        float2 alo[4], ahi[4], bfr[4];
        #pragma unroll
        for (int fm = 0; fm < 4; fm++) {
            alo[fm] = *(const float2*)&As[buf][wm + fm * 16 + gr    ][ks * 8 + 2 * gc];
            ahi[fm] = *(const float2*)&As[buf][wm + fm * 16 + gr + 8][ks * 8 + 2 * gc];
        }
        #pragma unroll
        for (int fn = 0; fn < 4; fn++)
            bfr[fn] = *(const float2*)&Ws[buf][wn + fn * 8 + gr][ks * 8 + 2 * gc];
        #pragma unroll
        for (int fm = 0; fm < 4; fm++)
            #pragma unroll
            for (int fn = 0; fn < 4; fn++)
                mma8(acc[fm][fn], alo[fm].x, ahi[fm].x, alo[fm].y, ahi[fm].y,
                     bfr[fn].x, bfr[fn].y);
    }

    #pragma unroll
    for (int fm = 0; fm < 4; fm++) {
        const int r0 = m0 + wm + fm * 16 + gr;
        #pragma unroll
        for (int fn = 0; fn < 4; fn++) {
            const int c0 = n0 + wn + fn * 8 + 2 * gc;
            if (c0 < N) {
                float v0 = acc[fm][fn][0], v1 = acc[fm][fn][1];
                float v2 = acc[fm][fn][2], v3 = acc[fm][fn][3];
                if (EPI == 1) {
                    v0 += bias[c0]; v1 += bias[c0 + 1];
                    v2 += bias[c0]; v3 += bias[c0 + 1];
                }
                *(float2*)&C[(size_t)r0 * ldc + c0]       = make_float2(v0, v1);
                *(float2*)&C[(size_t)(r0 + 8) * ldc + c0] = make_float2(v2, v3);
            }
        }
    }
}

// ---------------------------------------------------------------------------
// DUO GEMM: row-block split.  blockIdx.y < YT -> tensor path (tf32 mma),
// else SIMT fp32 path (fma pipe).  One path per CTA; smem union (48KB).
// Requires N%128==0 here (xz: 1024, Wo: 256).  EPI: 0 store, 1 +bias.
// ---------------------------------------------------------------------------
template <int EPI>
__global__ void __launch_bounds__(256, 2) duo_gemm(
    int N, int K, int YT,
    const float* __restrict__ A, int lda,
    const float* __restrict__ W,
    const float* __restrict__ bias,
    float* __restrict__ C, int ldc)
{
    __shared__ __align__(16) float sbuf[12288];   // 48KB

    const int tid  = threadIdx.x;
    const int m0   = blockIdx.y * 128;
    const int n0   = blockIdx.x * 128;
    const int lr0 = tid >> 2;
    const int lj  = tid & 3;

    if (blockIdx.y < YT) {
        // ================= TENSOR PATH (identical to tf32_gemm) ============
        float (*As)[128][SPAD] = (float (*)[128][SPAD])sbuf;
        float (*Ws)[128][SPAD] = (float (*)[128][SPAD])(sbuf + 6144);

        const int wid  = tid >> 5, lane = tid & 31;
        const int wm   = (wid >> 2) * 64;
        const int wn   = (wid & 3) * 32;
        const int gr   = lane >> 2;
        const int gc   = lane & 3;
        const int pb   = (lj & 2) * 4 + (lj & 1);

        const float* Ag = A + (size_t)(m0 + lr0) * lda + lj * 4;
        const float* Wg = W + (size_t)(n0 + lr0) * K + lj * 4;

        float acc[4][4][4];
        #pragma unroll
        for (int i = 0; i < 4; i++)
            #pragma unroll
            for (int j = 0; j < 4; j++)
                #pragma unroll
                for (int t = 0; t < 4; t++) acc[i][j][t] = 0.f;

        float4 ra0, ra1, rw0, rw1;

        ra0 = *(const float4*)(Ag);
        ra1 = *(const float4*)(Ag + (size_t)64 * lda);
        rw0 = *(const float4*)(Wg);
        rw1 = *(const float4*)(Wg + (size_t)64 * K);
        {
            As[0][lr0     ][pb]     = to_tf32(ra0.x);
            As[0][lr0     ][pb + 2] = to_tf32(ra0.y);
            As[0][lr0     ][pb + 4] = to_tf32(ra0.z);
            As[0][lr0     ][pb + 6] = to_tf32(ra0.w);
            As[0][lr0 + 64][pb]     = to_tf32(ra1.x);
            As[0][lr0 + 64][pb + 2] = to_tf32(ra1.y);
            As[0][lr0 + 64][pb + 4] = to_tf32(ra1.z);
            As[0][lr0 + 64][pb + 6] = to_tf32(ra1.w);
            Ws[0][lr0     ][pb]     = to_tf32(rw0.x);
            Ws[0][lr0     ][pb + 2] = to_tf32(rw0.y);
            Ws[0][lr0     ][pb + 4] = to_tf32(rw0.z);
            Ws[0][lr0     ][pb + 6] = to_tf32(rw0.w);
            Ws[0][lr0 + 64][pb]     = to_tf32(rw1.x);
            Ws[0][lr0 + 64][pb + 2] = to_tf32(rw1.y);
            Ws[0][lr0 + 64][pb + 4] = to_tf32(rw1.z);
            Ws[0][lr0 + 64][pb + 6] = to_tf32(rw1.w);
        }
        __syncthreads();

        int buf = 0;
        for (int k0 = 16; k0 < K; k0 += 16) {
            ra0 = *(const float4*)(Ag + k0);
            ra1 = *(const float4*)(Ag + (size_t)64 * lda + k0);
            rw0 = *(const float4*)(Wg + k0);
            rw1 = *(const float4*)(Wg + (size_t)64 * K + k0);

            #pragma unroll
            for (int ks = 0; ks < 2; ks++) {
                float2 alo[4], ahi[4], bfr[4];
                #pragma unroll
                for (int fm = 0; fm < 4; fm++) {
                    alo[fm] = *(const float2*)&As[buf][wm + fm * 16 + gr    ][ks * 8 + 2 * gc];
                    ahi[fm] = *(const float2*)&As[buf][wm + fm * 16 + gr + 8][ks * 8 + 2 * gc];
                }
                #pragma unroll
                for (int fn = 0; fn < 4; fn++)
                    bfr[fn] = *(const float2*)&Ws[buf][wn + fn * 8 + gr][ks * 8 + 2 * gc];
                #pragma unroll
                for (int fm = 0; fm < 4; fm++)
                    #pragma unroll
                    for (int fn = 0; fn < 4; fn++)
                        mma8(acc[fm][fn], alo[fm].x, ahi[fm].x, alo[fm].y, ahi[fm].y,
                             bfr[fn].x, bfr[fn].y);
            }

            const int nb = buf ^ 1;
            As[nb][lr0     ][pb]     = to_tf32(ra0.x);
            As[nb][lr0     ][pb + 2] = to_tf32(ra0.y);
            As[nb][lr0     ][pb + 4] = to_tf32(ra0.z);
            As[nb][lr0     ][pb + 6] = to_tf32(ra0.w);
            As[nb][lr0 + 64][pb]     = to_tf32(ra1.x);
            As[nb][lr0 + 64][pb + 2] = to_tf32(ra1.y);
            As[nb][lr0 + 64][pb + 4] = to_tf32(ra1.z);
            As[nb][lr0 + 64][pb + 6] = to_tf32(ra1.w);
            Ws[nb][lr0     ][pb]     = to_tf32(rw0.x);
            Ws[nb][lr0     ][pb + 2] = to_tf32(rw0.y);
            Ws[nb][lr0     ][pb + 4] = to_tf32(rw0.z);
            Ws[nb][lr0     ][pb + 6] = to_tf32(rw0.w);
            Ws[nb][lr0 + 64][pb]     = to_tf32(rw1.x);
            Ws[nb][lr0 + 64][pb + 2] = to_tf32(rw1.y);
            Ws[nb][lr0 + 64][pb + 4] = to_tf32(rw1.z);
            Ws[nb][lr0 + 64][pb + 6] = to_tf32(rw1.w);
            __syncthreads();
            buf = nb;
        }

        #pragma unroll
        for (int ks = 0; ks < 2; ks++) {
            float2 alo[4], ahi[4], bfr[4];
            #pragma unroll
            for (int fm = 0; fm < 4; fm++) {
                alo[fm] = *(const float2*)&As[buf][wm + fm * 16 + gr    ][ks * 8 + 2 * gc];
                ahi[fm] = *(const float2*)&As[buf][wm + fm * 16 + gr + 8][ks * 8 + 2 * gc];
            }
            #pragma unroll
            for (int fn = 0; fn < 4; fn++)
                bfr[fn] = *(const float2*)&Ws[buf][wn + fn * 8 + gr][ks * 8 + 2 * gc];
            #pragma unroll
            for (int fm = 0; fm < 4; fm++)
                #pragma unroll
                for (int fn = 0; fn < 4; fn++)
                    mma8(acc[fm][fn], alo[fm].x, ahi[fm].x, alo[fm].y, ahi[fm].y,
                         bfr[fn].x, bfr[fn].y);
        }

        #pragma unroll
        for (int fm = 0; fm < 4; fm++) {
            const int r0 = m0 + wm + fm * 16 + gr;
            #pragma unroll
            for (int fn = 0; fn < 4; fn++) {
                const int c0 = n0 + wn + fn * 8 + 2 * gc;
                float v0 = acc[fm][fn][0], v1 = acc[fm][fn][1];
                float v2 = acc[fm][fn][2], v3 = acc[fm][fn][3];
                if (EPI == 1) {
                    v0 += bias[c0]; v1 += bias[c0 + 1];
                    v2 += bias[c0]; v3 += bias[c0 + 1];
                }
                *(float2*)&C[(size_t)r0 * ldc + c0]       = make_float2(v0, v1);
                *(float2*)&C[(size_t)(r0 + 8) * ldc + c0] = make_float2(v2, v3);
            }
        }
    } else {
        // ================= SIMT PATH (identical to R1 sgemm_nt) ============
        float (*As2)[132] = (float (*)[132])sbuf;            // [8][132]
        float (*Ws2)[132] = (float (*)[132])(sbuf + 1056);   // [8][132]

        const int tx = tid & 15;
        const int ty = tid >> 4;
        const int lr = tid >> 1;
        const int lk = (tid & 1) * 4;

        float acc[8][8];
        #pragma unroll
        for (int i = 0; i < 8; i++)
            #pragma unroll
            for (int j = 0; j < 8; j++) acc[i][j] = 0.f;

        const float* Aptr = A + (size_t)(m0 + lr) * lda + lk;
        const float* Wptr = W + (size_t)(n0 + lr) * K + lk;

        for (int k0 = 0; k0 < K; k0 += 8) {
            float4 av = *(const float4*)(Aptr + k0);
            As2[lk + 0][lr] = av.x; As2[lk + 1][lr] = av.y;
            As2[lk + 2][lr] = av.z; As2[lk + 3][lr] = av.w;

            float4 wv = *(const float4*)(Wptr + k0);
            Ws2[lk + 0][lr] = wv.x; Ws2[lk + 1][lr] = wv.y;
            Ws2[lk + 2][lr] = wv.z; Ws2[lk + 3][lr] = wv.w;

            __syncthreads();
            #pragma unroll
            for (int k = 0; k < 8; k++) {
                float a[8], bb[8];
                *(float4*)&a[0]  = *(const float4*)&As2[k][ty * 4];
                *(float4*)&a[4]  = *(const float4*)&As2[k][64 + ty * 4];
                *(float4*)&bb[0] = *(const float4*)&Ws2[k][tx * 4];
                *(float4*)&bb[4] = *(const float4*)&Ws2[k][64 + tx * 4];
                #pragma unroll
                for (int i = 0; i < 8; i++)
                    #pragma unroll
                    for (int j = 0; j < 8; j++)
                        acc[i][j] = fmaf(a[i], bb[j], acc[i][j]);
            }
            __syncthreads();
        }

        #pragma unroll
        for (int i = 0; i < 8; i++) {
            const int r = m0 + ((i < 4) ? (ty * 4 + i) : (64 + ty * 4 + i - 4));
            #pragma unroll
            for (int j = 0; j < 8; j++) {
                const int c = n0 + ((j < 4) ? (tx * 4 + j) : (64 + tx * 4 + j - 4));
                float v = acc[i][j];
                if (EPI == 1) v += bias[c];
                C[(size_t)r * ldc + c] = v;
            }
        }
    }
}

// ---------------------------------------------------------------------------
// SIMT SGEMM for dt (N=512, K=16).  EPI 2 = softplus(+bias).  (R4-proven.)
// ---------------------------------------------------------------------------
__global__ void __launch_bounds__(256, 2) sgemm_dt(
    int N, int K,
    const float* __restrict__ A, int lda,
    const float* __restrict__ W,
    const float* __restrict__ bias,
    float* __restrict__ C, int ldc)
{
    __shared__ __align__(16) float As[8][132];
    __shared__ __align__(16) float Ws2[8][132];

    const int tid = threadIdx.x;
    const int tx = tid & 15;
    const int ty = tid >> 4;
    const int m0 = blockIdx.y * 128;
    const int n0 = blockIdx.x * 128;

    const int lr = tid >> 1;
    const int lk = (tid & 1) * 4;

    float acc[8][8];
    #pragma unroll
    for (int i = 0; i < 8; i++)
        #pragma unroll
        for (int j = 0; j < 8; j++) acc[i][j] = 0.f;

    const float* Aptr = A + (size_t)(m0 + lr) * lda + lk;
    const int wn = n0 + lr;
    const float* Wptr = W + (size_t)wn * K + lk;
    const bool wok = (wn < N);

    for (int k0 = 0; k0 < K; k0 += 8) {
        float4 av = *(const float4*)(Aptr + k0);
        As[lk + 0][lr] = av.x; As[lk + 1][lr] = av.y;
        As[lk + 2][lr] = av.z; As[lk + 3][lr] = av.w;

        float4 wv = make_float4(0.f, 0.f, 0.f, 0.f);
        if (wok) wv = *(const float4*)(Wptr + k0);
        Ws2[lk + 0][lr] = wv.x; Ws2[lk + 1][lr] = wv.y;
        Ws2[lk + 2][lr] = wv.z; Ws2[lk + 3][lr] = wv.w;

        __syncthreads();
        #pragma unroll
        for (int k = 0; k < 8; k++) {
            float a[8], bb[8];
            *(float4*)&a[0]  = *(const float4*)&As[k][ty * 4];
            *(float4*)&a[4]  = *(const float4*)&As[k][64 + ty * 4];
            *(float4*)&bb[0] = *(const float4*)&Ws2[k][tx * 4];
            *(float4*)&bb[4] = *(const float4*)&Ws2[k][64 + tx * 4];
            #pragma unroll
            for (int i = 0; i < 8; i++)
                #pragma unroll
                for (int j = 0; j < 8; j++)
                    acc[i][j] = fmaf(a[i], bb[j], acc[i][j]);
        }
        __syncthreads();
    }

    #pragma unroll
    for (int i = 0; i < 8; i++) {
        const int r = m0 + ((i < 4) ? (ty * 4 + i) : (64 + ty * 4 + i - 4));
        #pragma unroll
        for (int j = 0; j < 8; j++) {
            const int c = n0 + ((j < 4) ? (tx * 4 + j) : (64 + tx * 4 + j - 4));
            if (c < N) {
                float v = acc[i][j] + bias[c];
                C[(size_t)r * ldc + c] = softplus_f(v);
            }
        }
    }
}

// ---------------------------------------------------------------------------
// Depthwise causal conv (DC=4) + bias + SiLU — scalar (R4-proven).
// ---------------------------------------------------------------------------
__global__ void conv_silu_kernel(const float* __restrict__ xz,
                                 const float* __restrict__ w,
                                 const float* __restrict__ cb,
                                 float* __restrict__ u)
{
    const int idx = blockIdx.x * blockDim.x + threadIdx.x;
    if (idx >= Mrows * DIn) return;
    const int d  = idx & (DIn - 1);
    const int bl = idx >> 9;
    const int l  = bl & (Ln - 1);
    float acc = cb[d];
    #pragma unroll
    for (int k = 0; k < 4; k++) {
        const int ll = l - 3 + k;
        if (ll >= 0)
            acc = fmaf(w[d * 4 + k], xz[(size_t)(bl - 3 + k) * (2 * DIn) + d], acc);
    }
    u[idx] = silu_f(acc);
}

// ---------------------------------------------------------------------------
// LayerNorm over last dim (256), one block per row.
// ---------------------------------------------------------------------------
__global__ void ln256_kernel(const float* __restrict__ in, float* __restrict__ out,
                             const float* __restrict__ g, const float* __restrict__ b)
{
    const int row = blockIdx.x;
    const int t = threadIdx.x;
    const float v = in[(size_t)row * 256 + t];
    float s = v, sq = v * v;
    #pragma unroll
    for (int o = 16; o > 0; o >>= 1) {
        s  += __shfl_xor_sync(~0u, s, o);
        sq += __shfl_xor_sync(~0u, sq, o);
    }
    __shared__ float ss[8], ssq[8];
    if ((t & 31) == 0) { ss[t >> 5] = s; ssq[t >> 5] = sq; }
    __syncthreads();
    float tot = 0.f, totq = 0.f;
    #pragma unroll
    for (int i = 0; i < 8; i++) { tot += ss[i]; totq += ssq[i]; }
    const float mean = tot * (1.f / 256.f);
    const float var  = totq * (1.f / 256.f) - mean * mean;
    const float rstd = rsqrtf(var + 1e-5f);
    out[(size_t)row * 256 + t] = (v - mean) * rstd * g[t] + b[t];
}

// ---------------------------------------------------------------------------
// Chunked selective scan (4 chunks of 1024) — R4-proven.
// ---------------------------------------------------------------------------
#define SCH 64

__global__ void __launch_bounds__(512) scan_carry_kernel(
    const float* __restrict__ u, const float* __restrict__ dt,
    const float* __restrict__ xdbc, const float* __restrict__ A_log,
    float* __restrict__ Pout, float* __restrict__ h0out)
{
    __shared__ float s_dt[SCH][32], s_u[SCH][32], s_B[SCH][16];

    const int tid = threadIdx.x;
    const int c   = blockIdx.x >> 7;
    const int rem = blockIdx.x & 127;
    const int b   = rem >> 4;
    const int d0  = (rem & 15) * 32;
    const int s   = tid & 15;
    const int dd  = tid >> 4;
    const int d   = d0 + dd;

    const float A = -__expf(A_log[d * DSn + s]);
    float h = 0.f, P = 1.f;

    const size_t base_bl = (size_t)b * Ln + (size_t)c * CH_LEN;

    for (int l0 = 0; l0 < CH_LEN; l0 += SCH) {
        for (int i = tid; i < SCH * 32; i += 512) {
            const int r = i >> 5, cc = i & 31;
            const size_t bl = base_bl + l0 + r;
            s_dt[r][cc] = dt[bl * DIn + d0 + cc];
            s_u [r][cc] = u [bl * DIn + d0 + cc];
        }
        for (int i = tid; i < SCH * 16; i += 512) {
            const int r = i >> 4, cc = i & 15;
            const size_t bl = base_bl + l0 + r;
            s_B[r][cc] = xdbc[bl * 48 + 16 + cc];
        }
        __syncthreads();

        #pragma unroll 4
        for (int i = 0; i < SCH; i++) {
            const float dtv = s_dt[i][dd];
            const float dA  = __expf(dtv * A);
            P *= dA;
            h = fmaf(h, dA, dtv * s_u[i][dd] * s_B[i][s]);
        }
        __syncthreads();
    }

    const int ch = ((b * DIn + d) * DSn + s);
    Pout [c * NCH + ch] = P;
    h0out[c * NCH + ch] = h;
}

__global__ void scan_fix_kernel(const float* __restrict__ P,
                                const float* __restrict__ h0,
                                float* __restrict__ hini)
{
    const int ch = blockIdx.x * blockDim.x + threadIdx.x;
    float h = 0.f;
    hini[ch] = 0.f;
    #pragma unroll
    for (int c = 1; c < C_CHUNKS; c++) {
        h = fmaf(P[(c - 1) * NCH + ch], h, h0[(c - 1) * NCH + ch]);
        hini[c * NCH + ch] = h;
    }
}

__global__ void __launch_bounds__(512) scan_main_kernel(
    const float* __restrict__ u, const float* __restrict__ dt,
    const float* __restrict__ xz, const float* __restrict__ xdbc,
    const float* __restrict__ A_log, const float* __restrict__ Dp,
    const float* __restrict__ hini,
    float* __restrict__ y)
{
    __shared__ float s_dt[SCH][32], s_u[SCH][32], s_z[SCH][32], s_y[SCH][32];
    __shared__ float s_B[SCH][16], s_C[SCH][16];

    const int tid = threadIdx.x;
    const int c   = blockIdx.x >> 7;
    const int rem = blockIdx.x & 127;
    const int b   = rem >> 4;
    const int d0  = (rem & 15) * 32;
    const int s   = tid & 15;
    const int dd  = tid >> 4;
    const int d   = d0 + dd;

    const float A   = -__expf(A_log[d * DSn + s]);
    const float dpv = Dp[d];
    const int ch = ((b * DIn + d) * DSn + s);
    float h = hini[c * NCH + ch];

    const size_t base_bl = (size_t)b * Ln + (size_t)c * CH_LEN;

    for (int l0 = 0; l0 < CH_LEN; l0 += SCH) {
        for (int i = tid; i < SCH * 32; i += 512) {
            const int r = i >> 5, cc = i & 31;
            const size_t bl = base_bl + l0 + r;
            s_dt[r][cc] = dt[bl * DIn + d0 + cc];
            s_u [r][cc] = u [bl * DIn + d0 + cc];
            s_z [r][cc] = xz[bl * (2 * DIn) + DIn + d0 + cc];
        }
        for (int i = tid; i < SCH * 16; i += 512) {
            const int r = i >> 4, cc = i & 15;
            const size_t bl = base_bl + l0 + r;
            s_B[r][cc] = xdbc[bl * 48 + 16 + cc];
            s_C[r][cc] = xdbc[bl * 48 + 32 + cc];
        }
        __syncthreads();

        #pragma unroll 4
        for (int i = 0; i < SCH; i++) {
            const float dtv = s_dt[i][dd];
            const float uv  = s_u[i][dd];
            const float dA  = __expf(dtv * A);
            h = fmaf(h, dA, dtv * uv * s_B[i][s]);
            float yv = h * s_C[i][s];
            yv += __shfl_xor_sync(~0u, yv, 1);
            yv += __shfl_xor_sync(~0u, yv, 2);
            yv += __shfl_xor_sync(~0u, yv, 4);
            yv += __shfl_xor_sync(~0u, yv, 8);
            if (s == 0) {
                const float zv = s_z[i][dd];
                s_y[i][dd] = (yv + uv * dpv) * silu_f(zv);
            }
        }
        __syncthreads();

        for (int i = tid; i < SCH * 32; i += 512) {
            const int r = i >> 5, cc = i & 31;
            y[(base_bl + l0 + r) * DIn + d0 + cc] = s_y[r][cc];
        }
        __syncthreads();
    }
}

// ---------------------------------------------------------------------------
// Pooling (split, R4-proven).
// ---------------------------------------------------------------------------
__global__ void pool_logit_kernel(const float* __restrict__ h,
                                  const float* __restrict__ wa,
                                  const float* __restrict__ ba,
                                  float* __restrict__ logit)
{
    const int wid_in_blk = threadIdx.x >> 5;
    const int lane = threadIdx.x & 31;
    const int row = blockIdx.x * 8 + wid_in_blk;
    const float* r = h + (size_t)row * 256;
    float acc = 0.f;
    #pragma unroll
    for (int k = 0; k < 2; k++) {
        const float4 hv = *(const float4*)(r + k * 128 + lane * 4);
        const float4 wv = *(const float4*)(wa + k * 128 + lane * 4);
        acc += hv.x * wv.x + hv.y * wv.y + hv.z * wv.z + hv.w * wv.w;
    }
    #pragma unroll
    for (int o = 16; o > 0; o >>= 1) acc += __shfl_xor_sync(~0u, acc, o);
    if (lane == 0) logit[row] = acc + ba[0];
}

__global__ void __launch_bounds__(1024) pool_softmax_kernel(float* __restrict__ logit)
{
    __shared__ float s_red[32];
    const int b = blockIdx.x, tid = threadIdx.x;
    float* lg = logit + b * Ln;

    float mx = -1e30f;
    float v[4];
    #pragma unroll
    for (int k = 0; k < 4; k++) {
        v[k] = lg[tid + k * 1024];
        mx = fmaxf(mx, v[k]);
    }
    #pragma unroll
    for (int o = 16; o > 0; o >>= 1) mx = fmaxf(mx, __shfl_xor_sync(~0u, mx, o));
    if ((tid & 31) == 0) s_red[tid >> 5] = mx;
    __syncthreads();
    if (tid < 32) {
        float t = s_red[tid];
        #pragma unroll
        for (int o = 16; o > 0; o >>= 1) t = fmaxf(t, __shfl_xor_sync(~0u, t, o));
        s_red[tid] = t;
    }
    __syncthreads();
    mx = s_red[0];
    __syncthreads();

    float sum = 0.f;
    #pragma unroll
    for (int k = 0; k < 4; k++) {
        v[k] = __expf(v[k] - mx);
        sum += v[k];
    }
    #pragma unroll
    for (int o = 16; o > 0; o >>= 1) sum += __shfl_xor_sync(~0u, sum, o);
    if ((tid & 31) == 0) s_red[tid >> 5] = sum;
    __syncthreads();
    if (tid < 32) {
        float t = s_red[tid];
        #pragma unroll
        for (int o = 16; o > 0; o >>= 1) t += __shfl_xor_sync(~0u, t, o);
        s_red[tid] = t;
    }
    __syncthreads();
    const float inv = 1.f / s_red[0];
    #pragma unroll
    for (int k = 0; k < 4; k++) lg[tid + k * 1024] = v[k] * inv;
}

__global__ void pool_wsum_kernel(const float* __restrict__ h,
                                 const float* __restrict__ p,
                                 float* __restrict__ part)
{
    const int b = blockIdx.x >> 4;
    const int sp = blockIdx.x & 15;
    const int tid = threadIdx.x;
    const size_t base = ((size_t)b * Ln + sp * 256) * 256;
    const float* pp = p + b * Ln + sp * 256;
    float acc = 0.f;
    for (int l = 0; l < 256; l++)
        acc = fmaf(pp[l], h[base + (size_t)l * 256 + tid], acc);
    part[(size_t)(b * 16 + sp) * 256 + tid] = acc;
}

__global__ void pool_final_kernel(const float* __restrict__ part,
                                  const float* __restrict__ Wf,
                                  const float* __restrict__ bf,
                                  float* __restrict__ out)
{
    __shared__ float s_red[8];
    const int b = blockIdx.x, tid = threadIdx.x;
    float pooled = 0.f;
    #pragma unroll
    for (int sp = 0; sp < 16; sp++)
        pooled += part[(size_t)(b * 16 + sp) * 256 + tid];
    float val = pooled * Wf[tid];
    #pragma unroll
    for (int o = 16; o > 0; o >>= 1) val += __shfl_xor_sync(~0u, val, o);
    if ((tid & 31) == 0) s_red[tid >> 5] = val;
    __syncthreads();
    if (tid == 0) {
        float tot = 0.f;
        #pragma unroll
        for (int i = 0; i < 8; i++) tot += s_red[i];
        out[b] = tot + bf[0];
    }
}

// ---------------------------------------------------------------------------
// Launch
// ---------------------------------------------------------------------------
extern "C" void kernel_launch(void* const* d_in, const int* in_sizes, int n_in,
                              void* d_out, int out_size)
{
    const float* x      = (const float*)d_in[0];
    const float* Wp     = (const float*)d_in[1];
    const float* bp     = (const float*)d_in[2];
    const float* g0     = (const float*)d_in[3];
    const float* b0     = (const float*)d_in[4];
    const float* Wi     = (const float*)d_in[5];
    const float* conv_w = (const float*)d_in[6];
    const float* conv_b = (const float*)d_in[7];
    const float* Wx     = (const float*)d_in[8];
    const float* Wdt    = (const float*)d_in[9];
    const float* bdt    = (const float*)d_in[10];
    const float* A_log  = (const float*)d_in[11];
    const float* Dp     = (const float*)d_in[12];
    const float* Wo     = (const float*)d_in[13];
    const float* ln_g   = (const float*)d_in[14];
    const float* ln_b   = (const float*)d_in[15];
    const float* wa     = (const float*)d_in[16];
    const float* ba     = (const float*)d_in[17];
    const float* Wf     = (const float*)d_in[18];
    const float* bf     = (const float*)d_in[19];

    float *p_h, *p_t0, *p_xz, *p_u, *p_dt, *p_xdbc, *p_y;
    float *p_P, *p_h0, *p_hini, *p_logit, *p_part;
    cudaGetSymbolAddress((void**)&p_h,    g_h);
    cudaGetSymbolAddress((void**)&p_t0,   g_t0);
    cudaGetSymbolAddress((void**)&p_xz,   g_xz);
    cudaGetSymbolAddress((void**)&p_u,    g_u);
    cudaGetSymbolAddress((void**)&p_dt,   g_dt);
    cudaGetSymbolAddress((void**)&p_xdbc, g_xdbc);
    cudaGetSymbolAddress((void**)&p_y,    g_y);
    cudaGetSymbolAddress((void**)&p_P,    g_P);
    cudaGetSymbolAddress((void**)&p_h0,   g_h0);
    cudaGetSymbolAddress((void**)&p_hini, g_hini);
    cudaGetSymbolAddress((void**)&p_logit, g_logit);
    cudaGetSymbolAddress((void**)&p_part, g_part);

    // input projection + bias (tensor tf32) + LN
    tf32_gemm<1><<<dim3(2, 256), 256>>>(Dn, DINn, x, DINn, Wp, bp, p_t0, Dn);
    ln256_kernel<<<Mrows, 256>>>(p_t0, p_h, g0, b0);

    for (int l = 0; l < NLn; l++) {
        // xz = h @ Wi^T  (N=1024, K=256) — duo (tensor+SIMT row split)
        duo_gemm<0><<<dim3(8, 256), 256>>>(2 * DIn, Dn, YSPLIT, p_h, Dn,
                                           Wi + (size_t)l * 2 * DIn * Dn,
                                           nullptr, p_xz, 2 * DIn);
        // depthwise causal conv + silu
        conv_silu_kernel<<<(Mrows * DIn) / 256, 256>>>(
            p_xz, conv_w + (size_t)l * DIn * DCn, conv_b + (size_t)l * DIn, p_u);
        // xdbc = u @ Wx^T  (N=48, K=512) — tensor
        tf32_gemm<0><<<dim3(1, 256), 256>>>(48, DIn, p_u, DIn,
                                            Wx + (size_t)l * 48 * DIn,
                                            nullptr, p_xdbc, 48);
        // dt = softplus(dtraw @ Wdt^T + bdt)  — SIMT sgemm (R4-proven)
        sgemm_dt<<<dim3(4, 256), 256>>>(DIn, DTRn, p_xdbc, 48,
                                        Wdt + (size_t)l * DIn * DTRn,
                                        bdt + (size_t)l * DIn, p_dt, DIn);
        // chunked selective scan
        scan_carry_kernel<<<128 * (C_CHUNKS - 1), 512>>>(
            p_u, p_dt, p_xdbc, A_log + (size_t)l * DIn * DSn, p_P, p_h0);
        scan_fix_kernel<<<NCH / 256, 256>>>(p_P, p_h0, p_hini);
        scan_main_kernel<<<128 * C_CHUNKS, 512>>>(
            p_u, p_dt, p_xz, p_xdbc,
            A_log + (size_t)l * DIn * DSn, Dp + (size_t)l * DIn,
            p_hini, p_y);
        // out = y @ Wo^T  (N=256, K=512) — duo, then LN
        duo_gemm<0><<<dim3(2, 256), 256>>>(Dn, DIn, YSPLIT, p_y, DIn,
                                           Wo + (size_t)l * Dn * DIn,
                                           nullptr, p_t0, Dn);
        ln256_kernel<<<Mrows, 256>>>(p_t0, p_h,
                                     ln_g + (size_t)l * Dn, ln_b + (size_t)l * Dn);
    }

    // pooling + final linear
    pool_logit_kernel<<<Mrows / 8, 256>>>(p_h, wa, ba, p_logit);
    pool_softmax_kernel<<<Bn, 1024>>>(p_logit);
    pool_wsum_kernel<<<Bn * 16, 256>>>(p_h, p_logit, p_part);
    pool_final_kernel<<<Bn, 256>>>(p_part, Wf, bf, (float*)d_out);
}

// round 10
// speedup vs baseline: 1.8336x; 1.1290x over previous
#include <cuda_runtime.h>
#include <math.h>
#include <stdint.h>

// Problem constants
#define Bn   8
#define Ln   4096
#define DINn 64
#define Dn   256
#define NLn  2
#define DIn  512
#define DSn  16
#define DCn  4
#define DTRn 16
#define Mrows (Bn * Ln)   // 32768

#define C_CHUNKS 4
#define CH_LEN   1024
#define NCH      (Bn * DIn * DSn)

// ---------------------------------------------------------------------------
// Scratch (device globals — no runtime allocation allowed)
// ---------------------------------------------------------------------------
__device__ float g_h    [Mrows * Dn];
__device__ float g_t0   [Mrows * Dn];
__device__ float g_xz   [Mrows * 2 * DIn];
__device__ float g_u    [Mrows * DIn];
__device__ float g_dt   [Mrows * DIn];
__device__ float g_xdbc [Mrows * 48];
__device__ float g_y    [Mrows * DIn];
__device__ float g_P    [(C_CHUNKS - 1) * NCH];
__device__ float g_h0   [(C_CHUNKS - 1) * NCH];
__device__ float g_hini [C_CHUNKS * NCH];
__device__ float g_logit[Mrows];
__device__ float g_part [Bn * 16 * Dn];

// ---------------------------------------------------------------------------
// Helpers
// ---------------------------------------------------------------------------
__device__ __forceinline__ float softplus_f(float x) {
    return fmaxf(x, 0.f) + log1pf(__expf(-fabsf(x)));
}
__device__ __forceinline__ float silu_f(float x) {
    return x / (1.f + __expf(-x));
}
__device__ __forceinline__ float to_tf32(float x) {
    float r;
    asm("cvt.rna.tf32.f32 %0, %1;" : "=f"(r) : "f"(x));
    return r;
}
__device__ __forceinline__ void mma8(float* d,
                                     float a0, float a1, float a2, float a3,
                                     float b0, float b1) {
    asm volatile(
        "mma.sync.aligned.m16n8k8.row.col.f32.tf32.tf32.f32 "
        "{%0,%1,%2,%3},{%4,%5,%6,%7},{%8,%9},{%0,%1,%2,%3};"
        : "+f"(d[0]), "+f"(d[1]), "+f"(d[2]), "+f"(d[3])
        : "r"(__float_as_uint(a0)), "r"(__float_as_uint(a1)),
          "r"(__float_as_uint(a2)), "r"(__float_as_uint(a3)),
          "r"(__float_as_uint(b0)), "r"(__float_as_uint(b1)));
}

// ---------------------------------------------------------------------------
// TF32 tensor-core GEMM (R4-proven, byte-identical inner loop).
// C[M,N] = A[M,K](row-major,lda) * W[N,K]^T.  EPI: 0 store, 1 +bias.
// ---------------------------------------------------------------------------
#define SPAD 24
template <int EPI>
__global__ void __launch_bounds__(256, 2) tf32_gemm(
    int N, int K,
    const float* __restrict__ A, int lda,
    const float* __restrict__ W,
    const float* __restrict__ bias,
    float* __restrict__ C, int ldc)
{
    __shared__ float As[2][128][SPAD];
    __shared__ float Ws[2][128][SPAD];

    const int tid  = threadIdx.x;
    const int wid  = tid >> 5, lane = tid & 31;
    const int wm   = (wid >> 2) * 64;
    const int wn   = (wid & 3) * 32;
    const int gr   = lane >> 2;
    const int gc   = lane & 3;
    const int m0   = blockIdx.y * 128;
    const int n0   = blockIdx.x * 128;

    const int lr0 = tid >> 2;
    const int lj  = tid & 3;
    const int pb  = (lj & 2) * 4 + (lj & 1);

    const float* Ag = A + (size_t)(m0 + lr0) * lda + lj * 4;
    const float* Wg = W + (size_t)(n0 + lr0) * K + lj * 4;
    const bool wok0 = (n0 + lr0) < N;
    const bool wok1 = (n0 + lr0 + 64) < N;

    float acc[4][4][4];
    #pragma unroll
    for (int i = 0; i < 4; i++)
        #pragma unroll
        for (int j = 0; j < 4; j++)
            #pragma unroll
            for (int t = 0; t < 4; t++) acc[i][j][t] = 0.f;

    float4 ra0, ra1, rw0, rw1;
    const float4 z4 = make_float4(0.f, 0.f, 0.f, 0.f);

    ra0 = *(const float4*)(Ag);
    ra1 = *(const float4*)(Ag + (size_t)64 * lda);
    rw0 = wok0 ? *(const float4*)(Wg) : z4;
    rw1 = wok1 ? *(const float4*)(Wg + (size_t)64 * K) : z4;
    {
        As[0][lr0     ][pb]     = to_tf32(ra0.x);
        As[0][lr0     ][pb + 2] = to_tf32(ra0.y);
        As[0][lr0     ][pb + 4] = to_tf32(ra0.z);
        As[0][lr0     ][pb + 6] = to_tf32(ra0.w);
        As[0][lr0 + 64][pb]     = to_tf32(ra1.x);
        As[0][lr0 + 64][pb + 2] = to_tf32(ra1.y);
        As[0][lr0 + 64][pb + 4] = to_tf32(ra1.z);
        As[0][lr0 + 64][pb + 6] = to_tf32(ra1.w);
        Ws[0][lr0     ][pb]     = to_tf32(rw0.x);
        Ws[0][lr0     ][pb + 2] = to_tf32(rw0.y);
        Ws[0][lr0     ][pb + 4] = to_tf32(rw0.z);
        Ws[0][lr0     ][pb + 6] = to_tf32(rw0.w);
        Ws[0][lr0 + 64][pb]     = to_tf32(rw1.x);
        Ws[0][lr0 + 64][pb + 2] = to_tf32(rw1.y);
        Ws[0][lr0 + 64][pb + 4] = to_tf32(rw1.z);
        Ws[0][lr0 + 64][pb + 6] = to_tf32(rw1.w);
    }
    __syncthreads();

    int buf = 0;
    for (int k0 = 16; k0 < K; k0 += 16) {
        ra0 = *(const float4*)(Ag + k0);
        ra1 = *(const float4*)(Ag + (size_t)64 * lda + k0);
        rw0 = wok0 ? *(const float4*)(Wg + k0) : z4;
        rw1 = wok1 ? *(const float4*)(Wg + (size_t)64 * K + k0) : z4;

        #pragma unroll
        for (int ks = 0; ks < 2; ks++) {
            float2 alo[4], ahi[4], bfr[4];
            #pragma unroll
            for (int fm = 0; fm < 4; fm++) {
                alo[fm] = *(const float2*)&As[buf][wm + fm * 16 + gr    ][ks * 8 + 2 * gc];
                ahi[fm] = *(const float2*)&As[buf][wm + fm * 16 + gr + 8][ks * 8 + 2 * gc];
            }
            #pragma unroll
            for (int fn = 0; fn < 4; fn++)
                bfr[fn] = *(const float2*)&Ws[buf][wn + fn * 8 + gr][ks * 8 + 2 * gc];
            #pragma unroll
            for (int fm = 0; fm < 4; fm++)
                #pragma unroll
                for (int fn = 0; fn < 4; fn++)
                    mma8(acc[fm][fn], alo[fm].x, ahi[fm].x, alo[fm].y, ahi[fm].y,
                         bfr[fn].x, bfr[fn].y);
        }

        const int nb = buf ^ 1;
        As[nb][lr0     ][pb]     = to_tf32(ra0.x);
        As[nb][lr0     ][pb + 2] = to_tf32(ra0.y);
        As[nb][lr0     ][pb + 4] = to_tf32(ra0.z);
        As[nb][lr0     ][pb + 6] = to_tf32(ra0.w);
        As[nb][lr0 + 64][pb]     = to_tf32(ra1.x);
        As[nb][lr0 + 64][pb + 2] = to_tf32(ra1.y);
        As[nb][lr0 + 64][pb + 4] = to_tf32(ra1.z);
        As[nb][lr0 + 64][pb + 6] = to_tf32(ra1.w);
        Ws[nb][lr0     ][pb]     = to_tf32(rw0.x);
        Ws[nb][lr0     ][pb + 2] = to_tf32(rw0.y);
        Ws[nb][lr0     ][pb + 4] = to_tf32(rw0.z);
        Ws[nb][lr0     ][pb + 6] = to_tf32(rw0.w);
        Ws[nb][lr0 + 64][pb]     = to_tf32(rw1.x);
        Ws[nb][lr0 + 64][pb + 2] = to_tf32(rw1.y);
        Ws[nb][lr0 + 64][pb + 4] = to_tf32(rw1.z);
        Ws[nb][lr0 + 64][pb + 6] = to_tf32(rw1.w);
        __syncthreads();
        buf = nb;
    }

    #pragma unroll
    for (int ks = 0; ks < 2; ks++) {
        float2 alo[4], ahi[4], bfr[4];
        #pragma unroll
        for (int fm = 0; fm < 4; fm++) {
            alo[fm] = *(const float2*)&As[buf][wm + fm * 16 + gr    ][ks * 8 + 2 * gc];
            ahi[fm] = *(const float2*)&As[buf][wm + fm * 16 + gr + 8][ks * 8 + 2 * gc];
        }
        #pragma unroll
        for (int fn = 0; fn < 4; fn++)
            bfr[fn] = *(const float2*)&Ws[buf][wn + fn * 8 + gr][ks * 8 + 2 * gc];
        #pragma unroll
        for (int fm = 0; fm < 4; fm++)
            #pragma unroll
            for (int fn = 0; fn < 4; fn++)
                mma8(acc[fm][fn], alo[fm].x, ahi[fm].x, alo[fm].y, ahi[fm].y,
                     bfr[fn].x, bfr[fn].y);
    }

    #pragma unroll
    for (int fm = 0; fm < 4; fm++) {
        const int r0 = m0 + wm + fm * 16 + gr;
        #pragma unroll
        for (int fn = 0; fn < 4; fn++) {
            const int c0 = n0 + wn + fn * 8 + 2 * gc;
            if (c0 < N) {
                float v0 = acc[fm][fn][0], v1 = acc[fm][fn][1];
                float v2 = acc[fm][fn][2], v3 = acc[fm][fn][3];
                if (EPI == 1) {
                    v0 += bias[c0]; v1 += bias[c0 + 1];
                    v2 += bias[c0]; v3 += bias[c0 + 1];
                }
                *(float2*)&C[(size_t)r0 * ldc + c0]       = make_float2(v0, v1);
                *(float2*)&C[(size_t)(r0 + 8) * ldc + c0] = make_float2(v2, v3);
            }
        }
    }
}

// ---------------------------------------------------------------------------
// SIMT SGEMM for dt (N=512, K=16). softplus(+bias) epilogue. (R4-proven.)
// ---------------------------------------------------------------------------
__global__ void __launch_bounds__(256, 2) sgemm_dt(
    int N, int K,
    const float* __restrict__ A, int lda,
    const float* __restrict__ W,
    const float* __restrict__ bias,
    float* __restrict__ C, int ldc)
{
    __shared__ __align__(16) float As[8][132];
    __shared__ __align__(16) float Ws2[8][132];

    const int tid = threadIdx.x;
    const int tx = tid & 15;
    const int ty = tid >> 4;
    const int m0 = blockIdx.y * 128;
    const int n0 = blockIdx.x * 128;

    const int lr = tid >> 1;
    const int lk = (tid & 1) * 4;

    float acc[8][8];
    #pragma unroll
    for (int i = 0; i < 8; i++)
        #pragma unroll
        for (int j = 0; j < 8; j++) acc[i][j] = 0.f;

    const float* Aptr = A + (size_t)(m0 + lr) * lda + lk;
    const int wn = n0 + lr;
    const float* Wptr = W + (size_t)wn * K + lk;
    const bool wok = (wn < N);

    for (int k0 = 0; k0 < K; k0 += 8) {
        float4 av = *(const float4*)(Aptr + k0);
        As[lk + 0][lr] = av.x; As[lk + 1][lr] = av.y;
        As[lk + 2][lr] = av.z; As[lk + 3][lr] = av.w;

        float4 wv = make_float4(0.f, 0.f, 0.f, 0.f);
        if (wok) wv = *(const float4*)(Wptr + k0);
        Ws2[lk + 0][lr] = wv.x; Ws2[lk + 1][lr] = wv.y;
        Ws2[lk + 2][lr] = wv.z; Ws2[lk + 3][lr] = wv.w;

        __syncthreads();
        #pragma unroll
        for (int k = 0; k < 8; k++) {
            float a[8], bb[8];
            *(float4*)&a[0]  = *(const float4*)&As[k][ty * 4];
            *(float4*)&a[4]  = *(const float4*)&As[k][64 + ty * 4];
            *(float4*)&bb[0] = *(const float4*)&Ws2[k][tx * 4];
            *(float4*)&bb[4] = *(const float4*)&Ws2[k][64 + tx * 4];
            #pragma unroll
            for (int i = 0; i < 8; i++)
                #pragma unroll
                for (int j = 0; j < 8; j++)
                    acc[i][j] = fmaf(a[i], bb[j], acc[i][j]);
        }
        __syncthreads();
    }

    #pragma unroll
    for (int i = 0; i < 8; i++) {
        const int r = m0 + ((i < 4) ? (ty * 4 + i) : (64 + ty * 4 + i - 4));
        #pragma unroll
        for (int j = 0; j < 8; j++) {
            const int c = n0 + ((j < 4) ? (tx * 4 + j) : (64 + tx * 4 + j - 4));
            if (c < N) {
                float v = acc[i][j] + bias[c];
                C[(size_t)r * ldc + c] = softplus_f(v);
            }
        }
    }
}

// ---------------------------------------------------------------------------
// Depthwise causal conv (DC=4) + bias + SiLU — scalar (R4-proven).
// Reads only the u-half of xz (cols 0..511).
// ---------------------------------------------------------------------------
__global__ void conv_silu_kernel(const float* __restrict__ xz,
                                 const float* __restrict__ w,
                                 const float* __restrict__ cb,
                                 float* __restrict__ u)
{
    const int idx = blockIdx.x * blockDim.x + threadIdx.x;
    if (idx >= Mrows * DIn) return;
    const int d  = idx & (DIn - 1);
    const int bl = idx >> 9;
    const int l  = bl & (Ln - 1);
    float acc = cb[d];
    #pragma unroll
    for (int k = 0; k < 4; k++) {
        const int ll = l - 3 + k;
        if (ll >= 0)
            acc = fmaf(w[d * 4 + k], xz[(size_t)(bl - 3 + k) * (2 * DIn) + d], acc);
    }
    u[idx] = silu_f(acc);
}

// ---------------------------------------------------------------------------
// LayerNorm over last dim (256), one block per row.
// ---------------------------------------------------------------------------
__global__ void ln256_kernel(const float* __restrict__ in, float* __restrict__ out,
                             const float* __restrict__ g, const float* __restrict__ b)
{
    const int row = blockIdx.x;
    const int t = threadIdx.x;
    const float v = in[(size_t)row * 256 + t];
    float s = v, sq = v * v;
    #pragma unroll
    for (int o = 16; o > 0; o >>= 1) {
        s  += __shfl_xor_sync(~0u, s, o);
        sq += __shfl_xor_sync(~0u, sq, o);
    }
    __shared__ float ss[8], ssq[8];
    if ((t & 31) == 0) { ss[t >> 5] = s; ssq[t >> 5] = sq; }
    __syncthreads();
    float tot = 0.f, totq = 0.f;
    #pragma unroll
    for (int i = 0; i < 8; i++) { tot += ss[i]; totq += ssq[i]; }
    const float mean = tot * (1.f / 256.f);
    const float var  = totq * (1.f / 256.f) - mean * mean;
    const float rstd = rsqrtf(var + 1e-5f);
    out[(size_t)row * 256 + t] = (v - mean) * rstd * g[t] + b[t];
}

// ---------------------------------------------------------------------------
// Chunked selective scan (4 chunks of 1024) — R4-proven.
// ---------------------------------------------------------------------------
#define SCH 64

__global__ void __launch_bounds__(512) scan_carry_kernel(
    const float* __restrict__ u, const float* __restrict__ dt,
    const float* __restrict__ xdbc, const float* __restrict__ A_log,
    float* __restrict__ Pout, float* __restrict__ h0out)
{
    __shared__ float s_dt[SCH][32], s_u[SCH][32], s_B[SCH][16];

    const int tid = threadIdx.x;
    const int c   = blockIdx.x >> 7;
    const int rem = blockIdx.x & 127;
    const int b   = rem >> 4;
    const int d0  = (rem & 15) * 32;
    const int s   = tid & 15;
    const int dd  = tid >> 4;
    const int d   = d0 + dd;

    const float A = -__expf(A_log[d * DSn + s]);
    float h = 0.f, P = 1.f;

    const size_t base_bl = (size_t)b * Ln + (size_t)c * CH_LEN;

    for (int l0 = 0; l0 < CH_LEN; l0 += SCH) {
        for (int i = tid; i < SCH * 32; i += 512) {
            const int r = i >> 5, cc = i & 31;
            const size_t bl = base_bl + l0 + r;
            s_dt[r][cc] = dt[bl * DIn + d0 + cc];
            s_u [r][cc] = u [bl * DIn + d0 + cc];
        }
        for (int i = tid; i < SCH * 16; i += 512) {
            const int r = i >> 4, cc = i & 15;
            const size_t bl = base_bl + l0 + r;
            s_B[r][cc] = xdbc[bl * 48 + 16 + cc];
        }
        __syncthreads();

        #pragma unroll 4
        for (int i = 0; i < SCH; i++) {
            const float dtv = s_dt[i][dd];
            const float dA  = __expf(dtv * A);
            P *= dA;
            h = fmaf(h, dA, dtv * s_u[i][dd] * s_B[i][s]);
        }
        __syncthreads();
    }

    const int ch = ((b * DIn + d) * DSn + s);
    Pout [c * NCH + ch] = P;
    h0out[c * NCH + ch] = h;
}

__global__ void scan_fix_kernel(const float* __restrict__ P,
                                const float* __restrict__ h0,
                                float* __restrict__ hini)
{
    const int ch = blockIdx.x * blockDim.x + threadIdx.x;
    float h = 0.f;
    hini[ch] = 0.f;
    #pragma unroll
    for (int c = 1; c < C_CHUNKS; c++) {
        h = fmaf(P[(c - 1) * NCH + ch], h, h0[(c - 1) * NCH + ch]);
        hini[c * NCH + ch] = h;
    }
}

__global__ void __launch_bounds__(512) scan_main_kernel(
    const float* __restrict__ u, const float* __restrict__ dt,
    const float* __restrict__ xz, const float* __restrict__ xdbc,
    const float* __restrict__ A_log, const float* __restrict__ Dp,
    const float* __restrict__ hini,
    float* __restrict__ y)
{
    __shared__ float s_dt[SCH][32], s_u[SCH][32], s_z[SCH][32], s_y[SCH][32];
    __shared__ float s_B[SCH][16], s_C[SCH][16];

    const int tid = threadIdx.x;
    const int c   = blockIdx.x >> 7;
    const int rem = blockIdx.x & 127;
    const int b   = rem >> 4;
    const int d0  = (rem & 15) * 32;
    const int s   = tid & 15;
    const int dd  = tid >> 4;
    const int d   = d0 + dd;

    const float A   = -__expf(A_log[d * DSn + s]);
    const float dpv = Dp[d];
    const int ch = ((b * DIn + d) * DSn + s);
    float h = hini[c * NCH + ch];

    const size_t base_bl = (size_t)b * Ln + (size_t)c * CH_LEN;

    for (int l0 = 0; l0 < CH_LEN; l0 += SCH) {
        for (int i = tid; i < SCH * 32; i += 512) {
            const int r = i >> 5, cc = i & 31;
            const size_t bl = base_bl + l0 + r;
            s_dt[r][cc] = dt[bl * DIn + d0 + cc];
            s_u [r][cc] = u [bl * DIn + d0 + cc];
            s_z [r][cc] = xz[bl * (2 * DIn) + DIn + d0 + cc];
        }
        for (int i = tid; i < SCH * 16; i += 512) {
            const int r = i >> 4, cc = i & 15;
            const size_t bl = base_bl + l0 + r;
            s_B[r][cc] = xdbc[bl * 48 + 16 + cc];
            s_C[r][cc] = xdbc[bl * 48 + 32 + cc];
        }
        __syncthreads();

        #pragma unroll 4
        for (int i = 0; i < SCH; i++) {
            const float dtv = s_dt[i][dd];
            const float uv  = s_u[i][dd];
            const float dA  = __expf(dtv * A);
            h = fmaf(h, dA, dtv * uv * s_B[i][s]);
            float yv = h * s_C[i][s];
            yv += __shfl_xor_sync(~0u, yv, 1);
            yv += __shfl_xor_sync(~0u, yv, 2);
            yv += __shfl_xor_sync(~0u, yv, 4);
            yv += __shfl_xor_sync(~0u, yv, 8);
            if (s == 0) {
                const float zv = s_z[i][dd];
                s_y[i][dd] = (yv + uv * dpv) * silu_f(zv);
            }
        }
        __syncthreads();

        for (int i = tid; i < SCH * 32; i += 512) {
            const int r = i >> 5, cc = i & 31;
            y[(base_bl + l0 + r) * DIn + d0 + cc] = s_y[r][cc];
        }
        __syncthreads();
    }
}

// ---------------------------------------------------------------------------
// Pooling (split, R4-proven).
// ---------------------------------------------------------------------------
__global__ void pool_logit_kernel(const float* __restrict__ h,
                                  const float* __restrict__ wa,
                                  const float* __restrict__ ba,
                                  float* __restrict__ logit)
{
    const int wid_in_blk = threadIdx.x >> 5;
    const int lane = threadIdx.x & 31;
    const int row = blockIdx.x * 8 + wid_in_blk;
    const float* r = h + (size_t)row * 256;
    float acc = 0.f;
    #pragma unroll
    for (int k = 0; k < 2; k++) {
        const float4 hv = *(const float4*)(r + k * 128 + lane * 4);
        const float4 wv = *(const float4*)(wa + k * 128 + lane * 4);
        acc += hv.x * wv.x + hv.y * wv.y + hv.z * wv.z + hv.w * wv.w;
    }
    #pragma unroll
    for (int o = 16; o > 0; o >>= 1) acc += __shfl_xor_sync(~0u, acc, o);
    if (lane == 0) logit[row] = acc + ba[0];
}

__global__ void __launch_bounds__(1024) pool_softmax_kernel(float* __restrict__ logit)
{
    __shared__ float s_red[32];
    const int b = blockIdx.x, tid = threadIdx.x;
    float* lg = logit + b * Ln;

    float mx = -1e30f;
    float v[4];
    #pragma unroll
    for (int k = 0; k < 4; k++) {
        v[k] = lg[tid + k * 1024];
        mx = fmaxf(mx, v[k]);
    }
    #pragma unroll
    for (int o = 16; o > 0; o >>= 1) mx = fmaxf(mx, __shfl_xor_sync(~0u, mx, o));
    if ((tid & 31) == 0) s_red[tid >> 5] = mx;
    __syncthreads();
    if (tid < 32) {
        float t = s_red[tid];
        #pragma unroll
        for (int o = 16; o > 0; o >>= 1) t = fmaxf(t, __shfl_xor_sync(~0u, t, o));
        s_red[tid] = t;
    }
    __syncthreads();
    mx = s_red[0];
    __syncthreads();

    float sum = 0.f;
    #pragma unroll
    for (int k = 0; k < 4; k++) {
        v[k] = __expf(v[k] - mx);
        sum += v[k];
    }
    #pragma unroll
    for (int o = 16; o > 0; o >>= 1) sum += __shfl_xor_sync(~0u, sum, o);
    if ((tid & 31) == 0) s_red[tid >> 5] = sum;
    __syncthreads();
    if (tid < 32) {
        float t = s_red[tid];
        #pragma unroll
        for (int o = 16; o > 0; o >>= 1) t += __shfl_xor_sync(~0u, t, o);
        s_red[tid] = t;
    }
    __syncthreads();
    const float inv = 1.f / s_red[0];
    #pragma unroll
    for (int k = 0; k < 4; k++) lg[tid + k * 1024] = v[k] * inv;
}

__global__ void pool_wsum_kernel(const float* __restrict__ h,
                                 const float* __restrict__ p,
                                 float* __restrict__ part)
{
    const int b = blockIdx.x >> 4;
    const int sp = blockIdx.x & 15;
    const int tid = threadIdx.x;
    const size_t base = ((size_t)b * Ln + sp * 256) * 256;
    const float* pp = p + b * Ln + sp * 256;
    float acc = 0.f;
    for (int l = 0; l < 256; l++)
        acc = fmaf(pp[l], h[base + (size_t)l * 256 + tid], acc);
    part[(size_t)(b * 16 + sp) * 256 + tid] = acc;
}

__global__ void pool_final_kernel(const float* __restrict__ part,
                                  const float* __restrict__ Wf,
                                  const float* __restrict__ bf,
                                  float* __restrict__ out)
{
    __shared__ float s_red[8];
    const int b = blockIdx.x, tid = threadIdx.x;
    float pooled = 0.f;
    #pragma unroll
    for (int sp = 0; sp < 16; sp++)
        pooled += part[(size_t)(b * 16 + sp) * 256 + tid];
    float val = pooled * Wf[tid];
    #pragma unroll
    for (int o = 16; o > 0; o >>= 1) val += __shfl_xor_sync(~0u, val, o);
    if ((tid & 31) == 0) s_red[tid >> 5] = val;
    __syncthreads();
    if (tid == 0) {
        float tot = 0.f;
        #pragma unroll
        for (int i = 0; i < 8; i++) tot += s_red[i];
        out[b] = tot + bf[0];
    }
}

// ---------------------------------------------------------------------------
// Launch — stream fork: xz z-half (tensor-bound) overlaps the memory-bound
// conv->Wx->dt->carry->fix chain which only needs the u-half.
// ---------------------------------------------------------------------------
extern "C" void kernel_launch(void* const* d_in, const int* in_sizes, int n_in,
                              void* d_out, int out_size)
{
    const float* x      = (const float*)d_in[0];
    const float* Wp     = (const float*)d_in[1];
    const float* bp     = (const float*)d_in[2];
    const float* g0     = (const float*)d_in[3];
    const float* b0     = (const float*)d_in[4];
    const float* Wi     = (const float*)d_in[5];
    const float* conv_w = (const float*)d_in[6];
    const float* conv_b = (const float*)d_in[7];
    const float* Wx     = (const float*)d_in[8];
    const float* Wdt    = (const float*)d_in[9];
    const float* bdt    = (const float*)d_in[10];
    const float* A_log  = (const float*)d_in[11];
    const float* Dp     = (const float*)d_in[12];
    const float* Wo     = (const float*)d_in[13];
    const float* ln_g   = (const float*)d_in[14];
    const float* ln_b   = (const float*)d_in[15];
    const float* wa     = (const float*)d_in[16];
    const float* ba     = (const float*)d_in[17];
    const float* Wf     = (const float*)d_in[18];
    const float* bf     = (const float*)d_in[19];

    float *p_h, *p_t0, *p_xz, *p_u, *p_dt, *p_xdbc, *p_y;
    float *p_P, *p_h0, *p_hini, *p_logit, *p_part;
    cudaGetSymbolAddress((void**)&p_h,    g_h);
    cudaGetSymbolAddress((void**)&p_t0,   g_t0);
    cudaGetSymbolAddress((void**)&p_xz,   g_xz);
    cudaGetSymbolAddress((void**)&p_u,    g_u);
    cudaGetSymbolAddress((void**)&p_dt,   g_dt);
    cudaGetSymbolAddress((void**)&p_xdbc, g_xdbc);
    cudaGetSymbolAddress((void**)&p_y,    g_y);
    cudaGetSymbolAddress((void**)&p_P,    g_P);
    cudaGetSymbolAddress((void**)&p_h0,   g_h0);
    cudaGetSymbolAddress((void**)&p_hini, g_hini);
    cudaGetSymbolAddress((void**)&p_logit, g_logit);
    cudaGetSymbolAddress((void**)&p_part, g_part);

    // One-time side-stream/event setup (first call runs outside graph capture).
    static cudaStream_t s1 = nullptr;
    static cudaEvent_t evFork = nullptr, evJoin = nullptr;
    if (s1 == nullptr) {
        cudaStreamCreateWithFlags(&s1, cudaStreamNonBlocking);
        cudaEventCreateWithFlags(&evFork, cudaEventDisableTiming);
        cudaEventCreateWithFlags(&evJoin, cudaEventDisableTiming);
    }

    // input projection + bias (tensor tf32) + LN
    tf32_gemm<1><<<dim3(2, 256), 256>>>(Dn, DINn, x, DINn, Wp, bp, p_t0, Dn);
    ln256_kernel<<<Mrows, 256>>>(p_t0, p_h, g0, b0);

    for (int l = 0; l < NLn; l++) {
        const float* Wi_l = Wi + (size_t)l * 2 * DIn * Dn;

        // xz u-half = h @ Wi[0:512]^T   (N=512, K=256)
        tf32_gemm<0><<<dim3(4, 256), 256>>>(DIn, Dn, p_h, Dn,
                                            Wi_l, nullptr, p_xz, 2 * DIn);
        // fork: z-half on side stream (tensor-bound), overlaps mem-bound chain
        cudaEventRecord(evFork, 0);
        cudaStreamWaitEvent(s1, evFork, 0);
        tf32_gemm<0><<<dim3(4, 256), 256, 0, s1>>>(DIn, Dn, p_h, Dn,
                                                   Wi_l + (size_t)DIn * Dn,
                                                   nullptr, p_xz + DIn, 2 * DIn);
        cudaEventRecord(evJoin, s1);

        // mem-bound chain on default stream (needs only u-half)
        conv_silu_kernel<<<(Mrows * DIn) / 256, 256>>>(
            p_xz, conv_w + (size_t)l * DIn * DCn, conv_b + (size_t)l * DIn, p_u);
        tf32_gemm<0><<<dim3(1, 256), 256>>>(48, DIn, p_u, DIn,
                                            Wx + (size_t)l * 48 * DIn,
                                            nullptr, p_xdbc, 48);
        sgemm_dt<<<dim3(4, 256), 256>>>(DIn, DTRn, p_xdbc, 48,
                                        Wdt + (size_t)l * DIn * DTRn,
                                        bdt + (size_t)l * DIn, p_dt, DIn);
        scan_carry_kernel<<<128 * (C_CHUNKS - 1), 512>>>(
            p_u, p_dt, p_xdbc, A_log + (size_t)l * DIn * DSn, p_P, p_h0);
        scan_fix_kernel<<<NCH / 256, 256>>>(p_P, p_h0, p_hini);

        // join: scan_main needs z-half
        cudaStreamWaitEvent(0, evJoin, 0);
        scan_main_kernel<<<128 * C_CHUNKS, 512>>>(
            p_u, p_dt, p_xz, p_xdbc,
            A_log + (size_t)l * DIn * DSn, Dp + (size_t)l * DIn,
            p_hini, p_y);

        // out = y @ Wo^T  (N=256, K=512), then LN
        tf32_gemm<0><<<dim3(2, 256), 256>>>(Dn, DIn, p_y, DIn,
                                            Wo + (size_t)l * Dn * DIn,
                                            nullptr, p_t0, Dn);
        ln256_kernel<<<Mrows, 256>>>(p_t0, p_h,
                                     ln_g + (size_t)l * Dn, ln_b + (size_t)l * Dn);
    }

    // pooling + final linear
    pool_logit_kernel<<<Mrows / 8, 256>>>(p_h, wa, ba, p_logit);
    pool_softmax_kernel<<<Bn, 1024>>>(p_logit);
    pool_wsum_kernel<<<Bn * 16, 256>>>(p_h, p_logit, p_part);
    pool_final_kernel<<<Bn, 256>>>(p_part, Wf, bf, (float*)d_out);
}

// round 11
// speedup vs baseline: 2.6289x; 1.4337x over previous
#include <cuda_runtime.h>
#include <math.h>
#include <stdint.h>

// Problem constants
#define Bn   8
#define Ln   4096
#define DINn 64
#define Dn   256
#define NLn  2
#define DIn  512
#define DSn  16
#define DCn  4
#define DTRn 16
#define Mrows (Bn * Ln)   // 32768

#define C_CHUNKS 8
#define CH_LEN   512      // Ln / C_CHUNKS
#define NCH      (Bn * DIn * DSn)   // 65536

// ---------------------------------------------------------------------------
// Scratch (device globals — no runtime allocation allowed)
// ---------------------------------------------------------------------------
__device__ float g_h    [Mrows * Dn];
__device__ float g_t0   [Mrows * Dn];
__device__ float g_xz   [Mrows * 2 * DIn];
__device__ float g_u    [Mrows * DIn];
__device__ float g_dt   [Mrows * DIn];
__device__ float g_xdbc [Mrows * 48];
__device__ float g_y    [Mrows * DIn];
__device__ float g_P    [(C_CHUNKS - 1) * NCH];
__device__ float g_h0   [(C_CHUNKS - 1) * NCH];
__device__ float g_hini [C_CHUNKS * NCH];
__device__ float g_logit[Mrows];
__device__ float g_part [Bn * 16 * Dn];

// ---------------------------------------------------------------------------
// Helpers
// ---------------------------------------------------------------------------
__device__ __forceinline__ float softplus_f(float x) {
    return fmaxf(x, 0.f) + log1pf(__expf(-fabsf(x)));
}
__device__ __forceinline__ float silu_f(float x) {
    return x / (1.f + __expf(-x));
}
__device__ __forceinline__ float to_tf32(float x) {
    float r;
    asm("cvt.rna.tf32.f32 %0, %1;" : "=f"(r) : "f"(x));
    return r;
}
__device__ __forceinline__ float ex2f(float x) {
    float r;
    asm("ex2.approx.ftz.f32 %0, %1;" : "=f"(r) : "f"(x));
    return r;
}
#define LOG2E 1.4426950408889634f
__device__ __forceinline__ void mma8(float* d,
                                     float a0, float a1, float a2, float a3,
                                     float b0, float b1) {
    asm volatile(
        "mma.sync.aligned.m16n8k8.row.col.f32.tf32.tf32.f32 "
        "{%0,%1,%2,%3},{%4,%5,%6,%7},{%8,%9},{%0,%1,%2,%3};"
        : "+f"(d[0]), "+f"(d[1]), "+f"(d[2]), "+f"(d[3])
        : "r"(__float_as_uint(a0)), "r"(__float_as_uint(a1)),
          "r"(__float_as_uint(a2)), "r"(__float_as_uint(a3)),
          "r"(__float_as_uint(b0)), "r"(__float_as_uint(b1)));
}

// ---------------------------------------------------------------------------
// TF32 tensor-core GEMM (R4-proven, unchanged).
// ---------------------------------------------------------------------------
#define SPAD 24
template <int EPI>
__global__ void __launch_bounds__(256, 2) tf32_gemm(
    int N, int K,
    const float* __restrict__ A, int lda,
    const float* __restrict__ W,
    const float* __restrict__ bias,
    float* __restrict__ C, int ldc)
{
    __shared__ float As[2][128][SPAD];
    __shared__ float Ws[2][128][SPAD];

    const int tid  = threadIdx.x;
    const int wid  = tid >> 5, lane = tid & 31;
    const int wm   = (wid >> 2) * 64;
    const int wn   = (wid & 3) * 32;
    const int gr   = lane >> 2;
    const int gc   = lane & 3;
    const int m0   = blockIdx.y * 128;
    const int n0   = blockIdx.x * 128;

    const int lr0 = tid >> 2;
    const int lj  = tid & 3;
    const int pb  = (lj & 2) * 4 + (lj & 1);

    const float* Ag = A + (size_t)(m0 + lr0) * lda + lj * 4;
    const float* Wg = W + (size_t)(n0 + lr0) * K + lj * 4;
    const bool wok0 = (n0 + lr0) < N;
    const bool wok1 = (n0 + lr0 + 64) < N;

    float acc[4][4][4];
    #pragma unroll
    for (int i = 0; i < 4; i++)
        #pragma unroll
        for (int j = 0; j < 4; j++)
            #pragma unroll
            for (int t = 0; t < 4; t++) acc[i][j][t] = 0.f;

    float4 ra0, ra1, rw0, rw1;
    const float4 z4 = make_float4(0.f, 0.f, 0.f, 0.f);

    ra0 = *(const float4*)(Ag);
    ra1 = *(const float4*)(Ag + (size_t)64 * lda);
    rw0 = wok0 ? *(const float4*)(Wg) : z4;
    rw1 = wok1 ? *(const float4*)(Wg + (size_t)64 * K) : z4;
    {
        As[0][lr0     ][pb]     = to_tf32(ra0.x);
        As[0][lr0     ][pb + 2] = to_tf32(ra0.y);
        As[0][lr0     ][pb + 4] = to_tf32(ra0.z);
        As[0][lr0     ][pb + 6] = to_tf32(ra0.w);
        As[0][lr0 + 64][pb]     = to_tf32(ra1.x);
        As[0][lr0 + 64][pb + 2] = to_tf32(ra1.y);
        As[0][lr0 + 64][pb + 4] = to_tf32(ra1.z);
        As[0][lr0 + 64][pb + 6] = to_tf32(ra1.w);
        Ws[0][lr0     ][pb]     = to_tf32(rw0.x);
        Ws[0][lr0     ][pb + 2] = to_tf32(rw0.y);
        Ws[0][lr0     ][pb + 4] = to_tf32(rw0.z);
        Ws[0][lr0     ][pb + 6] = to_tf32(rw0.w);
        Ws[0][lr0 + 64][pb]     = to_tf32(rw1.x);
        Ws[0][lr0 + 64][pb + 2] = to_tf32(rw1.y);
        Ws[0][lr0 + 64][pb + 4] = to_tf32(rw1.z);
        Ws[0][lr0 + 64][pb + 6] = to_tf32(rw1.w);
    }
    __syncthreads();

    int buf = 0;
    for (int k0 = 16; k0 < K; k0 += 16) {
        ra0 = *(const float4*)(Ag + k0);
        ra1 = *(const float4*)(Ag + (size_t)64 * lda + k0);
        rw0 = wok0 ? *(const float4*)(Wg + k0) : z4;
        rw1 = wok1 ? *(const float4*)(Wg + (size_t)64 * K + k0) : z4;

        #pragma unroll
        for (int ks = 0; ks < 2; ks++) {
            float2 alo[4], ahi[4], bfr[4];
            #pragma unroll
            for (int fm = 0; fm < 4; fm++) {
                alo[fm] = *(const float2*)&As[buf][wm + fm * 16 + gr    ][ks * 8 + 2 * gc];
                ahi[fm] = *(const float2*)&As[buf][wm + fm * 16 + gr + 8][ks * 8 + 2 * gc];
            }
            #pragma unroll
            for (int fn = 0; fn < 4; fn++)
                bfr[fn] = *(const float2*)&Ws[buf][wn + fn * 8 + gr][ks * 8 + 2 * gc];
            #pragma unroll
            for (int fm = 0; fm < 4; fm++)
                #pragma unroll
                for (int fn = 0; fn < 4; fn++)
                    mma8(acc[fm][fn], alo[fm].x, ahi[fm].x, alo[fm].y, ahi[fm].y,
                         bfr[fn].x, bfr[fn].y);
        }

        const int nb = buf ^ 1;
        As[nb][lr0     ][pb]     = to_tf32(ra0.x);
        As[nb][lr0     ][pb + 2] = to_tf32(ra0.y);
        As[nb][lr0     ][pb + 4] = to_tf32(ra0.z);
        As[nb][lr0     ][pb + 6] = to_tf32(ra0.w);
        As[nb][lr0 + 64][pb]     = to_tf32(ra1.x);
        As[nb][lr0 + 64][pb + 2] = to_tf32(ra1.y);
        As[nb][lr0 + 64][pb + 4] = to_tf32(ra1.z);
        As[nb][lr0 + 64][pb + 6] = to_tf32(ra1.w);
        Ws[nb][lr0     ][pb]     = to_tf32(rw0.x);
        Ws[nb][lr0     ][pb + 2] = to_tf32(rw0.y);
        Ws[nb][lr0     ][pb + 4] = to_tf32(rw0.z);
        Ws[nb][lr0     ][pb + 6] = to_tf32(rw0.w);
        Ws[nb][lr0 + 64][pb]     = to_tf32(rw1.x);
        Ws[nb][lr0 + 64][pb + 2] = to_tf32(rw1.y);
        Ws[nb][lr0 + 64][pb + 4] = to_tf32(rw1.z);
        Ws[nb][lr0 + 64][pb + 6] = to_tf32(rw1.w);
        __syncthreads();
        buf = nb;
    }

    #pragma unroll
    for (int ks = 0; ks < 2; ks++) {
        float2 alo[4], ahi[4], bfr[4];
        #pragma unroll
        for (int fm = 0; fm < 4; fm++) {
            alo[fm] = *(const float2*)&As[buf][wm + fm * 16 + gr    ][ks * 8 + 2 * gc];
            ahi[fm] = *(const float2*)&As[buf][wm + fm * 16 + gr + 8][ks * 8 + 2 * gc];
        }
        #pragma unroll
        for (int fn = 0; fn < 4; fn++)
            bfr[fn] = *(const float2*)&Ws[buf][wn + fn * 8 + gr][ks * 8 + 2 * gc];
        #pragma unroll
        for (int fm = 0; fm < 4; fm++)
            #pragma unroll
            for (int fn = 0; fn < 4; fn++)
                mma8(acc[fm][fn], alo[fm].x, ahi[fm].x, alo[fm].y, ahi[fm].y,
                     bfr[fn].x, bfr[fn].y);
    }

    #pragma unroll
    for (int fm = 0; fm < 4; fm++) {
        const int r0 = m0 + wm + fm * 16 + gr;
        #pragma unroll
        for (int fn = 0; fn < 4; fn++) {
            const int c0 = n0 + wn + fn * 8 + 2 * gc;
            if (c0 < N) {
                float v0 = acc[fm][fn][0], v1 = acc[fm][fn][1];
                float v2 = acc[fm][fn][2], v3 = acc[fm][fn][3];
                if (EPI == 1) {
                    v0 += bias[c0]; v1 += bias[c0 + 1];
                    v2 += bias[c0]; v3 += bias[c0 + 1];
                }
                *(float2*)&C[(size_t)r0 * ldc + c0]       = make_float2(v0, v1);
                *(float2*)&C[(size_t)(r0 + 8) * ldc + c0] = make_float2(v2, v3);
            }
        }
    }
}

// ---------------------------------------------------------------------------
// SIMT SGEMM for dt (N=512, K=16). softplus(+bias) epilogue. (R4-proven.)
// ---------------------------------------------------------------------------
__global__ void __launch_bounds__(256, 2) sgemm_dt(
    int N, int K,
    const float* __restrict__ A, int lda,
    const float* __restrict__ W,
    const float* __restrict__ bias,
    float* __restrict__ C, int ldc)
{
    __shared__ __align__(16) float As[8][132];
    __shared__ __align__(16) float Ws2[8][132];

    const int tid = threadIdx.x;
    const int tx = tid & 15;
    const int ty = tid >> 4;
    const int m0 = blockIdx.y * 128;
    const int n0 = blockIdx.x * 128;

    const int lr = tid >> 1;
    const int lk = (tid & 1) * 4;

    float acc[8][8];
    #pragma unroll
    for (int i = 0; i < 8; i++)
        #pragma unroll
        for (int j = 0; j < 8; j++) acc[i][j] = 0.f;

    const float* Aptr = A + (size_t)(m0 + lr) * lda + lk;
    const int wn = n0 + lr;
    const float* Wptr = W + (size_t)wn * K + lk;
    const bool wok = (wn < N);

    for (int k0 = 0; k0 < K; k0 += 8) {
        float4 av = *(const float4*)(Aptr + k0);
        As[lk + 0][lr] = av.x; As[lk + 1][lr] = av.y;
        As[lk + 2][lr] = av.z; As[lk + 3][lr] = av.w;

        float4 wv = make_float4(0.f, 0.f, 0.f, 0.f);
        if (wok) wv = *(const float4*)(Wptr + k0);
        Ws2[lk + 0][lr] = wv.x; Ws2[lk + 1][lr] = wv.y;
        Ws2[lk + 2][lr] = wv.z; Ws2[lk + 3][lr] = wv.w;

        __syncthreads();
        #pragma unroll
        for (int k = 0; k < 8; k++) {
            float a[8], bb[8];
            *(float4*)&a[0]  = *(const float4*)&As[k][ty * 4];
            *(float4*)&a[4]  = *(const float4*)&As[k][64 + ty * 4];
            *(float4*)&bb[0] = *(const float4*)&Ws2[k][tx * 4];
            *(float4*)&bb[4] = *(const float4*)&Ws2[k][64 + tx * 4];
            #pragma unroll
            for (int i = 0; i < 8; i++)
                #pragma unroll
                for (int j = 0; j < 8; j++)
                    acc[i][j] = fmaf(a[i], bb[j], acc[i][j]);
        }
        __syncthreads();
    }

    #pragma unroll
    for (int i = 0; i < 8; i++) {
        const int r = m0 + ((i < 4) ? (ty * 4 + i) : (64 + ty * 4 + i - 4));
        #pragma unroll
        for (int j = 0; j < 8; j++) {
            const int c = n0 + ((j < 4) ? (tx * 4 + j) : (64 + tx * 4 + j - 4));
            if (c < N) {
                float v = acc[i][j] + bias[c];
                C[(size_t)r * ldc + c] = softplus_f(v);
            }
        }
    }
}

// ---------------------------------------------------------------------------
// Depthwise causal conv (DC=4) + bias + SiLU — scalar (R4-proven).
// ---------------------------------------------------------------------------
__global__ void conv_silu_kernel(const float* __restrict__ xz,
                                 const float* __restrict__ w,
                                 const float* __restrict__ cb,
                                 float* __restrict__ u)
{
    const int idx = blockIdx.x * blockDim.x + threadIdx.x;
    if (idx >= Mrows * DIn) return;
    const int d  = idx & (DIn - 1);
    const int bl = idx >> 9;
    const int l  = bl & (Ln - 1);
    float acc = cb[d];
    #pragma unroll
    for (int k = 0; k < 4; k++) {
        const int ll = l - 3 + k;
        if (ll >= 0)
            acc = fmaf(w[d * 4 + k], xz[(size_t)(bl - 3 + k) * (2 * DIn) + d], acc);
    }
    u[idx] = silu_f(acc);
}

// ---------------------------------------------------------------------------
// LayerNorm over last dim (256), one block per row.
// ---------------------------------------------------------------------------
__global__ void ln256_kernel(const float* __restrict__ in, float* __restrict__ out,
                             const float* __restrict__ g, const float* __restrict__ b)
{
    const int row = blockIdx.x;
    const int t = threadIdx.x;
    const float v = in[(size_t)row * 256 + t];
    float s = v, sq = v * v;
    #pragma unroll
    for (int o = 16; o > 0; o >>= 1) {
        s  += __shfl_xor_sync(~0u, s, o);
        sq += __shfl_xor_sync(~0u, sq, o);
    }
    __shared__ float ss[8], ssq[8];
    if ((t & 31) == 0) { ss[t >> 5] = s; ssq[t >> 5] = sq; }
    __syncthreads();
    float tot = 0.f, totq = 0.f;
    #pragma unroll
    for (int i = 0; i < 8; i++) { tot += ss[i]; totq += ssq[i]; }
    const float mean = tot * (1.f / 256.f);
    const float var  = totq * (1.f / 256.f) - mean * mean;
    const float rstd = rsqrtf(var + 1e-5f);
    out[(size_t)row * 256 + t] = (v - mean) * rstd * g[t] + b[t];
}

// ---------------------------------------------------------------------------
// Selective scan, thread-per-d: all 16 states in registers, no shuffles.
// Block = 128 threads = 128 d's; grid covers (chunk, b, dgroup).
// SCH2=16 smem staging for coalesced global access.
// ---------------------------------------------------------------------------
#define SCH2 16

__global__ void __launch_bounds__(128) scan_carry_kernel(
    const float* __restrict__ u, const float* __restrict__ dt,
    const float* __restrict__ xdbc, const float* __restrict__ A_log,
    float* __restrict__ Pout, float* __restrict__ h0out)
{
    __shared__ float s_dt[SCH2][128], s_u[SCH2][128];
    __shared__ float s_B[SCH2][16];

    const int tid = threadIdx.x;
    const int c   = blockIdx.x >> 5;          // 0..C-2
    const int rem = blockIdx.x & 31;
    const int b   = rem >> 2;
    const int dg  = rem & 3;
    const int d   = dg * 128 + tid;

    float A2[16];
    #pragma unroll
    for (int s = 0; s < 16; s++)
        A2[s] = -__expf(A_log[d * 16 + s]) * LOG2E;

    float P[16], h[16];
    #pragma unroll
    for (int s = 0; s < 16; s++) { P[s] = 1.f; h[s] = 0.f; }

    const size_t base_bl = (size_t)b * Ln + (size_t)c * CH_LEN;
    const int doff = dg * 128;

    for (int l0 = 0; l0 < CH_LEN; l0 += SCH2) {
        #pragma unroll
        for (int r = 0; r < SCH2; r++) {
            const size_t bl = base_bl + l0 + r;
            s_dt[r][tid] = dt[bl * DIn + doff + tid];
            s_u [r][tid] = u [bl * DIn + doff + tid];
        }
        for (int i = tid; i < SCH2 * 16; i += 128) {
            const int r = i >> 4, cc = i & 15;
            s_B[r][cc] = xdbc[(base_bl + l0 + r) * 48 + 16 + cc];
        }
        __syncthreads();

        for (int i = 0; i < SCH2; i++) {
            const float dtv = s_dt[i][tid];
            const float x   = dtv * s_u[i][tid];
            float Bv[16];
            *(float4*)&Bv[0]  = *(const float4*)&s_B[i][0];
            *(float4*)&Bv[4]  = *(const float4*)&s_B[i][4];
            *(float4*)&Bv[8]  = *(const float4*)&s_B[i][8];
            *(float4*)&Bv[12] = *(const float4*)&s_B[i][12];
            #pragma unroll
            for (int s = 0; s < 16; s++) {
                const float dA = ex2f(dtv * A2[s]);
                P[s] *= dA;
                h[s] = fmaf(h[s], dA, x * Bv[s]);
            }
        }
        __syncthreads();
    }

    const size_t chb = (size_t)(b * DIn + d) * DSn;
    #pragma unroll
    for (int s = 0; s < 16; s++) {
        Pout [(size_t)c * NCH + chb + s] = P[s];
        h0out[(size_t)c * NCH + chb + s] = h[s];
    }
}

__global__ void scan_fix_kernel(const float* __restrict__ P,
                                const float* __restrict__ h0,
                                float* __restrict__ hini)
{
    const int ch = blockIdx.x * blockDim.x + threadIdx.x;
    float h = 0.f;
    hini[ch] = 0.f;
    #pragma unroll
    for (int c = 1; c < C_CHUNKS; c++) {
        h = fmaf(P[(c - 1) * NCH + ch], h, h0[(c - 1) * NCH + ch]);
        hini[c * NCH + ch] = h;
    }
}

__global__ void __launch_bounds__(128) scan_main_kernel(
    const float* __restrict__ u, const float* __restrict__ dt,
    const float* __restrict__ xz, const float* __restrict__ xdbc,
    const float* __restrict__ A_log, const float* __restrict__ Dp,
    const float* __restrict__ hini,
    float* __restrict__ y)
{
    __shared__ float s_dt[SCH2][128], s_u[SCH2][128], s_z[SCH2][128];
    __shared__ float s_B[SCH2][16], s_C[SCH2][16];

    const int tid = threadIdx.x;
    const int c   = blockIdx.x >> 5;          // 0..C-1
    const int rem = blockIdx.x & 31;
    const int b   = rem >> 2;
    const int dg  = rem & 3;
    const int d   = dg * 128 + tid;

    float A2[16];
    #pragma unroll
    for (int s = 0; s < 16; s++)
        A2[s] = -__expf(A_log[d * 16 + s]) * LOG2E;
    const float dpv = Dp[d];

    const size_t chb = (size_t)(b * DIn + d) * DSn;
    float h[16];
    *(float4*)&h[0]  = *(const float4*)&hini[(size_t)c * NCH + chb];
    *(float4*)&h[4]  = *(const float4*)&hini[(size_t)c * NCH + chb + 4];
    *(float4*)&h[8]  = *(const float4*)&hini[(size_t)c * NCH + chb + 8];
    *(float4*)&h[12] = *(const float4*)&hini[(size_t)c * NCH + chb + 12];

    const size_t base_bl = (size_t)b * Ln + (size_t)c * CH_LEN;
    const int doff = dg * 128;

    for (int l0 = 0; l0 < CH_LEN; l0 += SCH2) {
        #pragma unroll
        for (int r = 0; r < SCH2; r++) {
            const size_t bl = base_bl + l0 + r;
            s_dt[r][tid] = dt[bl * DIn + doff + tid];
            s_u [r][tid] = u [bl * DIn + doff + tid];
            s_z [r][tid] = xz[bl * (2 * DIn) + DIn + doff + tid];
        }
        for (int i = tid; i < SCH2 * 16; i += 128) {
            const int r = i >> 4, cc = i & 15;
            const size_t bl = base_bl + l0 + r;
            s_B[r][cc] = xdbc[bl * 48 + 16 + cc];
            s_C[r][cc] = xdbc[bl * 48 + 32 + cc];
        }
        __syncthreads();

        for (int i = 0; i < SCH2; i++) {
            const float dtv = s_dt[i][tid];
            const float uv  = s_u[i][tid];
            const float zv  = s_z[i][tid];
            const float x   = dtv * uv;
            float Bv[16], Cv[16];
            *(float4*)&Bv[0]  = *(const float4*)&s_B[i][0];
            *(float4*)&Bv[4]  = *(const float4*)&s_B[i][4];
            *(float4*)&Bv[8]  = *(const float4*)&s_B[i][8];
            *(float4*)&Bv[12] = *(const float4*)&s_B[i][12];
            *(float4*)&Cv[0]  = *(const float4*)&s_C[i][0];
            *(float4*)&Cv[4]  = *(const float4*)&s_C[i][4];
            *(float4*)&Cv[8]  = *(const float4*)&s_C[i][8];
            *(float4*)&Cv[12] = *(const float4*)&s_C[i][12];
            float yv = 0.f;
            #pragma unroll
            for (int s = 0; s < 16; s++) {
                const float dA = ex2f(dtv * A2[s]);
                h[s] = fmaf(h[s], dA, x * Bv[s]);
                yv = fmaf(h[s], Cv[s], yv);
            }
            yv = (yv + uv * dpv) * silu_f(zv);
            y[(base_bl + l0 + i) * DIn + doff + tid] = yv;
        }
        __syncthreads();
    }
}

// ---------------------------------------------------------------------------
// Pooling (split, R4-proven).
// ---------------------------------------------------------------------------
__global__ void pool_logit_kernel(const float* __restrict__ h,
                                  const float* __restrict__ wa,
                                  const float* __restrict__ ba,
                                  float* __restrict__ logit)
{
    const int wid_in_blk = threadIdx.x >> 5;
    const int lane = threadIdx.x & 31;
    const int row = blockIdx.x * 8 + wid_in_blk;
    const float* r = h + (size_t)row * 256;
    float acc = 0.f;
    #pragma unroll
    for (int k = 0; k < 2; k++) {
        const float4 hv = *(const float4*)(r + k * 128 + lane * 4);
        const float4 wv = *(const float4*)(wa + k * 128 + lane * 4);
        acc += hv.x * wv.x + hv.y * wv.y + hv.z * wv.z + hv.w * wv.w;
    }
    #pragma unroll
    for (int o = 16; o > 0; o >>= 1) acc += __shfl_xor_sync(~0u, acc, o);
    if (lane == 0) logit[row] = acc + ba[0];
}

__global__ void __launch_bounds__(1024) pool_softmax_kernel(float* __restrict__ logit)
{
    __shared__ float s_red[32];
    const int b = blockIdx.x, tid = threadIdx.x;
    float* lg = logit + b * Ln;

    float mx = -1e30f;
    float v[4];
    #pragma unroll
    for (int k = 0; k < 4; k++) {
        v[k] = lg[tid + k * 1024];
        mx = fmaxf(mx, v[k]);
    }
    #pragma unroll
    for (int o = 16; o > 0; o >>= 1) mx = fmaxf(mx, __shfl_xor_sync(~0u, mx, o));
    if ((tid & 31) == 0) s_red[tid >> 5] = mx;
    __syncthreads();
    if (tid < 32) {
        float t = s_red[tid];
        #pragma unroll
        for (int o = 16; o > 0; o >>= 1) t = fmaxf(t, __shfl_xor_sync(~0u, t, o));
        s_red[tid] = t;
    }
    __syncthreads();
    mx = s_red[0];
    __syncthreads();

    float sum = 0.f;
    #pragma unroll
    for (int k = 0; k < 4; k++) {
        v[k] = __expf(v[k] - mx);
        sum += v[k];
    }
    #pragma unroll
    for (int o = 16; o > 0; o >>= 1) sum += __shfl_xor_sync(~0u, sum, o);
    if ((tid & 31) == 0) s_red[tid >> 5] = sum;
    __syncthreads();
    if (tid < 32) {
        float t = s_red[tid];
        #pragma unroll
        for (int o = 16; o > 0; o >>= 1) t += __shfl_xor_sync(~0u, t, o);
        s_red[tid] = t;
    }
    __syncthreads();
    const float inv = 1.f / s_red[0];
    #pragma unroll
    for (int k = 0; k < 4; k++) lg[tid + k * 1024] = v[k] * inv;
}

__global__ void pool_wsum_kernel(const float* __restrict__ h,
                                 const float* __restrict__ p,
                                 float* __restrict__ part)
{
    const int b = blockIdx.x >> 4;
    const int sp = blockIdx.x & 15;
    const int tid = threadIdx.x;
    const size_t base = ((size_t)b * Ln + sp * 256) * 256;
    const float* pp = p + b * Ln + sp * 256;
    float acc = 0.f;
    for (int l = 0; l < 256; l++)
        acc = fmaf(pp[l], h[base + (size_t)l * 256 + tid], acc);
    part[(size_t)(b * 16 + sp) * 256 + tid] = acc;
}

__global__ void pool_final_kernel(const float* __restrict__ part,
                                  const float* __restrict__ Wf,
                                  const float* __restrict__ bf,
                                  float* __restrict__ out)
{
    __shared__ float s_red[8];
    const int b = blockIdx.x, tid = threadIdx.x;
    float pooled = 0.f;
    #pragma unroll
    for (int sp = 0; sp < 16; sp++)
        pooled += part[(size_t)(b * 16 + sp) * 256 + tid];
    float val = pooled * Wf[tid];
    #pragma unroll
    for (int o = 16; o > 0; o >>= 1) val += __shfl_xor_sync(~0u, val, o);
    if ((tid & 31) == 0) s_red[tid >> 5] = val;
    __syncthreads();
    if (tid == 0) {
        float tot = 0.f;
        #pragma unroll
        for (int i = 0; i < 8; i++) tot += s_red[i];
        out[b] = tot + bf[0];
    }
}

// ---------------------------------------------------------------------------
// Launch (single-stream, R4 ordering)
// ---------------------------------------------------------------------------
extern "C" void kernel_launch(void* const* d_in, const int* in_sizes, int n_in,
                              void* d_out, int out_size)
{
    const float* x      = (const float*)d_in[0];
    const float* Wp     = (const float*)d_in[1];
    const float* bp     = (const float*)d_in[2];
    const float* g0     = (const float*)d_in[3];
    const float* b0     = (const float*)d_in[4];
    const float* Wi     = (const float*)d_in[5];
    const float* conv_w = (const float*)d_in[6];
    const float* conv_b = (const float*)d_in[7];
    const float* Wx     = (const float*)d_in[8];
    const float* Wdt    = (const float*)d_in[9];
    const float* bdt    = (const float*)d_in[10];
    const float* A_log  = (const float*)d_in[11];
    const float* Dp     = (const float*)d_in[12];
    const float* Wo     = (const float*)d_in[13];
    const float* ln_g   = (const float*)d_in[14];
    const float* ln_b   = (const float*)d_in[15];
    const float* wa     = (const float*)d_in[16];
    const float* ba     = (const float*)d_in[17];
    const float* Wf     = (const float*)d_in[18];
    const float* bf     = (const float*)d_in[19];

    float *p_h, *p_t0, *p_xz, *p_u, *p_dt, *p_xdbc, *p_y;
    float *p_P, *p_h0, *p_hini, *p_logit, *p_part;
    cudaGetSymbolAddress((void**)&p_h,    g_h);
    cudaGetSymbolAddress((void**)&p_t0,   g_t0);
    cudaGetSymbolAddress((void**)&p_xz,   g_xz);
    cudaGetSymbolAddress((void**)&p_u,    g_u);
    cudaGetSymbolAddress((void**)&p_dt,   g_dt);
    cudaGetSymbolAddress((void**)&p_xdbc, g_xdbc);
    cudaGetSymbolAddress((void**)&p_y,    g_y);
    cudaGetSymbolAddress((void**)&p_P,    g_P);
    cudaGetSymbolAddress((void**)&p_h0,   g_h0);
    cudaGetSymbolAddress((void**)&p_hini, g_hini);
    cudaGetSymbolAddress((void**)&p_logit, g_logit);
    cudaGetSymbolAddress((void**)&p_part, g_part);

    // input projection + bias (tensor tf32) + LN
    tf32_gemm<1><<<dim3(2, 256), 256>>>(Dn, DINn, x, DINn, Wp, bp, p_t0, Dn);
    ln256_kernel<<<Mrows, 256>>>(p_t0, p_h, g0, b0);

    for (int l = 0; l < NLn; l++) {
        // xz = h @ Wi^T  (N=1024, K=256)
        tf32_gemm<0><<<dim3(8, 256), 256>>>(2 * DIn, Dn, p_h, Dn,
                                            Wi + (size_t)l * 2 * DIn * Dn,
                                            nullptr, p_xz, 2 * DIn);
        // depthwise causal conv + silu
        conv_silu_kernel<<<(Mrows * DIn) / 256, 256>>>(
            p_xz, conv_w + (size_t)l * DIn * DCn, conv_b + (size_t)l * DIn, p_u);
        // xdbc = u @ Wx^T  (N=48, K=512)
        tf32_gemm<0><<<dim3(1, 256), 256>>>(48, DIn, p_u, DIn,
                                            Wx + (size_t)l * 48 * DIn,
                                            nullptr, p_xdbc, 48);
        // dt = softplus(dtraw @ Wdt^T + bdt)  — SIMT sgemm
        sgemm_dt<<<dim3(4, 256), 256>>>(DIn, DTRn, p_xdbc, 48,
                                        Wdt + (size_t)l * DIn * DTRn,
                                        bdt + (size_t)l * DIn, p_dt, DIn);
        // chunked selective scan (thread-per-d, states in registers)
        scan_carry_kernel<<<32 * (C_CHUNKS - 1), 128>>>(
            p_u, p_dt, p_xdbc, A_log + (size_t)l * DIn * DSn, p_P, p_h0);
        scan_fix_kernel<<<NCH / 256, 256>>>(p_P, p_h0, p_hini);
        scan_main_kernel<<<32 * C_CHUNKS, 128>>>(
            p_u, p_dt, p_xz, p_xdbc,
            A_log + (size_t)l * DIn * DSn, Dp + (size_t)l * DIn,
            p_hini, p_y);
        // out = y @ Wo^T  (N=256, K=512), then LN
        tf32_gemm<0><<<dim3(2, 256), 256>>>(Dn, DIn, p_y, DIn,
                                            Wo + (size_t)l * Dn * DIn,
                                            nullptr, p_t0, Dn);
        ln256_kernel<<<Mrows, 256>>>(p_t0, p_h,
                                     ln_g + (size_t)l * Dn, ln_b + (size_t)l * Dn);
    }

    // pooling + final linear
    pool_logit_kernel<<<Mrows / 8, 256>>>(p_h, wa, ba, p_logit);
    pool_softmax_kernel<<<Bn, 1024>>>(p_logit);
    pool_wsum_kernel<<<Bn * 16, 256>>>(p_h, p_logit, p_part);
    pool_final_kernel<<<Bn, 256>>>(p_part, Wf, bf, (float*)d_out);
}

// round 12
// speedup vs baseline: 3.1690x; 1.2055x over previous
#include <cuda_runtime.h>
#include <math.h>
#include <stdint.h>

// Problem constants
#define Bn   8
#define Ln   4096
#define DINn 64
#define Dn   256
#define NLn  2
#define DIn  512
#define DSn  16
#define DCn  4
#define DTRn 16
#define Mrows (Bn * Ln)   // 32768

#define C_CHUNKS 16
#define CH_LEN   256      // Ln / C_CHUNKS
#define NCH      (Bn * DIn * DSn)   // 65536

// ---------------------------------------------------------------------------
// Scratch (device globals — no runtime allocation allowed)
// ---------------------------------------------------------------------------
__device__ float g_h    [Mrows * Dn];
__device__ float g_t0   [Mrows * Dn];
__device__ float g_xz   [Mrows * 2 * DIn];
__device__ float g_u    [Mrows * DIn];
__device__ float g_dt   [Mrows * DIn];
__device__ float g_xdbc [Mrows * 48];
__device__ float g_y    [Mrows * DIn];
__device__ float g_P    [(C_CHUNKS - 1) * NCH];
__device__ float g_h0   [(C_CHUNKS - 1) * NCH];
__device__ float g_hini [C_CHUNKS * NCH];
__device__ float g_logit[Mrows];
__device__ float g_part [Bn * 16 * Dn];

// ---------------------------------------------------------------------------
// Helpers
// ---------------------------------------------------------------------------
__device__ __forceinline__ float softplus_f(float x) {
    return fmaxf(x, 0.f) + log1pf(__expf(-fabsf(x)));
}
__device__ __forceinline__ float silu_f(float x) {
    return x / (1.f + __expf(-x));
}
__device__ __forceinline__ float to_tf32(float x) {
    float r;
    asm("cvt.rna.tf32.f32 %0, %1;" : "=f"(r) : "f"(x));
    return r;
}
__device__ __forceinline__ float ex2f(float x) {
    float r;
    asm("ex2.approx.ftz.f32 %0, %1;" : "=f"(r) : "f"(x));
    return r;
}
#define LOG2E 1.4426950408889634f
__device__ __forceinline__ void mma8(float* d,
                                     float a0, float a1, float a2, float a3,
                                     float b0, float b1) {
    asm volatile(
        "mma.sync.aligned.m16n8k8.row.col.f32.tf32.tf32.f32 "
        "{%0,%1,%2,%3},{%4,%5,%6,%7},{%8,%9},{%0,%1,%2,%3};"
        : "+f"(d[0]), "+f"(d[1]), "+f"(d[2]), "+f"(d[3])
        : "r"(__float_as_uint(a0)), "r"(__float_as_uint(a1)),
          "r"(__float_as_uint(a2)), "r"(__float_as_uint(a3)),
          "r"(__float_as_uint(b0)), "r"(__float_as_uint(b1)));
}

// ---------------------------------------------------------------------------
// TF32 tensor-core GEMM (R4-proven, unchanged).
// ---------------------------------------------------------------------------
#define SPAD 24
template <int EPI>
__global__ void __launch_bounds__(256, 2) tf32_gemm(
    int N, int K,
    const float* __restrict__ A, int lda,
    const float* __restrict__ W,
    const float* __restrict__ bias,
    float* __restrict__ C, int ldc)
{
    __shared__ float As[2][128][SPAD];
    __shared__ float Ws[2][128][SPAD];

    const int tid  = threadIdx.x;
    const int wid  = tid >> 5, lane = tid & 31;
    const int wm   = (wid >> 2) * 64;
    const int wn   = (wid & 3) * 32;
    const int gr   = lane >> 2;
    const int gc   = lane & 3;
    const int m0   = blockIdx.y * 128;
    const int n0   = blockIdx.x * 128;

    const int lr0 = tid >> 2;
    const int lj  = tid & 3;
    const int pb  = (lj & 2) * 4 + (lj & 1);

    const float* Ag = A + (size_t)(m0 + lr0) * lda + lj * 4;
    const float* Wg = W + (size_t)(n0 + lr0) * K + lj * 4;
    const bool wok0 = (n0 + lr0) < N;
    const bool wok1 = (n0 + lr0 + 64) < N;

    float acc[4][4][4];
    #pragma unroll
    for (int i = 0; i < 4; i++)
        #pragma unroll
        for (int j = 0; j < 4; j++)
            #pragma unroll
            for (int t = 0; t < 4; t++) acc[i][j][t] = 0.f;

    float4 ra0, ra1, rw0, rw1;
    const float4 z4 = make_float4(0.f, 0.f, 0.f, 0.f);

    ra0 = *(const float4*)(Ag);
    ra1 = *(const float4*)(Ag + (size_t)64 * lda);
    rw0 = wok0 ? *(const float4*)(Wg) : z4;
    rw1 = wok1 ? *(const float4*)(Wg + (size_t)64 * K) : z4;
    {
        As[0][lr0     ][pb]     = to_tf32(ra0.x);
        As[0][lr0     ][pb + 2] = to_tf32(ra0.y);
        As[0][lr0     ][pb + 4] = to_tf32(ra0.z);
        As[0][lr0     ][pb + 6] = to_tf32(ra0.w);
        As[0][lr0 + 64][pb]     = to_tf32(ra1.x);
        As[0][lr0 + 64][pb + 2] = to_tf32(ra1.y);
        As[0][lr0 + 64][pb + 4] = to_tf32(ra1.z);
        As[0][lr0 + 64][pb + 6] = to_tf32(ra1.w);
        Ws[0][lr0     ][pb]     = to_tf32(rw0.x);
        Ws[0][lr0     ][pb + 2] = to_tf32(rw0.y);
        Ws[0][lr0     ][pb + 4] = to_tf32(rw0.z);
        Ws[0][lr0     ][pb + 6] = to_tf32(rw0.w);
        Ws[0][lr0 + 64][pb]     = to_tf32(rw1.x);
        Ws[0][lr0 + 64][pb + 2] = to_tf32(rw1.y);
        Ws[0][lr0 + 64][pb + 4] = to_tf32(rw1.z);
        Ws[0][lr0 + 64][pb + 6] = to_tf32(rw1.w);
    }
    __syncthreads();

    int buf = 0;
    for (int k0 = 16; k0 < K; k0 += 16) {
        ra0 = *(const float4*)(Ag + k0);
        ra1 = *(const float4*)(Ag + (size_t)64 * lda + k0);
        rw0 = wok0 ? *(const float4*)(Wg + k0) : z4;
        rw1 = wok1 ? *(const float4*)(Wg + (size_t)64 * K + k0) : z4;

        #pragma unroll
        for (int ks = 0; ks < 2; ks++) {
            float2 alo[4], ahi[4], bfr[4];
            #pragma unroll
            for (int fm = 0; fm < 4; fm++) {
                alo[fm] = *(const float2*)&As[buf][wm + fm * 16 + gr    ][ks * 8 + 2 * gc];
                ahi[fm] = *(const float2*)&As[buf][wm + fm * 16 + gr + 8][ks * 8 + 2 * gc];
            }
            #pragma unroll
            for (int fn = 0; fn < 4; fn++)
                bfr[fn] = *(const float2*)&Ws[buf][wn + fn * 8 + gr][ks * 8 + 2 * gc];
            #pragma unroll
            for (int fm = 0; fm < 4; fm++)
                #pragma unroll
                for (int fn = 0; fn < 4; fn++)
                    mma8(acc[fm][fn], alo[fm].x, ahi[fm].x, alo[fm].y, ahi[fm].y,
                         bfr[fn].x, bfr[fn].y);
        }

        const int nb = buf ^ 1;
        As[nb][lr0     ][pb]     = to_tf32(ra0.x);
        As[nb][lr0     ][pb + 2] = to_tf32(ra0.y);
        As[nb][lr0     ][pb + 4] = to_tf32(ra0.z);
        As[nb][lr0     ][pb + 6] = to_tf32(ra0.w);
        As[nb][lr0 + 64][pb]     = to_tf32(ra1.x);
        As[nb][lr0 + 64][pb + 2] = to_tf32(ra1.y);
        As[nb][lr0 + 64][pb + 4] = to_tf32(ra1.z);
        As[nb][lr0 + 64][pb + 6] = to_tf32(ra1.w);
        Ws[nb][lr0     ][pb]     = to_tf32(rw0.x);
        Ws[nb][lr0     ][pb + 2] = to_tf32(rw0.y);
        Ws[nb][lr0     ][pb + 4] = to_tf32(rw0.z);
        Ws[nb][lr0     ][pb + 6] = to_tf32(rw0.w);
        Ws[nb][lr0 + 64][pb]     = to_tf32(rw1.x);
        Ws[nb][lr0 + 64][pb + 2] = to_tf32(rw1.y);
        Ws[nb][lr0 + 64][pb + 4] = to_tf32(rw1.z);
        Ws[nb][lr0 + 64][pb + 6] = to_tf32(rw1.w);
        __syncthreads();
        buf = nb;
    }

    #pragma unroll
    for (int ks = 0; ks < 2; ks++) {
        float2 alo[4], ahi[4], bfr[4];
        #pragma unroll
        for (int fm = 0; fm < 4; fm++) {
            alo[fm] = *(const float2*)&As[buf][wm + fm * 16 + gr    ][ks * 8 + 2 * gc];
            ahi[fm] = *(const float2*)&As[buf][wm + fm * 16 + gr + 8][ks * 8 + 2 * gc];
        }
        #pragma unroll
        for (int fn = 0; fn < 4; fn++)
            bfr[fn] = *(const float2*)&Ws[buf][wn + fn * 8 + gr][ks * 8 + 2 * gc];
        #pragma unroll
        for (int fm = 0; fm < 4; fm++)
            #pragma unroll
            for (int fn = 0; fn < 4; fn++)
                mma8(acc[fm][fn], alo[fm].x, ahi[fm].x, alo[fm].y, ahi[fm].y,
                     bfr[fn].x, bfr[fn].y);
    }

    #pragma unroll
    for (int fm = 0; fm < 4; fm++) {
        const int r0 = m0 + wm + fm * 16 + gr;
        #pragma unroll
        for (int fn = 0; fn < 4; fn++) {
            const int c0 = n0 + wn + fn * 8 + 2 * gc;
            if (c0 < N) {
                float v0 = acc[fm][fn][0], v1 = acc[fm][fn][1];
                float v2 = acc[fm][fn][2], v3 = acc[fm][fn][3];
                if (EPI == 1) {
                    v0 += bias[c0]; v1 += bias[c0 + 1];
                    v2 += bias[c0]; v3 += bias[c0 + 1];
                }
                *(float2*)&C[(size_t)r0 * ldc + c0]       = make_float2(v0, v1);
                *(float2*)&C[(size_t)(r0 + 8) * ldc + c0] = make_float2(v2, v3);
            }
        }
    }
}

// ---------------------------------------------------------------------------
// SIMT SGEMM for dt (N=512, K=16). softplus(+bias) epilogue. (R4-proven.)
// ---------------------------------------------------------------------------
__global__ void __launch_bounds__(256, 2) sgemm_dt(
    int N, int K,
    const float* __restrict__ A, int lda,
    const float* __restrict__ W,
    const float* __restrict__ bias,
    float* __restrict__ C, int ldc)
{
    __shared__ __align__(16) float As[8][132];
    __shared__ __align__(16) float Ws2[8][132];

    const int tid = threadIdx.x;
    const int tx = tid & 15;
    const int ty = tid >> 4;
    const int m0 = blockIdx.y * 128;
    const int n0 = blockIdx.x * 128;

    const int lr = tid >> 1;
    const int lk = (tid & 1) * 4;

    float acc[8][8];
    #pragma unroll
    for (int i = 0; i < 8; i++)
        #pragma unroll
        for (int j = 0; j < 8; j++) acc[i][j] = 0.f;

    const float* Aptr = A + (size_t)(m0 + lr) * lda + lk;
    const int wn = n0 + lr;
    const float* Wptr = W + (size_t)wn * K + lk;
    const bool wok = (wn < N);

    for (int k0 = 0; k0 < K; k0 += 8) {
        float4 av = *(const float4*)(Aptr + k0);
        As[lk + 0][lr] = av.x; As[lk + 1][lr] = av.y;
        As[lk + 2][lr] = av.z; As[lk + 3][lr] = av.w;

        float4 wv = make_float4(0.f, 0.f, 0.f, 0.f);
        if (wok) wv = *(const float4*)(Wptr + k0);
        Ws2[lk + 0][lr] = wv.x; Ws2[lk + 1][lr] = wv.y;
        Ws2[lk + 2][lr] = wv.z; Ws2[lk + 3][lr] = wv.w;

        __syncthreads();
        #pragma unroll
        for (int k = 0; k < 8; k++) {
            float a[8], bb[8];
            *(float4*)&a[0]  = *(const float4*)&As[k][ty * 4];
            *(float4*)&a[4]  = *(const float4*)&As[k][64 + ty * 4];
            *(float4*)&bb[0] = *(const float4*)&Ws2[k][tx * 4];
            *(float4*)&bb[4] = *(const float4*)&Ws2[k][64 + tx * 4];
            #pragma unroll
            for (int i = 0; i < 8; i++)
                #pragma unroll
                for (int j = 0; j < 8; j++)
                    acc[i][j] = fmaf(a[i], bb[j], acc[i][j]);
        }
        __syncthreads();
    }

    #pragma unroll
    for (int i = 0; i < 8; i++) {
        const int r = m0 + ((i < 4) ? (ty * 4 + i) : (64 + ty * 4 + i - 4));
        #pragma unroll
        for (int j = 0; j < 8; j++) {
            const int c = n0 + ((j < 4) ? (tx * 4 + j) : (64 + tx * 4 + j - 4));
            if (c < N) {
                float v = acc[i][j] + bias[c];
                C[(size_t)r * ldc + c] = softplus_f(v);
            }
        }
    }
}

// ---------------------------------------------------------------------------
// Depthwise causal conv (DC=4) + bias + SiLU — scalar (R4-proven).
// ---------------------------------------------------------------------------
__global__ void conv_silu_kernel(const float* __restrict__ xz,
                                 const float* __restrict__ w,
                                 const float* __restrict__ cb,
                                 float* __restrict__ u)
{
    const int idx = blockIdx.x * blockDim.x + threadIdx.x;
    if (idx >= Mrows * DIn) return;
    const int d  = idx & (DIn - 1);
    const int bl = idx >> 9;
    const int l  = bl & (Ln - 1);
    float acc = cb[d];
    #pragma unroll
    for (int k = 0; k < 4; k++) {
        const int ll = l - 3 + k;
        if (ll >= 0)
            acc = fmaf(w[d * 4 + k], xz[(size_t)(bl - 3 + k) * (2 * DIn) + d], acc);
    }
    u[idx] = silu_f(acc);
}

// ---------------------------------------------------------------------------
// LayerNorm over last dim (256), one block per row.
// ---------------------------------------------------------------------------
__global__ void ln256_kernel(const float* __restrict__ in, float* __restrict__ out,
                             const float* __restrict__ g, const float* __restrict__ b)
{
    const int row = blockIdx.x;
    const int t = threadIdx.x;
    const float v = in[(size_t)row * 256 + t];
    float s = v, sq = v * v;
    #pragma unroll
    for (int o = 16; o > 0; o >>= 1) {
        s  += __shfl_xor_sync(~0u, s, o);
        sq += __shfl_xor_sync(~0u, sq, o);
    }
    __shared__ float ss[8], ssq[8];
    if ((t & 31) == 0) { ss[t >> 5] = s; ssq[t >> 5] = sq; }
    __syncthreads();
    float tot = 0.f, totq = 0.f;
    #pragma unroll
    for (int i = 0; i < 8; i++) { tot += ss[i]; totq += ssq[i]; }
    const float mean = tot * (1.f / 256.f);
    const float var  = totq * (1.f / 256.f) - mean * mean;
    const float rstd = rsqrtf(var + 1e-5f);
    out[(size_t)row * 256 + t] = (v - mean) * rstd * g[t] + b[t];
}

// ---------------------------------------------------------------------------
// Selective scan, thread-per-d: all 16 states in registers, no shuffles.
// Block = 128 threads = 128 d's; grid covers (chunk, b, dgroup).
// ---------------------------------------------------------------------------
#define SCH2 16

__global__ void __launch_bounds__(128) scan_carry_kernel(
    const float* __restrict__ u, const float* __restrict__ dt,
    const float* __restrict__ xdbc, const float* __restrict__ A_log,
    float* __restrict__ Pout, float* __restrict__ h0out)
{
    __shared__ float s_dt[SCH2][128], s_u[SCH2][128];
    __shared__ float s_B[SCH2][16];

    const int tid = threadIdx.x;
    const int c   = blockIdx.x >> 5;          // 0..C-2
    const int rem = blockIdx.x & 31;
    const int b   = rem >> 2;
    const int dg  = rem & 3;
    const int d   = dg * 128 + tid;

    float A2[16];
    #pragma unroll
    for (int s = 0; s < 16; s++)
        A2[s] = -__expf(A_log[d * 16 + s]) * LOG2E;

    float P[16], h[16];
    #pragma unroll
    for (int s = 0; s < 16; s++) { P[s] = 1.f; h[s] = 0.f; }

    const size_t base_bl = (size_t)b * Ln + (size_t)c * CH_LEN;
    const int doff = dg * 128;

    for (int l0 = 0; l0 < CH_LEN; l0 += SCH2) {
        #pragma unroll
        for (int r = 0; r < SCH2; r++) {
            const size_t bl = base_bl + l0 + r;
            s_dt[r][tid] = dt[bl * DIn + doff + tid];
            s_u [r][tid] = u [bl * DIn + doff + tid];
        }
        for (int i = tid; i < SCH2 * 16; i += 128) {
            const int r = i >> 4, cc = i & 15;
            s_B[r][cc] = xdbc[(base_bl + l0 + r) * 48 + 16 + cc];
        }
        __syncthreads();

        for (int i = 0; i < SCH2; i++) {
            const float dtv = s_dt[i][tid];
            const float x   = dtv * s_u[i][tid];
            float Bv[16];
            *(float4*)&Bv[0]  = *(const float4*)&s_B[i][0];
            *(float4*)&Bv[4]  = *(const float4*)&s_B[i][4];
            *(float4*)&Bv[8]  = *(const float4*)&s_B[i][8];
            *(float4*)&Bv[12] = *(const float4*)&s_B[i][12];
            #pragma unroll
            for (int s = 0; s < 16; s++) {
                const float dA = ex2f(dtv * A2[s]);
                P[s] *= dA;
                h[s] = fmaf(h[s], dA, x * Bv[s]);
            }
        }
        __syncthreads();
    }

    const size_t chb = (size_t)(b * DIn + d) * DSn;
    #pragma unroll
    for (int s = 0; s < 16; s++) {
        Pout [(size_t)c * NCH + chb + s] = P[s];
        h0out[(size_t)c * NCH + chb + s] = h[s];
    }
}

__global__ void scan_fix_kernel(const float* __restrict__ P,
                                const float* __restrict__ h0,
                                float* __restrict__ hini)
{
    const int ch = blockIdx.x * blockDim.x + threadIdx.x;
    float h = 0.f;
    hini[ch] = 0.f;
    #pragma unroll
    for (int c = 1; c < C_CHUNKS; c++) {
        h = fmaf(P[(c - 1) * NCH + ch], h, h0[(c - 1) * NCH + ch]);
        hini[c * NCH + ch] = h;
    }
}

__global__ void __launch_bounds__(128) scan_main_kernel(
    const float* __restrict__ u, const float* __restrict__ dt,
    const float* __restrict__ xz, const float* __restrict__ xdbc,
    const float* __restrict__ A_log, const float* __restrict__ Dp,
    const float* __restrict__ hini,
    float* __restrict__ y)
{
    __shared__ float s_dt[SCH2][128], s_u[SCH2][128], s_z[SCH2][128];
    __shared__ float s_B[SCH2][16], s_C[SCH2][16];

    const int tid = threadIdx.x;
    const int c   = blockIdx.x >> 5;          // 0..C-1
    const int rem = blockIdx.x & 31;
    const int b   = rem >> 2;
    const int dg  = rem & 3;
    const int d   = dg * 128 + tid;

    float A2[16];
    #pragma unroll
    for (int s = 0; s < 16; s++)
        A2[s] = -__expf(A_log[d * 16 + s]) * LOG2E;
    const float dpv = Dp[d];

    const size_t chb = (size_t)(b * DIn + d) * DSn;
    float h[16];
    *(float4*)&h[0]  = *(const float4*)&hini[(size_t)c * NCH + chb];
    *(float4*)&h[4]  = *(const float4*)&hini[(size_t)c * NCH + chb + 4];
    *(float4*)&h[8]  = *(const float4*)&hini[(size_t)c * NCH + chb + 8];
    *(float4*)&h[12] = *(const float4*)&hini[(size_t)c * NCH + chb + 12];

    const size_t base_bl = (size_t)b * Ln + (size_t)c * CH_LEN;
    const int doff = dg * 128;

    for (int l0 = 0; l0 < CH_LEN; l0 += SCH2) {
        #pragma unroll
        for (int r = 0; r < SCH2; r++) {
            const size_t bl = base_bl + l0 + r;
            s_dt[r][tid] = dt[bl * DIn + doff + tid];
            s_u [r][tid] = u [bl * DIn + doff + tid];
            s_z [r][tid] = xz[bl * (2 * DIn) + DIn + doff + tid];
        }
        for (int i = tid; i < SCH2 * 16; i += 128) {
            const int r = i >> 4, cc = i & 15;
            const size_t bl = base_bl + l0 + r;
            s_B[r][cc] = xdbc[bl * 48 + 16 + cc];
            s_C[r][cc] = xdbc[bl * 48 + 32 + cc];
        }
        __syncthreads();

        for (int i = 0; i < SCH2; i++) {
            const float dtv = s_dt[i][tid];
            const float uv  = s_u[i][tid];
            const float zv  = s_z[i][tid];
            const float x   = dtv * uv;
            float Bv[16], Cv[16];
            *(float4*)&Bv[0]  = *(const float4*)&s_B[i][0];
            *(float4*)&Bv[4]  = *(const float4*)&s_B[i][4];
            *(float4*)&Bv[8]  = *(const float4*)&s_B[i][8];
            *(float4*)&Bv[12] = *(const float4*)&s_B[i][12];
            *(float4*)&Cv[0]  = *(const float4*)&s_C[i][0];
            *(float4*)&Cv[4]  = *(const float4*)&s_C[i][4];
            *(float4*)&Cv[8]  = *(const float4*)&s_C[i][8];
            *(float4*)&Cv[12] = *(const float4*)&s_C[i][12];
            float yv = 0.f;
            #pragma unroll
            for (int s = 0; s < 16; s++) {
                const float dA = ex2f(dtv * A2[s]);
                h[s] = fmaf(h[s], dA, x * Bv[s]);
                yv = fmaf(h[s], Cv[s], yv);
            }
            yv = (yv + uv * dpv) * silu_f(zv);
            y[(base_bl + l0 + i) * DIn + doff + tid] = yv;
        }
        __syncthreads();
    }
}

// ---------------------------------------------------------------------------
// Pooling (split, R4-proven).
// ---------------------------------------------------------------------------
__global__ void pool_logit_kernel(const float* __restrict__ h,
                                  const float* __restrict__ wa,
                                  const float* __restrict__ ba,
                                  float* __restrict__ logit)
{
    const int wid_in_blk = threadIdx.x >> 5;
    const int lane = threadIdx.x & 31;
    const int row = blockIdx.x * 8 + wid_in_blk;
    const float* r = h + (size_t)row * 256;
    float acc = 0.f;
    #pragma unroll
    for (int k = 0; k < 2; k++) {
        const float4 hv = *(const float4*)(r + k * 128 + lane * 4);
        const float4 wv = *(const float4*)(wa + k * 128 + lane * 4);
        acc += hv.x * wv.x + hv.y * wv.y + hv.z * wv.z + hv.w * wv.w;
    }
    #pragma unroll
    for (int o = 16; o > 0; o >>= 1) acc += __shfl_xor_sync(~0u, acc, o);
    if (lane == 0) logit[row] = acc + ba[0];
}

__global__ void __launch_bounds__(1024) pool_softmax_kernel(float* __restrict__ logit)
{
    __shared__ float s_red[32];
    const int b = blockIdx.x, tid = threadIdx.x;
    float* lg = logit + b * Ln;

    float mx = -1e30f;
    float v[4];
    #pragma unroll
    for (int k = 0; k < 4; k++) {
        v[k] = lg[tid + k * 1024];
        mx = fmaxf(mx, v[k]);
    }
    #pragma unroll
    for (int o = 16; o > 0; o >>= 1) mx = fmaxf(mx, __shfl_xor_sync(~0u, mx, o));
    if ((tid & 31) == 0) s_red[tid >> 5] = mx;
    __syncthreads();
    if (tid < 32) {
        float t = s_red[tid];
        #pragma unroll
        for (int o = 16; o > 0; o >>= 1) t = fmaxf(t, __shfl_xor_sync(~0u, t, o));
        s_red[tid] = t;
    }
    __syncthreads();
    mx = s_red[0];
    __syncthreads();

    float sum = 0.f;
    #pragma unroll
    for (int k = 0; k < 4; k++) {
        v[k] = __expf(v[k] - mx);
        sum += v[k];
    }
    #pragma unroll
    for (int o = 16; o > 0; o >>= 1) sum += __shfl_xor_sync(~0u, sum, o);
    if ((tid & 31) == 0) s_red[tid >> 5] = sum;
    __syncthreads();
    if (tid < 32) {
        float t = s_red[tid];
        #pragma unroll
        for (int o = 16; o > 0; o >>= 1) t += __shfl_xor_sync(~0u, t, o);
        s_red[tid] = t;
    }
    __syncthreads();
    const float inv = 1.f / s_red[0];
    #pragma unroll
    for (int k = 0; k < 4; k++) lg[tid + k * 1024] = v[k] * inv;
}

__global__ void pool_wsum_kernel(const float* __restrict__ h,
                                 const float* __restrict__ p,
                                 float* __restrict__ part)
{
    const int b = blockIdx.x >> 4;
    const int sp = blockIdx.x & 15;
    const int tid = threadIdx.x;
    const size_t base = ((size_t)b * Ln + sp * 256) * 256;
    const float* pp = p + b * Ln + sp * 256;
    float acc = 0.f;
    for (int l = 0; l < 256; l++)
        acc = fmaf(pp[l], h[base + (size_t)l * 256 + tid], acc);
    part[(size_t)(b * 16 + sp) * 256 + tid] = acc;
}

__global__ void pool_final_kernel(const float* __restrict__ part,
                                  const float* __restrict__ Wf,
                                  const float* __restrict__ bf,
                                  float* __restrict__ out)
{
    __shared__ float s_red[8];
    const int b = blockIdx.x, tid = threadIdx.x;
    float pooled = 0.f;
    #pragma unroll
    for (int sp = 0; sp < 16; sp++)
        pooled += part[(size_t)(b * 16 + sp) * 256 + tid];
    float val = pooled * Wf[tid];
    #pragma unroll
    for (int o = 16; o > 0; o >>= 1) val += __shfl_xor_sync(~0u, val, o);
    if ((tid & 31) == 0) s_red[tid >> 5] = val;
    __syncthreads();
    if (tid == 0) {
        float tot = 0.f;
        #pragma unroll
        for (int i = 0; i < 8; i++) tot += s_red[i];
        out[b] = tot + bf[0];
    }
}

// ---------------------------------------------------------------------------
// Launch
// ---------------------------------------------------------------------------
extern "C" void kernel_launch(void* const* d_in, const int* in_sizes, int n_in,
                              void* d_out, int out_size)
{
    const float* x      = (const float*)d_in[0];
    const float* Wp     = (const float*)d_in[1];
    const float* bp     = (const float*)d_in[2];
    const float* g0     = (const float*)d_in[3];
    const float* b0     = (const float*)d_in[4];
    const float* Wi     = (const float*)d_in[5];
    const float* conv_w = (const float*)d_in[6];
    const float* conv_b = (const float*)d_in[7];
    const float* Wx     = (const float*)d_in[8];
    const float* Wdt    = (const float*)d_in[9];
    const float* bdt    = (const float*)d_in[10];
    const float* A_log  = (const float*)d_in[11];
    const float* Dp     = (const float*)d_in[12];
    const float* Wo     = (const float*)d_in[13];
    const float* ln_g   = (const float*)d_in[14];
    const float* ln_b   = (const float*)d_in[15];
    const float* wa     = (const float*)d_in[16];
    const float* ba     = (const float*)d_in[17];
    const float* Wf     = (const float*)d_in[18];
    const float* bf     = (const float*)d_in[19];

    float *p_h, *p_t0, *p_xz, *p_u, *p_dt, *p_xdbc, *p_y;
    float *p_P, *p_h0, *p_hini, *p_logit, *p_part;
    cudaGetSymbolAddress((void**)&p_h,    g_h);
    cudaGetSymbolAddress((void**)&p_t0,   g_t0);
    cudaGetSymbolAddress((void**)&p_xz,   g_xz);
    cudaGetSymbolAddress((void**)&p_u,    g_u);
    cudaGetSymbolAddress((void**)&p_dt,   g_dt);
    cudaGetSymbolAddress((void**)&p_xdbc, g_xdbc);
    cudaGetSymbolAddress((void**)&p_y,    g_y);
    cudaGetSymbolAddress((void**)&p_P,    g_P);
    cudaGetSymbolAddress((void**)&p_h0,   g_h0);
    cudaGetSymbolAddress((void**)&p_hini, g_hini);
    cudaGetSymbolAddress((void**)&p_logit, g_logit);
    cudaGetSymbolAddress((void**)&p_part, g_part);

    // input projection + bias (tensor tf32) + LN
    tf32_gemm<1><<<dim3(2, 256), 256>>>(Dn, DINn, x, DINn, Wp, bp, p_t0, Dn);
    ln256_kernel<<<Mrows, 256>>>(p_t0, p_h, g0, b0);

    for (int l = 0; l < NLn; l++) {
        // xz = h @ Wi^T  (N=1024, K=256)
        tf32_gemm<0><<<dim3(8, 256), 256>>>(2 * DIn, Dn, p_h, Dn,
                                            Wi + (size_t)l * 2 * DIn * Dn,
                                            nullptr, p_xz, 2 * DIn);
        // depthwise causal conv + silu
        conv_silu_kernel<<<(Mrows * DIn) / 256, 256>>>(
            p_xz, conv_w + (size_t)l * DIn * DCn, conv_b + (size_t)l * DIn, p_u);
        // xdbc = u @ Wx^T  (N=48, K=512)
        tf32_gemm<0><<<dim3(1, 256), 256>>>(48, DIn, p_u, DIn,
                                            Wx + (size_t)l * 48 * DIn,
                                            nullptr, p_xdbc, 48);
        // dt = softplus(dtraw @ Wdt^T + bdt)  — SIMT sgemm
        sgemm_dt<<<dim3(4, 256), 256>>>(DIn, DTRn, p_xdbc, 48,
                                        Wdt + (size_t)l * DIn * DTRn,
                                        bdt + (size_t)l * DIn, p_dt, DIn);
        // chunked selective scan (thread-per-d, states in registers)
        scan_carry_kernel<<<32 * (C_CHUNKS - 1), 128>>>(
            p_u, p_dt, p_xdbc, A_log + (size_t)l * DIn * DSn, p_P, p_h0);
        scan_fix_kernel<<<NCH / 256, 256>>>(p_P, p_h0, p_hini);
        scan_main_kernel<<<32 * C_CHUNKS, 128>>>(
            p_u, p_dt, p_xz, p_xdbc,
            A_log + (size_t)l * DIn * DSn, Dp + (size_t)l * DIn,
            p_hini, p_y);
        // out = y @ Wo^T  (N=256, K=512), then LN
        tf32_gemm<0><<<dim3(2, 256), 256>>>(Dn, DIn, p_y, DIn,
                                            Wo + (size_t)l * Dn * DIn,
                                            nullptr, p_t0, Dn);
        ln256_kernel<<<Mrows, 256>>>(p_t0, p_h,
                                     ln_g + (size_t)l * Dn, ln_b + (size_t)l * Dn);
    }

    // pooling + final linear
    pool_logit_kernel<<<Mrows / 8, 256>>>(p_h, wa, ba, p_logit);
    pool_softmax_kernel<<<Bn, 1024>>>(p_logit);
    pool_wsum_kernel<<<Bn * 16, 256>>>(p_h, p_logit, p_part);
    pool_final_kernel<<<Bn, 256>>>(p_part, Wf, bf, (float*)d_out);
}

// round 13
// speedup vs baseline: 3.6937x; 1.1656x over previous
#include <cuda_runtime.h>
#include <math.h>
#include <stdint.h>

// Problem constants
#define Bn   8
#define Ln   4096
#define DINn 64
#define Dn   256
#define NLn  2
#define DIn  512
#define DSn  16
#define DCn  4
#define DTRn 16
#define Mrows (Bn * Ln)   // 32768

#define C_CHUNKS 32
#define CH_LEN   128      // Ln / C_CHUNKS
#define NCH      (Bn * DIn * DSn)   // 65536

// ---------------------------------------------------------------------------
// Scratch (device globals — no runtime allocation allowed)
// ---------------------------------------------------------------------------
__device__ float g_h    [Mrows * Dn];
__device__ float g_t0   [Mrows * Dn];
__device__ float g_xz   [Mrows * 2 * DIn];
__device__ float g_u    [Mrows * DIn];
__device__ float g_dt   [Mrows * DIn];
__device__ float g_xdbc [Mrows * 48];
__device__ float g_y    [Mrows * DIn];
__device__ float g_P    [(C_CHUNKS - 1) * NCH];
__device__ float g_h0   [(C_CHUNKS - 1) * NCH];
__device__ float g_hini [C_CHUNKS * NCH];
__device__ float g_logit[Mrows];
__device__ float g_part [Bn * 16 * Dn];

// ---------------------------------------------------------------------------
// Helpers
// ---------------------------------------------------------------------------
__device__ __forceinline__ float softplus_f(float x) {
    return fmaxf(x, 0.f) + log1pf(__expf(-fabsf(x)));
}
__device__ __forceinline__ float silu_f(float x) {
    return x / (1.f + __expf(-x));
}
__device__ __forceinline__ float to_tf32(float x) {
    float r;
    asm("cvt.rna.tf32.f32 %0, %1;" : "=f"(r) : "f"(x));
    return r;
}
__device__ __forceinline__ float ex2f(float x) {
    float r;
    asm("ex2.approx.ftz.f32 %0, %1;" : "=f"(r) : "f"(x));
    return r;
}
#define LOG2E 1.4426950408889634f
__device__ __forceinline__ void mma8(float* d,
                                     float a0, float a1, float a2, float a3,
                                     float b0, float b1) {
    asm volatile(
        "mma.sync.aligned.m16n8k8.row.col.f32.tf32.tf32.f32 "
        "{%0,%1,%2,%3},{%4,%5,%6,%7},{%8,%9},{%0,%1,%2,%3};"
        : "+f"(d[0]), "+f"(d[1]), "+f"(d[2]), "+f"(d[3])
        : "r"(__float_as_uint(a0)), "r"(__float_as_uint(a1)),
          "r"(__float_as_uint(a2)), "r"(__float_as_uint(a3)),
          "r"(__float_as_uint(b0)), "r"(__float_as_uint(b1)));
}

// ---------------------------------------------------------------------------
// TF32 tensor-core GEMM (R4-proven, unchanged).
// ---------------------------------------------------------------------------
#define SPAD 24
template <int EPI>
__global__ void __launch_bounds__(256, 2) tf32_gemm(
    int N, int K,
    const float* __restrict__ A, int lda,
    const float* __restrict__ W,
    const float* __restrict__ bias,
    float* __restrict__ C, int ldc)
{
    __shared__ float As[2][128][SPAD];
    __shared__ float Ws[2][128][SPAD];

    const int tid  = threadIdx.x;
    const int wid  = tid >> 5, lane = tid & 31;
    const int wm   = (wid >> 2) * 64;
    const int wn   = (wid & 3) * 32;
    const int gr   = lane >> 2;
    const int gc   = lane & 3;
    const int m0   = blockIdx.y * 128;
    const int n0   = blockIdx.x * 128;

    const int lr0 = tid >> 2;
    const int lj  = tid & 3;
    const int pb  = (lj & 2) * 4 + (lj & 1);

    const float* Ag = A + (size_t)(m0 + lr0) * lda + lj * 4;
    const float* Wg = W + (size_t)(n0 + lr0) * K + lj * 4;
    const bool wok0 = (n0 + lr0) < N;
    const bool wok1 = (n0 + lr0 + 64) < N;

    float acc[4][4][4];
    #pragma unroll
    for (int i = 0; i < 4; i++)
        #pragma unroll
        for (int j = 0; j < 4; j++)
            #pragma unroll
            for (int t = 0; t < 4; t++) acc[i][j][t] = 0.f;

    float4 ra0, ra1, rw0, rw1;
    const float4 z4 = make_float4(0.f, 0.f, 0.f, 0.f);

    ra0 = *(const float4*)(Ag);
    ra1 = *(const float4*)(Ag + (size_t)64 * lda);
    rw0 = wok0 ? *(const float4*)(Wg) : z4;
    rw1 = wok1 ? *(const float4*)(Wg + (size_t)64 * K) : z4;
    {
        As[0][lr0     ][pb]     = to_tf32(ra0.x);
        As[0][lr0     ][pb + 2] = to_tf32(ra0.y);
        As[0][lr0     ][pb + 4] = to_tf32(ra0.z);
        As[0][lr0     ][pb + 6] = to_tf32(ra0.w);
        As[0][lr0 + 64][pb]     = to_tf32(ra1.x);
        As[0][lr0 + 64][pb + 2] = to_tf32(ra1.y);
        As[0][lr0 + 64][pb + 4] = to_tf32(ra1.z);
        As[0][lr0 + 64][pb + 6] = to_tf32(ra1.w);
        Ws[0][lr0     ][pb]     = to_tf32(rw0.x);
        Ws[0][lr0     ][pb + 2] = to_tf32(rw0.y);
        Ws[0][lr0     ][pb + 4] = to_tf32(rw0.z);
        Ws[0][lr0     ][pb + 6] = to_tf32(rw0.w);
        Ws[0][lr0 + 64][pb]     = to_tf32(rw1.x);
        Ws[0][lr0 + 64][pb + 2] = to_tf32(rw1.y);
        Ws[0][lr0 + 64][pb + 4] = to_tf32(rw1.z);
        Ws[0][lr0 + 64][pb + 6] = to_tf32(rw1.w);
    }
    __syncthreads();

    int buf = 0;
    for (int k0 = 16; k0 < K; k0 += 16) {
        ra0 = *(const float4*)(Ag + k0);
        ra1 = *(const float4*)(Ag + (size_t)64 * lda + k0);
        rw0 = wok0 ? *(const float4*)(Wg + k0) : z4;
        rw1 = wok1 ? *(const float4*)(Wg + (size_t)64 * K + k0) : z4;

        #pragma unroll
        for (int ks = 0; ks < 2; ks++) {
            float2 alo[4], ahi[4], bfr[4];
            #pragma unroll
            for (int fm = 0; fm < 4; fm++) {
                alo[fm] = *(const float2*)&As[buf][wm + fm * 16 + gr    ][ks * 8 + 2 * gc];
                ahi[fm] = *(const float2*)&As[buf][wm + fm * 16 + gr + 8][ks * 8 + 2 * gc];
            }
            #pragma unroll
            for (int fn = 0; fn < 4; fn++)
                bfr[fn] = *(const float2*)&Ws[buf][wn + fn * 8 + gr][ks * 8 + 2 * gc];
            #pragma unroll
            for (int fm = 0; fm < 4; fm++)
                #pragma unroll
                for (int fn = 0; fn < 4; fn++)
                    mma8(acc[fm][fn], alo[fm].x, ahi[fm].x, alo[fm].y, ahi[fm].y,
                         bfr[fn].x, bfr[fn].y);
        }

        const int nb = buf ^ 1;
        As[nb][lr0     ][pb]     = to_tf32(ra0.x);
        As[nb][lr0     ][pb + 2] = to_tf32(ra0.y);
        As[nb][lr0     ][pb + 4] = to_tf32(ra0.z);
        As[nb][lr0     ][pb + 6] = to_tf32(ra0.w);
        As[nb][lr0 + 64][pb]     = to_tf32(ra1.x);
        As[nb][lr0 + 64][pb + 2] = to_tf32(ra1.y);
        As[nb][lr0 + 64][pb + 4] = to_tf32(ra1.z);
        As[nb][lr0 + 64][pb + 6] = to_tf32(ra1.w);
        Ws[nb][lr0     ][pb]     = to_tf32(rw0.x);
        Ws[nb][lr0     ][pb + 2] = to_tf32(rw0.y);
        Ws[nb][lr0     ][pb + 4] = to_tf32(rw0.z);
        Ws[nb][lr0     ][pb + 6] = to_tf32(rw0.w);
        Ws[nb][lr0 + 64][pb]     = to_tf32(rw1.x);
        Ws[nb][lr0 + 64][pb + 2] = to_tf32(rw1.y);
        Ws[nb][lr0 + 64][pb + 4] = to_tf32(rw1.z);
        Ws[nb][lr0 + 64][pb + 6] = to_tf32(rw1.w);
        __syncthreads();
        buf = nb;
    }

    #pragma unroll
    for (int ks = 0; ks < 2; ks++) {
        float2 alo[4], ahi[4], bfr[4];
        #pragma unroll
        for (int fm = 0; fm < 4; fm++) {
            alo[fm] = *(const float2*)&As[buf][wm + fm * 16 + gr    ][ks * 8 + 2 * gc];
            ahi[fm] = *(const float2*)&As[buf][wm + fm * 16 + gr + 8][ks * 8 + 2 * gc];
        }
        #pragma unroll
        for (int fn = 0; fn < 4; fn++)
            bfr[fn] = *(const float2*)&Ws[buf][wn + fn * 8 + gr][ks * 8 + 2 * gc];
        #pragma unroll
        for (int fm = 0; fm < 4; fm++)
            #pragma unroll
            for (int fn = 0; fn < 4; fn++)
                mma8(acc[fm][fn], alo[fm].x, ahi[fm].x, alo[fm].y, ahi[fm].y,
                     bfr[fn].x, bfr[fn].y);
    }

    #pragma unroll
    for (int fm = 0; fm < 4; fm++) {
        const int r0 = m0 + wm + fm * 16 + gr;
        #pragma unroll
        for (int fn = 0; fn < 4; fn++) {
            const int c0 = n0 + wn + fn * 8 + 2 * gc;
            if (c0 < N) {
                float v0 = acc[fm][fn][0], v1 = acc[fm][fn][1];
                float v2 = acc[fm][fn][2], v3 = acc[fm][fn][3];
                if (EPI == 1) {
                    v0 += bias[c0]; v1 += bias[c0 + 1];
                    v2 += bias[c0]; v3 += bias[c0 + 1];
                }
                *(float2*)&C[(size_t)r0 * ldc + c0]       = make_float2(v0, v1);
                *(float2*)&C[(size_t)(r0 + 8) * ldc + c0] = make_float2(v2, v3);
            }
        }
    }
}

// ---------------------------------------------------------------------------
// SIMT SGEMM for dt (N=512, K=16). softplus(+bias) epilogue. (R4-proven.)
// ---------------------------------------------------------------------------
__global__ void __launch_bounds__(256, 2) sgemm_dt(
    int N, int K,
    const float* __restrict__ A, int lda,
    const float* __restrict__ W,
    const float* __restrict__ bias,
    float* __restrict__ C, int ldc)
{
    __shared__ __align__(16) float As[8][132];
    __shared__ __align__(16) float Ws2[8][132];

    const int tid = threadIdx.x;
    const int tx = tid & 15;
    const int ty = tid >> 4;
    const int m0 = blockIdx.y * 128;
    const int n0 = blockIdx.x * 128;

    const int lr = tid >> 1;
    const int lk = (tid & 1) * 4;

    float acc[8][8];
    #pragma unroll
    for (int i = 0; i < 8; i++)
        #pragma unroll
        for (int j = 0; j < 8; j++) acc[i][j] = 0.f;

    const float* Aptr = A + (size_t)(m0 + lr) * lda + lk;
    const int wn = n0 + lr;
    const float* Wptr = W + (size_t)wn * K + lk;
    const bool wok = (wn < N);

    for (int k0 = 0; k0 < K; k0 += 8) {
        float4 av = *(const float4*)(Aptr + k0);
        As[lk + 0][lr] = av.x; As[lk + 1][lr] = av.y;
        As[lk + 2][lr] = av.z; As[lk + 3][lr] = av.w;

        float4 wv = make_float4(0.f, 0.f, 0.f, 0.f);
        if (wok) wv = *(const float4*)(Wptr + k0);
        Ws2[lk + 0][lr] = wv.x; Ws2[lk + 1][lr] = wv.y;
        Ws2[lk + 2][lr] = wv.z; Ws2[lk + 3][lr] = wv.w;

        __syncthreads();
        #pragma unroll
        for (int k = 0; k < 8; k++) {
            float a[8], bb[8];
            *(float4*)&a[0]  = *(const float4*)&As[k][ty * 4];
            *(float4*)&a[4]  = *(const float4*)&As[k][64 + ty * 4];
            *(float4*)&bb[0] = *(const float4*)&Ws2[k][tx * 4];
            *(float4*)&bb[4] = *(const float4*)&Ws2[k][64 + tx * 4];
            #pragma unroll
            for (int i = 0; i < 8; i++)
                #pragma unroll
                for (int j = 0; j < 8; j++)
                    acc[i][j] = fmaf(a[i], bb[j], acc[i][j]);
        }
        __syncthreads();
    }

    #pragma unroll
    for (int i = 0; i < 8; i++) {
        const int r = m0 + ((i < 4) ? (ty * 4 + i) : (64 + ty * 4 + i - 4));
        #pragma unroll
        for (int j = 0; j < 8; j++) {
            const int c = n0 + ((j < 4) ? (tx * 4 + j) : (64 + tx * 4 + j - 4));
            if (c < N) {
                float v = acc[i][j] + bias[c];
                C[(size_t)r * ldc + c] = softplus_f(v);
            }
        }
    }
}

// ---------------------------------------------------------------------------
// Depthwise causal conv (DC=4) + bias + SiLU — vectorized over l (4 steps).
// Thread owns one d and 4 consecutive l; loads 7 xz values for 4 outputs.
// Loads and stores stay d-coalesced.
// ---------------------------------------------------------------------------
__global__ void conv_silu_kernel(const float* __restrict__ xz,
                                 const float* __restrict__ w,
                                 const float* __restrict__ cb,
                                 float* __restrict__ u)
{
    const int idx = blockIdx.x * blockDim.x + threadIdx.x;
    if (idx >= Mrows * DIn / 4) return;
    const int d   = idx & (DIn - 1);
    const int bl4 = idx >> 9;
    const int l4  = bl4 & (Ln / 4 - 1);
    const int b   = bl4 >> 10;
    const int l0  = l4 * 4;
    const int bl0 = b * Ln + l0;

    float xv[7];
    #pragma unroll
    for (int k = 0; k < 7; k++) {
        const int ll = l0 - 3 + k;
        xv[k] = (ll >= 0) ? xz[(size_t)(bl0 - 3 + k) * (2 * DIn) + d] : 0.f;
    }
    const float w0 = w[d * 4 + 0], w1 = w[d * 4 + 1];
    const float w2 = w[d * 4 + 2], w3 = w[d * 4 + 3];
    const float cbv = cb[d];

    #pragma unroll
    for (int j = 0; j < 4; j++) {
        float acc = cbv;
        acc = fmaf(w0, xv[j + 0], acc);
        acc = fmaf(w1, xv[j + 1], acc);
        acc = fmaf(w2, xv[j + 2], acc);
        acc = fmaf(w3, xv[j + 3], acc);
        u[(size_t)(bl0 + j) * DIn + d] = silu_f(acc);
    }
}

// ---------------------------------------------------------------------------
// LayerNorm over last dim (256): warp-per-row, 8 floats/lane, no barriers.
// Block 256 = 8 warps = 8 rows.
// ---------------------------------------------------------------------------
__global__ void ln256_kernel(const float* __restrict__ in, float* __restrict__ out,
                             const float* __restrict__ g, const float* __restrict__ b)
{
    const int warp = threadIdx.x >> 5;
    const int lane = threadIdx.x & 31;
    const int row  = blockIdx.x * 8 + warp;
    const float* r = in + (size_t)row * 256;

    float4 v0 = *(const float4*)(r + lane * 4);
    float4 v1 = *(const float4*)(r + 128 + lane * 4);

    float s  = v0.x + v0.y + v0.z + v0.w + v1.x + v1.y + v1.z + v1.w;
    float sq = v0.x * v0.x + v0.y * v0.y + v0.z * v0.z + v0.w * v0.w
             + v1.x * v1.x + v1.y * v1.y + v1.z * v1.z + v1.w * v1.w;
    #pragma unroll
    for (int o = 16; o > 0; o >>= 1) {
        s  += __shfl_xor_sync(~0u, s, o);
        sq += __shfl_xor_sync(~0u, sq, o);
    }
    const float mean = s * (1.f / 256.f);
    const float var  = sq * (1.f / 256.f) - mean * mean;
    const float rstd = rsqrtf(var + 1e-5f);

    const float4 g0 = *(const float4*)(g + lane * 4);
    const float4 g1 = *(const float4*)(g + 128 + lane * 4);
    const float4 b0 = *(const float4*)(b + lane * 4);
    const float4 b1 = *(const float4*)(b + 128 + lane * 4);

    float4 o0, o1;
    o0.x = (v0.x - mean) * rstd * g0.x + b0.x;
    o0.y = (v0.y - mean) * rstd * g0.y + b0.y;
    o0.z = (v0.z - mean) * rstd * g0.z + b0.z;
    o0.w = (v0.w - mean) * rstd * g0.w + b0.w;
    o1.x = (v1.x - mean) * rstd * g1.x + b1.x;
    o1.y = (v1.y - mean) * rstd * g1.y + b1.y;
    o1.z = (v1.z - mean) * rstd * g1.z + b1.z;
    o1.w = (v1.w - mean) * rstd * g1.w + b1.w;

    float* ro = out + (size_t)row * 256;
    *(float4*)(ro + lane * 4)       = o0;
    *(float4*)(ro + 128 + lane * 4) = o1;
}

// ---------------------------------------------------------------------------
// Selective scan, thread-per-d: all 16 states in registers, no shuffles.
// Block = 128 threads = 128 d's; grid covers (chunk, b, dgroup).
// ---------------------------------------------------------------------------
#define SCH2 16

__global__ void __launch_bounds__(128) scan_carry_kernel(
    const float* __restrict__ u, const float* __restrict__ dt,
    const float* __restrict__ xdbc, const float* __restrict__ A_log,
    float* __restrict__ Pout, float* __restrict__ h0out)
{
    __shared__ float s_dt[SCH2][128], s_u[SCH2][128];
    __shared__ float s_B[SCH2][16];

    const int tid = threadIdx.x;
    const int c   = blockIdx.x >> 5;          // 0..C-2
    const int rem = blockIdx.x & 31;
    const int b   = rem >> 2;
    const int dg  = rem & 3;
    const int d   = dg * 128 + tid;

    float A2[16];
    #pragma unroll
    for (int s = 0; s < 16; s++)
        A2[s] = -__expf(A_log[d * 16 + s]) * LOG2E;

    float P[16], h[16];
    #pragma unroll
    for (int s = 0; s < 16; s++) { P[s] = 1.f; h[s] = 0.f; }

    const size_t base_bl = (size_t)b * Ln + (size_t)c * CH_LEN;
    const int doff = dg * 128;

    for (int l0 = 0; l0 < CH_LEN; l0 += SCH2) {
        #pragma unroll
        for (int r = 0; r < SCH2; r++) {
            const size_t bl = base_bl + l0 + r;
            s_dt[r][tid] = dt[bl * DIn + doff + tid];
            s_u [r][tid] = u [bl * DIn + doff + tid];
        }
        for (int i = tid; i < SCH2 * 16; i += 128) {
            const int r = i >> 4, cc = i & 15;
            s_B[r][cc] = xdbc[(base_bl + l0 + r) * 48 + 16 + cc];
        }
        __syncthreads();

        for (int i = 0; i < SCH2; i++) {
            const float dtv = s_dt[i][tid];
            const float x   = dtv * s_u[i][tid];
            float Bv[16];
            *(float4*)&Bv[0]  = *(const float4*)&s_B[i][0];
            *(float4*)&Bv[4]  = *(const float4*)&s_B[i][4];
            *(float4*)&Bv[8]  = *(const float4*)&s_B[i][8];
            *(float4*)&Bv[12] = *(const float4*)&s_B[i][12];
            #pragma unroll
            for (int s = 0; s < 16; s++) {
                const float dA = ex2f(dtv * A2[s]);
                P[s] *= dA;
                h[s] = fmaf(h[s], dA, x * Bv[s]);
            }
        }
        __syncthreads();
    }

    const size_t chb = (size_t)(b * DIn + d) * DSn;
    #pragma unroll
    for (int s = 0; s < 16; s++) {
        Pout [(size_t)c * NCH + chb + s] = P[s];
        h0out[(size_t)c * NCH + chb + s] = h[s];
    }
}

__global__ void scan_fix_kernel(const float* __restrict__ P,
                                const float* __restrict__ h0,
                                float* __restrict__ hini)
{
    const int ch = blockIdx.x * blockDim.x + threadIdx.x;
    float h = 0.f;
    hini[ch] = 0.f;
    #pragma unroll 4
    for (int c = 1; c < C_CHUNKS; c++) {
        h = fmaf(P[(c - 1) * NCH + ch], h, h0[(c - 1) * NCH + ch]);
        hini[c * NCH + ch] = h;
    }
}

__global__ void __launch_bounds__(128) scan_main_kernel(
    const float* __restrict__ u, const float* __restrict__ dt,
    const float* __restrict__ xz, const float* __restrict__ xdbc,
    const float* __restrict__ A_log, const float* __restrict__ Dp,
    const float* __restrict__ hini,
    float* __restrict__ y)
{
    __shared__ float s_dt[SCH2][128], s_u[SCH2][128], s_z[SCH2][128];
    __shared__ float s_B[SCH2][16], s_C[SCH2][16];

    const int tid = threadIdx.x;
    const int c   = blockIdx.x >> 5;          // 0..C-1
    const int rem = blockIdx.x & 31;
    const int b   = rem >> 2;
    const int dg  = rem & 3;
    const int d   = dg * 128 + tid;

    float A2[16];
    #pragma unroll
    for (int s = 0; s < 16; s++)
        A2[s] = -__expf(A_log[d * 16 + s]) * LOG2E;
    const float dpv = Dp[d];

    const size_t chb = (size_t)(b * DIn + d) * DSn;
    float h[16];
    *(float4*)&h[0]  = *(const float4*)&hini[(size_t)c * NCH + chb];
    *(float4*)&h[4]  = *(const float4*)&hini[(size_t)c * NCH + chb + 4];
    *(float4*)&h[8]  = *(const float4*)&hini[(size_t)c * NCH + chb + 8];
    *(float4*)&h[12] = *(const float4*)&hini[(size_t)c * NCH + chb + 12];

    const size_t base_bl = (size_t)b * Ln + (size_t)c * CH_LEN;
    const int doff = dg * 128;

    for (int l0 = 0; l0 < CH_LEN; l0 += SCH2) {
        #pragma unroll
        for (int r = 0; r < SCH2; r++) {
            const size_t bl = base_bl + l0 + r;
            s_dt[r][tid] = dt[bl * DIn + doff + tid];
            s_u [r][tid] = u [bl * DIn + doff + tid];
            s_z [r][tid] = xz[bl * (2 * DIn) + DIn + doff + tid];
        }
        for (int i = tid; i < SCH2 * 16; i += 128) {
            const int r = i >> 4, cc = i & 15;
            const size_t bl = base_bl + l0 + r;
            s_B[r][cc] = xdbc[bl * 48 + 16 + cc];
            s_C[r][cc] = xdbc[bl * 48 + 32 + cc];
        }
        __syncthreads();

        for (int i = 0; i < SCH2; i++) {
            const float dtv = s_dt[i][tid];
            const float uv  = s_u[i][tid];
            const float zv  = s_z[i][tid];
            const float x   = dtv * uv;
            float Bv[16], Cv[16];
            *(float4*)&Bv[0]  = *(const float4*)&s_B[i][0];
            *(float4*)&Bv[4]  = *(const float4*)&s_B[i][4];
            *(float4*)&Bv[8]  = *(const float4*)&s_B[i][8];
            *(float4*)&Bv[12] = *(const float4*)&s_B[i][12];
            *(float4*)&Cv[0]  = *(const float4*)&s_C[i][0];
            *(float4*)&Cv[4]  = *(const float4*)&s_C[i][4];
            *(float4*)&Cv[8]  = *(const float4*)&s_C[i][8];
            *(float4*)&Cv[12] = *(const float4*)&s_C[i][12];
            float yv = 0.f;
            #pragma unroll
            for (int s = 0; s < 16; s++) {
                const float dA = ex2f(dtv * A2[s]);
                h[s] = fmaf(h[s], dA, x * Bv[s]);
                yv = fmaf(h[s], Cv[s], yv);
            }
            yv = (yv + uv * dpv) * silu_f(zv);
            y[(base_bl + l0 + i) * DIn + doff + tid] = yv;
        }
        __syncthreads();
    }
}

// ---------------------------------------------------------------------------
// Pooling (split, R4-proven).
// ---------------------------------------------------------------------------
__global__ void pool_logit_kernel(const float* __restrict__ h,
                                  const float* __restrict__ wa,
                                  const float* __restrict__ ba,
                                  float* __restrict__ logit)
{
    const int wid_in_blk = threadIdx.x >> 5;
    const int lane = threadIdx.x & 31;
    const int row = blockIdx.x * 8 + wid_in_blk;
    const float* r = h + (size_t)row * 256;
    float acc = 0.f;
    #pragma unroll
    for (int k = 0; k < 2; k++) {
        const float4 hv = *(const float4*)(r + k * 128 + lane * 4);
        const float4 wv = *(const float4*)(wa + k * 128 + lane * 4);
        acc += hv.x * wv.x + hv.y * wv.y + hv.z * wv.z + hv.w * wv.w;
    }
    #pragma unroll
    for (int o = 16; o > 0; o >>= 1) acc += __shfl_xor_sync(~0u, acc, o);
    if (lane == 0) logit[row] = acc + ba[0];
}

__global__ void __launch_bounds__(1024) pool_softmax_kernel(float* __restrict__ logit)
{
    __shared__ float s_red[32];
    const int b = blockIdx.x, tid = threadIdx.x;
    float* lg = logit + b * Ln;

    float mx = -1e30f;
    float v[4];
    #pragma unroll
    for (int k = 0; k < 4; k++) {
        v[k] = lg[tid + k * 1024];
        mx = fmaxf(mx, v[k]);
    }
    #pragma unroll
    for (int o = 16; o > 0; o >>= 1) mx = fmaxf(mx, __shfl_xor_sync(~0u, mx, o));
    if ((tid & 31) == 0) s_red[tid >> 5] = mx;
    __syncthreads();
    if (tid < 32) {
        float t = s_red[tid];
        #pragma unroll
        for (int o = 16; o > 0; o >>= 1) t = fmaxf(t, __shfl_xor_sync(~0u, t, o));
        s_red[tid] = t;
    }
    __syncthreads();
    mx = s_red[0];
    __syncthreads();

    float sum = 0.f;
    #pragma unroll
    for (int k = 0; k < 4; k++) {
        v[k] = __expf(v[k] - mx);
        sum += v[k];
    }
    #pragma unroll
    for (int o = 16; o > 0; o >>= 1) sum += __shfl_xor_sync(~0u, sum, o);
    if ((tid & 31) == 0) s_red[tid >> 5] = sum;
    __syncthreads();
    if (tid < 32) {
        float t = s_red[tid];
        #pragma unroll
        for (int o = 16; o > 0; o >>= 1) t += __shfl_xor_sync(~0u, t, o);
        s_red[tid] = t;
    }
    __syncthreads();
    const float inv = 1.f / s_red[0];
    #pragma unroll
    for (int k = 0; k < 4; k++) lg[tid + k * 1024] = v[k] * inv;
}

__global__ void pool_wsum_kernel(const float* __restrict__ h,
                                 const float* __restrict__ p,
                                 float* __restrict__ part)
{
    const int b = blockIdx.x >> 4;
    const int sp = blockIdx.x & 15;
    const int tid = threadIdx.x;
    const size_t base = ((size_t)b * Ln + sp * 256) * 256;
    const float* pp = p + b * Ln + sp * 256;
    float acc = 0.f;
    for (int l = 0; l < 256; l++)
        acc = fmaf(pp[l], h[base + (size_t)l * 256 + tid], acc);
    part[(size_t)(b * 16 + sp) * 256 + tid] = acc;
}

__global__ void pool_final_kernel(const float* __restrict__ part,
                                  const float* __restrict__ Wf,
                                  const float* __restrict__ bf,
                                  float* __restrict__ out)
{
    __shared__ float s_red[8];
    const int b = blockIdx.x, tid = threadIdx.x;
    float pooled = 0.f;
    #pragma unroll
    for (int sp = 0; sp < 16; sp++)
        pooled += part[(size_t)(b * 16 + sp) * 256 + tid];
    float val = pooled * Wf[tid];
    #pragma unroll
    for (int o = 16; o > 0; o >>= 1) val += __shfl_xor_sync(~0u, val, o);
    if ((tid & 31) == 0) s_red[tid >> 5] = val;
    __syncthreads();
    if (tid == 0) {
        float tot = 0.f;
        #pragma unroll
        for (int i = 0; i < 8; i++) tot += s_red[i];
        out[b] = tot + bf[0];
    }
}

// ---------------------------------------------------------------------------
// Launch
// ---------------------------------------------------------------------------
extern "C" void kernel_launch(void* const* d_in, const int* in_sizes, int n_in,
                              void* d_out, int out_size)
{
    const float* x      = (const float*)d_in[0];
    const float* Wp     = (const float*)d_in[1];
    const float* bp     = (const float*)d_in[2];
    const float* g0     = (const float*)d_in[3];
    const float* b0     = (const float*)d_in[4];
    const float* Wi     = (const float*)d_in[5];
    const float* conv_w = (const float*)d_in[6];
    const float* conv_b = (const float*)d_in[7];
    const float* Wx     = (const float*)d_in[8];
    const float* Wdt    = (const float*)d_in[9];
    const float* bdt    = (const float*)d_in[10];
    const float* A_log  = (const float*)d_in[11];
    const float* Dp     = (const float*)d_in[12];
    const float* Wo     = (const float*)d_in[13];
    const float* ln_g   = (const float*)d_in[14];
    const float* ln_b   = (const float*)d_in[15];
    const float* wa     = (const float*)d_in[16];
    const float* ba     = (const float*)d_in[17];
    const float* Wf     = (const float*)d_in[18];
    const float* bf     = (const float*)d_in[19];

    float *p_h, *p_t0, *p_xz, *p_u, *p_dt, *p_xdbc, *p_y;
    float *p_P, *p_h0, *p_hini, *p_logit, *p_part;
    cudaGetSymbolAddress((void**)&p_h,    g_h);
    cudaGetSymbolAddress((void**)&p_t0,   g_t0);
    cudaGetSymbolAddress((void**)&p_xz,   g_xz);
    cudaGetSymbolAddress((void**)&p_u,    g_u);
    cudaGetSymbolAddress((void**)&p_dt,   g_dt);
    cudaGetSymbolAddress((void**)&p_xdbc, g_xdbc);
    cudaGetSymbolAddress((void**)&p_y,    g_y);
    cudaGetSymbolAddress((void**)&p_P,    g_P);
    cudaGetSymbolAddress((void**)&p_h0,   g_h0);
    cudaGetSymbolAddress((void**)&p_hini, g_hini);
    cudaGetSymbolAddress((void**)&p_logit, g_logit);
    cudaGetSymbolAddress((void**)&p_part, g_part);

    // input projection + bias (tensor tf32) + LN
    tf32_gemm<1><<<dim3(2, 256), 256>>>(Dn, DINn, x, DINn, Wp, bp, p_t0, Dn);
    ln256_kernel<<<Mrows / 8, 256>>>(p_t0, p_h, g0, b0);

    for (int l = 0; l < NLn; l++) {
        // xz = h @ Wi^T  (N=1024, K=256)
        tf32_gemm<0><<<dim3(8, 256), 256>>>(2 * DIn, Dn, p_h, Dn,
                                            Wi + (size_t)l * 2 * DIn * Dn,
                                            nullptr, p_xz, 2 * DIn);
        // depthwise causal conv + silu (l-vectorized)
        conv_silu_kernel<<<(Mrows * DIn / 4) / 256, 256>>>(
            p_xz, conv_w + (size_t)l * DIn * DCn, conv_b + (size_t)l * DIn, p_u);
        // xdbc = u @ Wx^T  (N=48, K=512)
        tf32_gemm<0><<<dim3(1, 256), 256>>>(48, DIn, p_u, DIn,
                                            Wx + (size_t)l * 48 * DIn,
                                            nullptr, p_xdbc, 48);
        // dt = softplus(dtraw @ Wdt^T + bdt)  — SIMT sgemm
        sgemm_dt<<<dim3(4, 256), 256>>>(DIn, DTRn, p_xdbc, 48,
                                        Wdt + (size_t)l * DIn * DTRn,
                                        bdt + (size_t)l * DIn, p_dt, DIn);
        // chunked selective scan (thread-per-d, states in registers)
        scan_carry_kernel<<<32 * (C_CHUNKS - 1), 128>>>(
            p_u, p_dt, p_xdbc, A_log + (size_t)l * DIn * DSn, p_P, p_h0);
        scan_fix_kernel<<<NCH / 256, 256>>>(p_P, p_h0, p_hini);
        scan_main_kernel<<<32 * C_CHUNKS, 128>>>(
            p_u, p_dt, p_xz, p_xdbc,
            A_log + (size_t)l * DIn * DSn, Dp + (size_t)l * DIn,
            p_hini, p_y);
        // out = y @ Wo^T  (N=256, K=512), then LN
        tf32_gemm<0><<<dim3(2, 256), 256>>>(Dn, DIn, p_y, DIn,
                                            Wo + (size_t)l * Dn * DIn,
                                            nullptr, p_t0, Dn);
        ln256_kernel<<<Mrows / 8, 256>>>(p_t0, p_h,
                                         ln_g + (size_t)l * Dn, ln_b + (size_t)l * Dn);
    }

    // pooling + final linear
    pool_logit_kernel<<<Mrows / 8, 256>>>(p_h, wa, ba, p_logit);
    pool_softmax_kernel<<<Bn, 1024>>>(p_logit);
    pool_wsum_kernel<<<Bn * 16, 256>>>(p_h, p_logit, p_part);
    pool_final_kernel<<<Bn, 256>>>(p_part, Wf, bf, (float*)d_out);
}